// round 3
// baseline (speedup 1.0000x reference)
#include <cuda_runtime.h>
#include <cstdint>

#define HID 4096
#define KVD 1024
#define SEQ 2048
#define NHEADS 32
#define NKVH 8
#define HD 128

// ---------------- scratch (static device allocations) ----------------
__device__ float g_wmq[HID * HID];
__device__ float g_wmo[HID * HID];
__device__ float g_wmk[KVD * HID];
__device__ float g_wmv[KVD * HID];
__device__ float g_hst[SEQ * HID];
__device__ float g_q[SEQ * HID];
__device__ float g_k[SEQ * KVD];
__device__ float g_v[SEQ * KVD];
__device__ float g_ao[SEQ * HID];
__device__ int   g_invp_qkv[HID];
__device__ int   g_invp_o[HID];

__device__ __forceinline__ float tf32_rna(float x) {
    uint32_t u;
    asm("cvt.rna.tf32.f32 %0, %1;" : "=r"(u) : "f"(x));
    return __uint_as_float(u);
}

// ---------------- permutation extraction ----------------
__global__ void perm_extract(const float* __restrict__ P, int* __restrict__ invp, int n) {
    int idx = blockIdx.x * blockDim.x + threadIdx.x;
    if (idx >= n * n) return;
    if (P[idx] > 0.5f) invp[idx % n] = idx / n;
}

// ---------------- round hidden states to tf32 ----------------
__global__ void round_tf32(const float* __restrict__ X, float* __restrict__ Y, int n4) {
    int idx = blockIdx.x * blockDim.x + threadIdx.x;
    if (idx >= n4) return;
    float4 v = ((const float4*)X)[idx];
    v.x = tf32_rna(v.x); v.y = tf32_rna(v.y);
    v.z = tf32_rna(v.z); v.w = tf32_rna(v.w);
    ((float4*)Y)[idx] = v;
}

// ---------------- 2:4 hard mask (wanda metric, permuted groups) ----------------
// Output is tf32-rounded so the tf32 GEMM sees round-to-nearest operands.
__global__ void mask_weights(const float* __restrict__ W, const float* __restrict__ scaler,
                             const int* __restrict__ invp, float* __restrict__ Wm,
                             int R, int H) {
    int idx = blockIdx.x * blockDim.x + threadIdx.x;
    int G = H >> 2;
    if (idx >= R * G) return;
    int r = idx / G, g = idx % G;
    int c[4]; float w[4], m[4];
#pragma unroll
    for (int t = 0; t < 4; t++) {
        c[t] = invp[4 * g + t];
        w[t] = W[r * H + c[t]];
        m[t] = fabsf(w[t]) * sqrtf(scaler[c[t]]);
    }
#pragma unroll
    for (int t = 0; t < 4; t++) {
        int rank = 0;
#pragma unroll
        for (int u = 0; u < 4; u++)
            rank += (m[u] > m[t]) || (m[u] == m[t] && u < t);
        Wm[r * H + c[t]] = (rank < 2) ? tf32_rna(w[t]) : 0.0f;
    }
}

// ---------------- tf32 tensor-core NT GEMM: C[M,N] = A[M,K] * B[N,K]^T ----------
// 128x128x32 CTA tile, 256 threads (2x4 warps, 64x32 warp tiles),
// double-buffered cp.async, mma.sync.m16n8k8.tf32.
#define GS 36                      // smem row stride (floats): conflict-free frag loads
#define STAGE_F (128 * GS)         // floats per stage per operand
#define GEMM_SMEM_BYTES (4 * STAGE_F * 4)

__device__ __forceinline__ void mma_tf32(float c[4], uint32_t a0, uint32_t a1,
                                         uint32_t a2, uint32_t a3,
                                         uint32_t b0, uint32_t b1) {
    asm volatile(
        "mma.sync.aligned.m16n8k8.row.col.f32.tf32.tf32.f32 "
        "{%0,%1,%2,%3}, {%4,%5,%6,%7}, {%8,%9}, {%0,%1,%2,%3};"
        : "+f"(c[0]), "+f"(c[1]), "+f"(c[2]), "+f"(c[3])
        : "r"(a0), "r"(a1), "r"(a2), "r"(a3), "r"(b0), "r"(b1));
}

__global__ void __launch_bounds__(256) gemm_tf32(const float* __restrict__ A,
                                                 const float* __restrict__ B,
                                                 float* __restrict__ C,
                                                 int M, int N, int K) {
    extern __shared__ float sm[];
    float* As = sm;                    // [2][128][GS]
    float* Bs = sm + 2 * STAGE_F;      // [2][128][GS]

    const int tid = threadIdx.x;
    const int wid = tid >> 5, lane = tid & 31;
    const int g = lane >> 2, tg = lane & 3;
    const int wm = (wid >> 2) * 64, wn = (wid & 3) * 32;
    const int bm = blockIdx.y * 128, bn = blockIdx.x * 128;
    const int ar = tid >> 3, ac = (tid & 7) * 4;

    float acc[4][4][4] = {};

    const float* Ag = A + (size_t)(bm + ar) * K + ac;
    const float* Bg = B + (size_t)(bn + ar) * K + ac;

    uint32_t sA = (uint32_t)__cvta_generic_to_shared(As);
    uint32_t sB = (uint32_t)__cvta_generic_to_shared(Bs);

#define LOAD_STAGE(s, k0)                                                        \
    do {                                                                         \
        uint32_t soff = (uint32_t)(s) * STAGE_F * 4;                             \
        _Pragma("unroll")                                                        \
        for (int i = 0; i < 4; i++) {                                            \
            uint32_t da = sA + soff + ((ar + i * 32) * GS + ac) * 4;             \
            uint32_t db = sB + soff + ((ar + i * 32) * GS + ac) * 4;             \
            const float* pa = Ag + (size_t)i * 32 * K + (k0);                    \
            const float* pb = Bg + (size_t)i * 32 * K + (k0);                    \
            asm volatile("cp.async.cg.shared.global [%0], [%1], 16;" ::"r"(da), "l"(pa)); \
            asm volatile("cp.async.cg.shared.global [%0], [%1], 16;" ::"r"(db), "l"(pb)); \
        }                                                                        \
    } while (0)

    LOAD_STAGE(0, 0);
    asm volatile("cp.async.commit_group;");

    const int nk = K >> 5;
    for (int t = 0; t < nk; t++) {
        int s = t & 1;
        if (t + 1 < nk) LOAD_STAGE(s ^ 1, (t + 1) * 32);
        asm volatile("cp.async.commit_group;");
        asm volatile("cp.async.wait_group 1;");
        __syncthreads();

        const float* Ast = As + s * STAGE_F;
        const float* Bst = Bs + s * STAGE_F;
#pragma unroll
        for (int kk = 0; kk < 32; kk += 8) {
            uint32_t bf[4][2];
#pragma unroll
            for (int ni = 0; ni < 4; ni++) {
                int rn = (wn + ni * 8 + g) * GS + kk + tg;
                bf[ni][0] = __float_as_uint(Bst[rn]);
                bf[ni][1] = __float_as_uint(Bst[rn + 4]);
            }
#pragma unroll
            for (int mi = 0; mi < 4; mi++) {
                int rm = (wm + mi * 16 + g) * GS + kk + tg;
                uint32_t a0 = __float_as_uint(Ast[rm]);
                uint32_t a1 = __float_as_uint(Ast[rm + 8 * GS]);
                uint32_t a2 = __float_as_uint(Ast[rm + 4]);
                uint32_t a3 = __float_as_uint(Ast[rm + 8 * GS + 4]);
#pragma unroll
                for (int ni = 0; ni < 4; ni++)
                    mma_tf32(acc[mi][ni], a0, a1, a2, a3, bf[ni][0], bf[ni][1]);
            }
        }
        __syncthreads();
    }

#pragma unroll
    for (int mi = 0; mi < 4; mi++)
#pragma unroll
        for (int ni = 0; ni < 4; ni++) {
            int row = bm + wm + mi * 16 + g;
            int col = bn + wn + ni * 8 + tg * 2;
            *(float2*)&C[(size_t)row * N + col] =
                make_float2(acc[mi][ni][0], acc[mi][ni][1]);
            *(float2*)&C[(size_t)(row + 8) * N + col] =
                make_float2(acc[mi][ni][2], acc[mi][ni][3]);
        }
#undef LOAD_STAGE
}

// ---------------- RoPE (in place, paired halves) ----------------
__global__ void rope_kernel(float* __restrict__ X, const float* __restrict__ cosT,
                            const float* __restrict__ sinT, int nheads) {
    int idx = blockIdx.x * blockDim.x + threadIdx.x;
    int total = SEQ * nheads * 64;
    if (idx >= total) return;
    int d = idx & 63;
    int h = (idx >> 6) % nheads;
    int s = idx / (64 * nheads);
    float* p = X + (size_t)s * nheads * HD + h * HD + d;
    float x1 = p[0], x2 = p[64];
    float c1 = cosT[s * HD + d],      s1 = sinT[s * HD + d];
    float c2 = cosT[s * HD + 64 + d], s2 = sinT[s * HD + 64 + d];
    p[0]  = fmaf(x1, c1, -x2 * s1);
    p[64] = fmaf(x2, c2,  x1 * s2);
}

// ---------------- causal flash attention, fp32 ----------------
#define FL_SMEM_FLOATS (128*68 + 128*68 + 64*132 + 64*65 + 64*17 + 4*64)

__global__ void __launch_bounds__(256) flash_kernel(const float* __restrict__ Qg,
                                                    const float* __restrict__ Kg,
                                                    const float* __restrict__ Vg,
                                                    float* __restrict__ Og) {
    extern __shared__ float sm[];
    float* Qst  = sm;
    float* Kst  = Qst + 128 * 68;
    float* Vs   = Kst + 128 * 68;
    float* Ss   = Vs + 64 * 132;
    float* part = Ss + 64 * 65;
    float* mrow = part + 64 * 17;
    float* lrow = mrow + 64;
    float* fsc  = lrow + 64;
    float* mnew = fsc + 64;

    const int tid = threadIdx.x;
    const int qb = blockIdx.x;
    const int head = blockIdx.y;
    const int kvh = head >> 2;
    const float* Qh = Qg + head * HD;
    const float* Kh = Kg + kvh * HD;
    const float* Vh = Vg + kvh * HD;

#pragma unroll
    for (int i = 0; i < 8; i++) {
        int lin = tid + i * 256;
        int r = lin >> 5, c4 = lin & 31;
        float4 qv = *(const float4*)&Qh[(size_t)(qb * 64 + r) * HID + c4 * 4];
        Qst[(c4 * 4 + 0) * 68 + r] = qv.x;
        Qst[(c4 * 4 + 1) * 68 + r] = qv.y;
        Qst[(c4 * 4 + 2) * 68 + r] = qv.z;
        Qst[(c4 * 4 + 3) * 68 + r] = qv.w;
    }
    if (tid < 64) { mrow[tid] = -1e30f; lrow[tid] = 0.f; }

    float acc[32];
#pragma unroll
    for (int i = 0; i < 32; i++) acc[i] = 0.f;

    const int tx = tid & 15, ty = tid >> 4;
    const int qr = tid >> 2, chunk = tid & 3;
    const float scale = 0.08838834764831845f;

    for (int kb = 0; kb <= qb; kb++) {
        __syncthreads();
#pragma unroll
        for (int i = 0; i < 8; i++) {
            int lin = tid + i * 256;
            int r = lin >> 5, c4 = lin & 31;
            float4 kv = *(const float4*)&Kh[(size_t)(kb * 64 + r) * KVD + c4 * 4];
            Kst[(c4 * 4 + 0) * 68 + r] = kv.x;
            Kst[(c4 * 4 + 1) * 68 + r] = kv.y;
            Kst[(c4 * 4 + 2) * 68 + r] = kv.z;
            Kst[(c4 * 4 + 3) * 68 + r] = kv.w;
            float4 vv = *(const float4*)&Vh[(size_t)(kb * 64 + r) * KVD + c4 * 4];
            *(float4*)&Vs[r * 132 + c4 * 4] = vv;
        }
        __syncthreads();

        float sreg[4][4];
#pragma unroll
        for (int i = 0; i < 4; i++)
#pragma unroll
            for (int j = 0; j < 4; j++) sreg[i][j] = 0.f;
#pragma unroll 8
        for (int kk = 0; kk < 128; kk++) {
            float4 av = *(const float4*)&Qst[kk * 68 + ty * 4];
            float4 bv = *(const float4*)&Kst[kk * 68 + tx * 4];
            float a[4] = {av.x, av.y, av.z, av.w};
            float b[4] = {bv.x, bv.y, bv.z, bv.w};
#pragma unroll
            for (int i = 0; i < 4; i++)
#pragma unroll
                for (int j = 0; j < 4; j++)
                    sreg[i][j] = fmaf(a[i], b[j], sreg[i][j]);
        }
        bool diag = (kb == qb);
#pragma unroll
        for (int i = 0; i < 4; i++)
#pragma unroll
            for (int j = 0; j < 4; j++) {
                float sv = sreg[i][j] * scale;
                if (diag && (tx * 4 + j) > (ty * 4 + i)) sv = -1e30f;
                sreg[i][j] = sv;
                Ss[(ty * 4 + i) * 65 + tx * 4 + j] = sv;
            }
        __syncthreads();

        if (tid < 64) {
            float mx = -1e30f;
            for (int c = 0; c < 64; c++) mx = fmaxf(mx, Ss[tid * 65 + c]);
            float mo = mrow[tid];
            float mn = fmaxf(mo, mx);
            mnew[tid] = mn;
            fsc[tid] = __expf(mo - mn);
        }
        __syncthreads();

        float psum[4] = {0.f, 0.f, 0.f, 0.f};
#pragma unroll
        for (int i = 0; i < 4; i++) {
            float mn = mnew[ty * 4 + i];
#pragma unroll
            for (int j = 0; j < 4; j++) {
                float p = __expf(sreg[i][j] - mn);
                Ss[(ty * 4 + i) * 65 + tx * 4 + j] = p;
                psum[i] += p;
            }
        }
#pragma unroll
        for (int i = 0; i < 4; i++) part[(ty * 4 + i) * 17 + tx] = psum[i];
        __syncthreads();

        if (tid < 64) {
            float s = 0.f;
            for (int x = 0; x < 16; x++) s += part[tid * 17 + x];
            lrow[tid] = lrow[tid] * fsc[tid] + s;
            mrow[tid] = mnew[tid];
        }

        float f = fsc[qr];
#pragma unroll
        for (int d = 0; d < 32; d++) acc[d] *= f;
        for (int kkk = 0; kkk < 64; kkk++) {
            float p = Ss[qr * 65 + kkk];
            const float* vr = &Vs[kkk * 132 + chunk * 32];
#pragma unroll
            for (int dd = 0; dd < 8; dd++) {
                float4 vv = *(const float4*)(vr + dd * 4);
                acc[dd * 4 + 0] = fmaf(p, vv.x, acc[dd * 4 + 0]);
                acc[dd * 4 + 1] = fmaf(p, vv.y, acc[dd * 4 + 1]);
                acc[dd * 4 + 2] = fmaf(p, vv.z, acc[dd * 4 + 2]);
                acc[dd * 4 + 3] = fmaf(p, vv.w, acc[dd * 4 + 3]);
            }
        }
    }
    __syncthreads();
    float linv = 1.f / lrow[qr];
    // tf32-round the attention output so the O-projection GEMM sees RNA operands
    float* op = Og + (size_t)(qb * 64 + qr) * HID + head * HD + chunk * 32;
#pragma unroll
    for (int dd = 0; dd < 8; dd++) {
        float4 o = make_float4(tf32_rna(acc[dd * 4 + 0] * linv),
                               tf32_rna(acc[dd * 4 + 1] * linv),
                               tf32_rna(acc[dd * 4 + 2] * linv),
                               tf32_rna(acc[dd * 4 + 3] * linv));
        *(float4*)(op + dd * 4) = o;
    }
}

// ---------------- launch ----------------
extern "C" void kernel_launch(void* const* d_in, const int* in_sizes, int n_in,
                              void* d_out, int out_size) {
    const float* hs   = (const float*)d_in[0];
    const float* wq   = (const float*)d_in[1];
    const float* wk   = (const float*)d_in[2];
    const float* wv   = (const float*)d_in[3];
    const float* wo   = (const float*)d_in[4];
    const float* scq  = (const float*)d_in[5];
    const float* sck  = (const float*)d_in[6];
    const float* scv  = (const float*)d_in[7];
    const float* sco  = (const float*)d_in[8];
    const float* pqkv = (const float*)d_in[9];
    const float* po   = (const float*)d_in[10];
    const float* cosT = (const float*)d_in[11];
    const float* sinT = (const float*)d_in[12];
    float* out = (float*)d_out;

    float *wmq, *wmk, *wmv, *wmo, *hst, *q, *k, *v, *ao;
    int *ipq, *ipo;
    cudaGetSymbolAddress((void**)&wmq, g_wmq);
    cudaGetSymbolAddress((void**)&wmk, g_wmk);
    cudaGetSymbolAddress((void**)&wmv, g_wmv);
    cudaGetSymbolAddress((void**)&wmo, g_wmo);
    cudaGetSymbolAddress((void**)&hst, g_hst);
    cudaGetSymbolAddress((void**)&q,   g_q);
    cudaGetSymbolAddress((void**)&k,   g_k);
    cudaGetSymbolAddress((void**)&v,   g_v);
    cudaGetSymbolAddress((void**)&ao,  g_ao);
    cudaGetSymbolAddress((void**)&ipq, g_invp_qkv);
    cudaGetSymbolAddress((void**)&ipo, g_invp_o);

    cudaFuncSetAttribute(gemm_tf32, cudaFuncAttributeMaxDynamicSharedMemorySize,
                         GEMM_SMEM_BYTES);
    int fl_smem = FL_SMEM_FLOATS * (int)sizeof(float);
    cudaFuncSetAttribute(flash_kernel, cudaFuncAttributeMaxDynamicSharedMemorySize, fl_smem);

    // Launch order chosen so the 6th launch (ncu -s 5 -c 1) is the big Q GEMM.
    round_tf32<<<(SEQ * HID / 4 + 255) / 256, 256>>>(hs, hst, SEQ * HID / 4);          // 1
    perm_extract<<<(HID * HID + 255) / 256, 256>>>(pqkv, ipq, HID);                    // 2
    mask_weights<<<(HID * (HID / 4) + 255) / 256, 256>>>(wq, scq, ipq, wmq, HID, HID); // 3
    mask_weights<<<(KVD * (HID / 4) + 255) / 256, 256>>>(wk, sck, ipq, wmk, KVD, HID); // 4
    mask_weights<<<(KVD * (HID / 4) + 255) / 256, 256>>>(wv, scv, ipq, wmv, KVD, HID); // 5

    gemm_tf32<<<dim3(HID / 128, SEQ / 128), 256, GEMM_SMEM_BYTES>>>(hst, wmq, q,       // 6 (profiled)
                                                                    SEQ, HID, HID);
    gemm_tf32<<<dim3(KVD / 128, SEQ / 128), 256, GEMM_SMEM_BYTES>>>(hst, wmk, k,
                                                                    SEQ, KVD, HID);
    gemm_tf32<<<dim3(KVD / 128, SEQ / 128), 256, GEMM_SMEM_BYTES>>>(hst, wmv, v,
                                                                    SEQ, KVD, HID);

    perm_extract<<<(HID * HID + 255) / 256, 256>>>(po, ipo, HID);
    mask_weights<<<(HID * (HID / 4) + 255) / 256, 256>>>(wo, sco, ipo, wmo, HID, HID);

    rope_kernel<<<(SEQ * NHEADS * 64 + 255) / 256, 256>>>(q, cosT, sinT, NHEADS);
    rope_kernel<<<(SEQ * NKVH * 64 + 255) / 256, 256>>>(k, cosT, sinT, NKVH);

    flash_kernel<<<dim3(SEQ / 64, NHEADS), 256, fl_smem>>>(q, k, v, ao);

    gemm_tf32<<<dim3(HID / 128, SEQ / 128), 256, GEMM_SMEM_BYTES>>>(ao, wmo, out,
                                                                    SEQ, HID, HID);
}

// round 4
// speedup vs baseline: 3.8244x; 3.8244x over previous
#include <cuda_runtime.h>
#include <cstdint>

#define HID 4096
#define KVD 1024
#define SEQ 2048
#define NHEADS 32
#define NKVH 8
#define HD 128

// ---------------- scratch ----------------
__device__ float g_wmq[HID * HID];
__device__ float g_wmo[HID * HID];
__device__ float g_wmk[KVD * HID];
__device__ float g_wmv[KVD * HID];
__device__ float g_hst[SEQ * HID];
__device__ float g_q[SEQ * HID];
__device__ float g_k[SEQ * KVD];
__device__ float g_v[SEQ * KVD];
__device__ float g_ao[SEQ * HID];
__device__ int   g_invp_qkv[HID];
__device__ int   g_invp_o[HID];

__device__ __forceinline__ float tf32_rna(float x) {
    uint32_t u;
    asm("cvt.rna.tf32.f32 %0, %1;" : "=r"(u) : "f"(x));
    return __uint_as_float(u);
}
// k-interleave within 8-group: orig o -> stored 2o (o<4) else 2(o-4)+1
__device__ __forceinline__ int perm8(int o) { return ((o & 3) << 1) | (o >> 2); }
__device__ __forceinline__ int pcol(int c) { return (c & ~7) | perm8(c & 7); }
#define U(x) __float_as_uint(x)

// ---------------- permutation extraction ----------------
__global__ void perm_extract(const float* __restrict__ P, int* __restrict__ invp, int n) {
    int idx = blockIdx.x * blockDim.x + threadIdx.x;
    if (idx >= n * n) return;
    if (P[idx] > 0.5f) invp[idx % n] = idx / n;
}

// ---------------- hidden states: tf32 round + k-interleave ----------------
__global__ void round_tf32_perm(const float* __restrict__ X, float* __restrict__ Y, int ngrp) {
    int i = blockIdx.x * blockDim.x + threadIdx.x;
    if (i >= ngrp) return;
    const float4* p = (const float4*)(X + (size_t)i * 8);
    float4 a = p[0], b = p[1];
    float4 o0 = make_float4(tf32_rna(a.x), tf32_rna(b.x), tf32_rna(a.y), tf32_rna(b.y));
    float4 o1 = make_float4(tf32_rna(a.z), tf32_rna(b.z), tf32_rna(a.w), tf32_rna(b.w));
    float4* q = (float4*)(Y + (size_t)i * 8);
    q[0] = o0; q[1] = o1;
}

// ---------------- 2:4 hard mask -> tf32, k-interleaved output ----------------
__global__ void mask_weights(const float* __restrict__ W, const float* __restrict__ scaler,
                             const int* __restrict__ invp, float* __restrict__ Wm,
                             int R, int H) {
    int idx = blockIdx.x * blockDim.x + threadIdx.x;
    int G = H >> 2;
    if (idx >= R * G) return;
    int r = idx / G, g = idx % G;
    int c[4]; float w[4], m[4];
#pragma unroll
    for (int t = 0; t < 4; t++) {
        c[t] = invp[4 * g + t];
        w[t] = W[(size_t)r * H + c[t]];
        m[t] = fabsf(w[t]) * sqrtf(scaler[c[t]]);
    }
#pragma unroll
    for (int t = 0; t < 4; t++) {
        int rank = 0;
#pragma unroll
        for (int u = 0; u < 4; u++)
            rank += (m[u] > m[t]) || (m[u] == m[t] && u < t);
        Wm[(size_t)r * H + pcol(c[t])] = (rank < 2) ? tf32_rna(w[t]) : 0.0f;
    }
}

// ---------------- tf32 NT GEMM, interleaved-K operands ----------------
#define GS 40
#define STAGE_F (128 * GS)
#define GEMM_SMEM_BYTES (4 * STAGE_F * 4)

__device__ __forceinline__ void mma_tf32(float c[4], uint32_t a0, uint32_t a1,
                                         uint32_t a2, uint32_t a3,
                                         uint32_t b0, uint32_t b1) {
    asm volatile(
        "mma.sync.aligned.m16n8k8.row.col.f32.tf32.tf32.f32 "
        "{%0,%1,%2,%3}, {%4,%5,%6,%7}, {%8,%9}, {%0,%1,%2,%3};"
        : "+f"(c[0]), "+f"(c[1]), "+f"(c[2]), "+f"(c[3])
        : "r"(a0), "r"(a1), "r"(a2), "r"(a3), "r"(b0), "r"(b1));
}

__global__ void __launch_bounds__(256) gemm_tf32(const float* __restrict__ A,
                                                 const float* __restrict__ B,
                                                 float* __restrict__ C,
                                                 int M, int N, int K) {
    extern __shared__ float sm[];
    float* As = sm;
    float* Bs = sm + 2 * STAGE_F;

    const int tid = threadIdx.x;
    const int wid = tid >> 5, lane = tid & 31;
    const int g = lane >> 2, tg = lane & 3;
    const int wm = (wid >> 2) * 64, wn = (wid & 3) * 32;
    const int bm = blockIdx.y * 128, bn = blockIdx.x * 128;
    const int ar = tid >> 3, ac = (tid & 7) * 4;

    float acc[4][4][4] = {};

    const float* Ag = A + (size_t)(bm + ar) * K + ac;
    const float* Bg = B + (size_t)(bn + ar) * K + ac;

    uint32_t sA = (uint32_t)__cvta_generic_to_shared(As);
    uint32_t sB = (uint32_t)__cvta_generic_to_shared(Bs);

#define LOAD_STAGE(s, k0)                                                        \
    do {                                                                         \
        uint32_t soff = (uint32_t)(s) * STAGE_F * 4;                             \
        _Pragma("unroll")                                                        \
        for (int i = 0; i < 4; i++) {                                            \
            uint32_t da = sA + soff + ((ar + i * 32) * GS + ac) * 4;             \
            uint32_t db = sB + soff + ((ar + i * 32) * GS + ac) * 4;             \
            const float* pa = Ag + (size_t)i * 32 * K + (k0);                    \
            const float* pb = Bg + (size_t)i * 32 * K + (k0);                    \
            asm volatile("cp.async.cg.shared.global [%0], [%1], 16;" ::"r"(da), "l"(pa)); \
            asm volatile("cp.async.cg.shared.global [%0], [%1], 16;" ::"r"(db), "l"(pb)); \
        }                                                                        \
    } while (0)

    LOAD_STAGE(0, 0);
    asm volatile("cp.async.commit_group;");

    const int nk = K >> 5;
    for (int t = 0; t < nk; t++) {
        int s = t & 1;
        if (t + 1 < nk) LOAD_STAGE(s ^ 1, (t + 1) * 32);
        asm volatile("cp.async.commit_group;");
        asm volatile("cp.async.wait_group 1;");
        __syncthreads();

        const float* Ast = As + s * STAGE_F;
        const float* Bst = Bs + s * STAGE_F;
#pragma unroll
        for (int kk = 0; kk < 32; kk += 8) {
            // interleaved layout: frag pair (k=tg, k=tg+4) adjacent -> LDS.64
            float2 bf[4];
#pragma unroll
            for (int ni = 0; ni < 4; ni++)
                bf[ni] = *(const float2*)&Bst[(wn + ni * 8 + g) * GS + kk + 2 * tg];
#pragma unroll
            for (int mi = 0; mi < 4; mi++) {
                int rm = (wm + mi * 16 + g) * GS + kk + 2 * tg;
                float2 alo = *(const float2*)&Ast[rm];            // (a0,a2)
                float2 ahi = *(const float2*)&Ast[rm + 8 * GS];   // (a1,a3)
#pragma unroll
                for (int ni = 0; ni < 4; ni++)
                    mma_tf32(acc[mi][ni], U(alo.x), U(ahi.x), U(alo.y), U(ahi.y),
                             U(bf[ni].x), U(bf[ni].y));
            }
        }
        __syncthreads();
    }

#pragma unroll
    for (int mi = 0; mi < 4; mi++)
#pragma unroll
        for (int ni = 0; ni < 4; ni++) {
            int row = bm + wm + mi * 16 + g;
            int col = bn + wn + ni * 8 + tg * 2;
            *(float2*)&C[(size_t)row * N + col] =
                make_float2(acc[mi][ni][0], acc[mi][ni][1]);
            *(float2*)&C[(size_t)(row + 8) * N + col] =
                make_float2(acc[mi][ni][2], acc[mi][ni][3]);
        }
#undef LOAD_STAGE
}

// ---------------- RoPE (in place, paired halves) ----------------
__global__ void rope_kernel(float* __restrict__ X, const float* __restrict__ cosT,
                            const float* __restrict__ sinT, int nheads) {
    int idx = blockIdx.x * blockDim.x + threadIdx.x;
    int total = SEQ * nheads * 64;
    if (idx >= total) return;
    int d = idx & 63;
    int h = (idx >> 6) % nheads;
    int s = idx / (64 * nheads);
    float* p = X + (size_t)s * nheads * HD + h * HD + d;
    float x1 = p[0], x2 = p[64];
    float c1 = cosT[s * HD + d],      s1 = sinT[s * HD + d];
    float c2 = cosT[s * HD + 64 + d], s2 = sinT[s * HD + 64 + d];
    p[0]  = fmaf(x1, c1, -x2 * s1);
    p[64] = fmaf(x2, c2,  x1 * s2);
}

// ---------------- tensor-core causal flash attention (tf32) ----------------
// CTA: 128 q-rows x one head. 8 warps, 16 rows/warp. kv-blocks of 64.
#define FSTR 132
#define FL2_SMEM ((128 + 64 + 64) * FSTR * 4)

__global__ void __launch_bounds__(256) flash_tc(const float* __restrict__ Qg,
                                                const float* __restrict__ Kg,
                                                const float* __restrict__ Vg,
                                                float* __restrict__ Og) {
    extern __shared__ float sm[];
    float* Qst = sm;                 // [128][FSTR]
    float* Kst = Qst + 128 * FSTR;   // [64][FSTR]
    float* Vs  = Kst + 64 * FSTR;    // [64][FSTR]

    const int tid = threadIdx.x, wid = tid >> 5, lane = tid & 31;
    const int g = lane >> 2, tg = lane & 3;
    const int qb = blockIdx.x, head = blockIdx.y, kvh = head >> 2;
    const float* Qh = Qg + head * HD;
    const float* Kh = Kg + kvh * HD;
    const float* Vh = Vg + kvh * HD;

    // fill Q tile (row-major, tf32-rounded)
#pragma unroll
    for (int i = 0; i < 16; i++) {
        int lin = tid + i * 256;
        int r = lin >> 5, c4 = lin & 31;
        float4 v = *(const float4*)&Qh[(size_t)(qb * 128 + r) * HID + c4 * 4];
        v.x = tf32_rna(v.x); v.y = tf32_rna(v.y);
        v.z = tf32_rna(v.z); v.w = tf32_rna(v.w);
        *(float4*)&Qst[r * FSTR + c4 * 4] = v;
    }

    const int wm = wid * 16;
    const int row0 = qb * 128 + wm + g, row1 = row0 + 8;
    const int rowTop = qb * 128 + wm + 15;
    float m0 = -1e30f, m1 = -1e30f, l0 = 0.f, l1 = 0.f;
    float oacc[16][4];
#pragma unroll
    for (int i = 0; i < 16; i++)
#pragma unroll
        for (int j = 0; j < 4; j++) oacc[i][j] = 0.f;

    const float scale = 0.08838834764831845f;
    const int nkb = 2 * qb + 2;

    for (int kb = 0; kb < nkb; kb++) {
        __syncthreads();
#pragma unroll
        for (int i = 0; i < 8; i++) {
            int lin = tid + i * 256;
            int r = lin >> 5, c4 = lin & 31;
            float4 kv = *(const float4*)&Kh[(size_t)(kb * 64 + r) * KVD + c4 * 4];
            kv.x = tf32_rna(kv.x); kv.y = tf32_rna(kv.y);
            kv.z = tf32_rna(kv.z); kv.w = tf32_rna(kv.w);
            *(float4*)&Kst[r * FSTR + c4 * 4] = kv;
            float4 vv = *(const float4*)&Vh[(size_t)(kb * 64 + r) * KVD + c4 * 4];
            vv.x = tf32_rna(vv.x); vv.y = tf32_rna(vv.y);
            vv.z = tf32_rna(vv.z); vv.w = tf32_rna(vv.w);
            *(float4*)&Vs[r * FSTR + c4 * 4] = vv;
        }
        __syncthreads();
        if (kb * 64 > rowTop) continue;   // whole block masked for this warp

        // S = Q K^T (16 x 64 per warp)
        float sacc[8][4];
#pragma unroll
        for (int ni = 0; ni < 8; ni++)
#pragma unroll
            for (int j = 0; j < 4; j++) sacc[ni][j] = 0.f;
#pragma unroll
        for (int kk = 0; kk < 16; kk++) {
            int ka = kk * 8 + tg;
            float a0 = Qst[(wm + g) * FSTR + ka];
            float a1 = Qst[(wm + g + 8) * FSTR + ka];
            float a2 = Qst[(wm + g) * FSTR + ka + 4];
            float a3 = Qst[(wm + g + 8) * FSTR + ka + 4];
#pragma unroll
            for (int ni = 0; ni < 8; ni++) {
                float b0 = Kst[(ni * 8 + g) * FSTR + ka];
                float b1 = Kst[(ni * 8 + g) * FSTR + ka + 4];
                mma_tf32(sacc[ni], U(a0), U(a1), U(a2), U(a3), U(b0), U(b1));
            }
        }

        // scale + causal mask
#pragma unroll
        for (int ni = 0; ni < 8; ni++) {
            int c0 = kb * 64 + ni * 8 + 2 * tg, c1 = c0 + 1;
            sacc[ni][0] = (c0 <= row0) ? sacc[ni][0] * scale : -1e30f;
            sacc[ni][1] = (c1 <= row0) ? sacc[ni][1] * scale : -1e30f;
            sacc[ni][2] = (c0 <= row1) ? sacc[ni][2] * scale : -1e30f;
            sacc[ni][3] = (c1 <= row1) ? sacc[ni][3] * scale : -1e30f;
        }

        // online softmax (registers + quad shuffles; quad lanes share rows)
        float mx0 = -1e30f, mx1 = -1e30f;
#pragma unroll
        for (int ni = 0; ni < 8; ni++) {
            mx0 = fmaxf(mx0, fmaxf(sacc[ni][0], sacc[ni][1]));
            mx1 = fmaxf(mx1, fmaxf(sacc[ni][2], sacc[ni][3]));
        }
        mx0 = fmaxf(mx0, __shfl_xor_sync(0xffffffffu, mx0, 1));
        mx0 = fmaxf(mx0, __shfl_xor_sync(0xffffffffu, mx0, 2));
        mx1 = fmaxf(mx1, __shfl_xor_sync(0xffffffffu, mx1, 1));
        mx1 = fmaxf(mx1, __shfl_xor_sync(0xffffffffu, mx1, 2));
        float mn0 = fmaxf(m0, mx0), mn1 = fmaxf(m1, mx1);
        float fs0 = __expf(m0 - mn0), fs1 = __expf(m1 - mn1);

        float ps0 = 0.f, ps1 = 0.f;
#pragma unroll
        for (int ni = 0; ni < 8; ni++) {
            float p0 = (sacc[ni][0] > -1e29f) ? tf32_rna(__expf(sacc[ni][0] - mn0)) : 0.f;
            float p1 = (sacc[ni][1] > -1e29f) ? tf32_rna(__expf(sacc[ni][1] - mn0)) : 0.f;
            float p2 = (sacc[ni][2] > -1e29f) ? tf32_rna(__expf(sacc[ni][2] - mn1)) : 0.f;
            float p3 = (sacc[ni][3] > -1e29f) ? tf32_rna(__expf(sacc[ni][3] - mn1)) : 0.f;
            sacc[ni][0] = p0; sacc[ni][1] = p1; sacc[ni][2] = p2; sacc[ni][3] = p3;
            ps0 += p0 + p1; ps1 += p2 + p3;
        }
        ps0 += __shfl_xor_sync(0xffffffffu, ps0, 1);
        ps0 += __shfl_xor_sync(0xffffffffu, ps0, 2);
        ps1 += __shfl_xor_sync(0xffffffffu, ps1, 1);
        ps1 += __shfl_xor_sync(0xffffffffu, ps1, 2);
        l0 = l0 * fs0 + ps0; l1 = l1 * fs1 + ps1;
        m0 = mn0; m1 = mn1;

#pragma unroll
        for (int nd = 0; nd < 16; nd++) {
            oacc[nd][0] *= fs0; oacc[nd][1] *= fs0;
            oacc[nd][2] *= fs1; oacc[nd][3] *= fs1;
        }

        // O += P V ; P C-frag == A-frag under 8-group interleave absorbed
        // into the V row address (kk*8+2tg, +1): a = (c0,c2,c1,c3).
#pragma unroll
        for (int kk = 0; kk < 8; kk++) {
            uint32_t a0 = U(sacc[kk][0]), a1 = U(sacc[kk][2]);
            uint32_t a2 = U(sacc[kk][1]), a3 = U(sacc[kk][3]);
            int vr = (kk * 8 + 2 * tg) * FSTR;
#pragma unroll
            for (int nd = 0; nd < 16; nd++) {
                float b0 = Vs[vr + nd * 8 + g];
                float b1 = Vs[vr + FSTR + nd * 8 + g];
                mma_tf32(oacc[nd], a0, a1, a2, a3, U(b0), U(b1));
            }
        }
    }

    // epilogue: normalize, tf32-round, store with O-GEMM k-interleave
    float li0 = 1.f / l0, li1 = 1.f / l1;
#pragma unroll
    for (int nd = 0; nd < 16; nd++)
#pragma unroll
        for (int j = 0; j < 2; j++) {
            int d = nd * 8 + 2 * tg + j;
            int col = head * HD + pcol(d);
            Og[(size_t)row0 * HID + col] = tf32_rna(oacc[nd][j] * li0);
            Og[(size_t)row1 * HID + col] = tf32_rna(oacc[nd][j + 2] * li1);
        }
}

// ---------------- launch ----------------
extern "C" void kernel_launch(void* const* d_in, const int* in_sizes, int n_in,
                              void* d_out, int out_size) {
    const float* hs   = (const float*)d_in[0];
    const float* wq   = (const float*)d_in[1];
    const float* wk   = (const float*)d_in[2];
    const float* wv   = (const float*)d_in[3];
    const float* wo   = (const float*)d_in[4];
    const float* scq  = (const float*)d_in[5];
    const float* sck  = (const float*)d_in[6];
    const float* scv  = (const float*)d_in[7];
    const float* sco  = (const float*)d_in[8];
    const float* pqkv = (const float*)d_in[9];
    const float* po   = (const float*)d_in[10];
    const float* cosT = (const float*)d_in[11];
    const float* sinT = (const float*)d_in[12];
    float* out = (float*)d_out;

    float *wmq, *wmk, *wmv, *wmo, *hst, *q, *k, *v, *ao;
    int *ipq, *ipo;
    cudaGetSymbolAddress((void**)&wmq, g_wmq);
    cudaGetSymbolAddress((void**)&wmk, g_wmk);
    cudaGetSymbolAddress((void**)&wmv, g_wmv);
    cudaGetSymbolAddress((void**)&wmo, g_wmo);
    cudaGetSymbolAddress((void**)&hst, g_hst);
    cudaGetSymbolAddress((void**)&q,   g_q);
    cudaGetSymbolAddress((void**)&k,   g_k);
    cudaGetSymbolAddress((void**)&v,   g_v);
    cudaGetSymbolAddress((void**)&ao,  g_ao);
    cudaGetSymbolAddress((void**)&ipq, g_invp_qkv);
    cudaGetSymbolAddress((void**)&ipo, g_invp_o);

    cudaFuncSetAttribute(gemm_tf32, cudaFuncAttributeMaxDynamicSharedMemorySize,
                         GEMM_SMEM_BYTES);
    cudaFuncSetAttribute(flash_tc, cudaFuncAttributeMaxDynamicSharedMemorySize,
                         FL2_SMEM);

    round_tf32_perm<<<(SEQ * HID / 8 + 255) / 256, 256>>>(hs, hst, SEQ * HID / 8); // 1
    perm_extract<<<(HID * HID + 255) / 256, 256>>>(pqkv, ipq, HID);                // 2
    mask_weights<<<(HID * (HID / 4) + 255) / 256, 256>>>(wq, scq, ipq, wmq, HID, HID); // 3
    mask_weights<<<(KVD * (HID / 4) + 255) / 256, 256>>>(wk, sck, ipq, wmk, KVD, HID); // 4
    gemm_tf32<<<dim3(HID / 128, SEQ / 128), 256, GEMM_SMEM_BYTES>>>(hst, wmq, q,   // 5 (profiled)
                                                                    SEQ, HID, HID);
    gemm_tf32<<<dim3(KVD / 128, SEQ / 128), 256, GEMM_SMEM_BYTES>>>(hst, wmk, k,   // 6
                                                                    SEQ, KVD, HID);
    mask_weights<<<(KVD * (HID / 4) + 255) / 256, 256>>>(wv, scv, ipq, wmv, KVD, HID);
    gemm_tf32<<<dim3(KVD / 128, SEQ / 128), 256, GEMM_SMEM_BYTES>>>(hst, wmv, v,
                                                                    SEQ, KVD, HID);
    perm_extract<<<(HID * HID + 255) / 256, 256>>>(po, ipo, HID);
    mask_weights<<<(HID * (HID / 4) + 255) / 256, 256>>>(wo, sco, ipo, wmo, HID, HID);

    rope_kernel<<<(SEQ * NHEADS * 64 + 255) / 256, 256>>>(q, cosT, sinT, NHEADS);
    rope_kernel<<<(SEQ * NKVH * 64 + 255) / 256, 256>>>(k, cosT, sinT, NKVH);

    flash_tc<<<dim3(SEQ / 128, NHEADS), 256, FL2_SMEM>>>(q, k, v, ao);

    gemm_tf32<<<dim3(HID / 128, SEQ / 128), 256, GEMM_SMEM_BYTES>>>(ao, wmo, out,
                                                                    SEQ, HID, HID);
}

// round 6
// speedup vs baseline: 5.0922x; 1.3315x over previous
#include <cuda_runtime.h>
#include <cuda_fp16.h>
#include <cstdint>

#define HID 4096
#define KVD 1024
#define SEQ 2048
#define NHEADS 32
#define NKVH 8
#define HD 128

// ---------------- scratch ----------------
__device__ __half g_wmq[HID * HID];
__device__ __half g_wmo[HID * HID];
__device__ __half g_wmk[KVD * HID];
__device__ __half g_wmv[KVD * HID];
__device__ __half g_hst[SEQ * HID];
__device__ float  g_q[SEQ * HID];
__device__ float  g_k[SEQ * KVD];
__device__ float  g_v[SEQ * KVD];
__device__ __half g_ao[SEQ * HID];
__device__ int    g_invp_qkv[HID];
__device__ int    g_invp_o[HID];

__device__ __forceinline__ uint32_t smem_u32(const void* p) {
    return (uint32_t)__cvta_generic_to_shared((void*)p);
}
__device__ __forceinline__ uint32_t packh2(float x, float y) {
    __half2 h = __floats2half2_rn(x, y);
    return *(uint32_t*)&h;
}
__device__ __forceinline__ void ldm_x4(uint32_t (&r)[4], uint32_t addr) {
    asm volatile("ldmatrix.sync.aligned.m8n8.x4.shared.b16 {%0,%1,%2,%3}, [%4];"
                 : "=r"(r[0]), "=r"(r[1]), "=r"(r[2]), "=r"(r[3]) : "r"(addr));
}
__device__ __forceinline__ void ldm_x4_t(uint32_t (&r)[4], uint32_t addr) {
    asm volatile("ldmatrix.sync.aligned.m8n8.x4.trans.shared.b16 {%0,%1,%2,%3}, [%4];"
                 : "=r"(r[0]), "=r"(r[1]), "=r"(r[2]), "=r"(r[3]) : "r"(addr));
}
__device__ __forceinline__ void mma_fp16(float c[4], uint32_t a0, uint32_t a1,
                                         uint32_t a2, uint32_t a3,
                                         uint32_t b0, uint32_t b1) {
    asm volatile(
        "mma.sync.aligned.m16n8k16.row.col.f32.f16.f16.f32 "
        "{%0,%1,%2,%3}, {%4,%5,%6,%7}, {%8,%9}, {%0,%1,%2,%3};"
        : "+f"(c[0]), "+f"(c[1]), "+f"(c[2]), "+f"(c[3])
        : "r"(a0), "r"(a1), "r"(a2), "r"(a3), "r"(b0), "r"(b1));
}

// ---------------- permutation extraction ----------------
__global__ void perm_extract(const float* __restrict__ P, int* __restrict__ invp, int n) {
    int idx = blockIdx.x * blockDim.x + threadIdx.x;
    if (idx >= n * n) return;
    if (P[idx] > 0.5f) invp[idx % n] = idx / n;
}

// ---------------- hidden states: fp32 -> fp16 ----------------
__global__ void round_half(const float* __restrict__ X, __half* __restrict__ Y, int n8) {
    int i = blockIdx.x * blockDim.x + threadIdx.x;
    if (i >= n8) return;
    const float4* p = (const float4*)(X + (size_t)i * 8);
    float4 a = p[0], b = p[1];
    uint4 o;
    o.x = packh2(a.x, a.y); o.y = packh2(a.z, a.w);
    o.z = packh2(b.x, b.y); o.w = packh2(b.z, b.w);
    *(uint4*)(Y + (size_t)i * 8) = o;
}

// ---------------- 2:4 hard mask (wanda metric, permuted groups) -> fp16 --------
__global__ void mask_weights(const float* __restrict__ W, const float* __restrict__ scaler,
                             const int* __restrict__ invp, __half* __restrict__ Wm,
                             int R, int H) {
    int idx = blockIdx.x * blockDim.x + threadIdx.x;
    int G = H >> 2;
    if (idx >= R * G) return;
    int r = idx / G, g = idx % G;
    int c[4]; float w[4], m[4];
#pragma unroll
    for (int t = 0; t < 4; t++) {
        c[t] = invp[4 * g + t];
        w[t] = W[(size_t)r * H + c[t]];
        m[t] = fabsf(w[t]) * sqrtf(scaler[c[t]]);
    }
#pragma unroll
    for (int t = 0; t < 4; t++) {
        int rank = 0;
#pragma unroll
        for (int u = 0; u < 4; u++)
            rank += (m[u] > m[t]) || (m[u] == m[t] && u < t);
        Wm[(size_t)r * H + c[t]] = __float2half_rn((rank < 2) ? w[t] : 0.0f);
    }
}

// ---------------- fp16 NT GEMM: C[M,N](f32) = Ah[M,K] * Bh[N,K]^T ---------------
// 128x128x32 tiles, 256 threads, warp 64x32, double-buffered cp.async, ldmatrix.
#define GS2 40                    // smem row stride (halves); 80B = 5x16B (odd -> conflict-free)
#define STGH (128 * GS2)          // halves per operand-stage
#define STGB (STGH * 2)           // bytes per operand-stage
#define GEMM_SMEM (4 * STGB)

__global__ void __launch_bounds__(256) gemm_fp16(const __half* __restrict__ A,
                                                 const __half* __restrict__ B,
                                                 float* __restrict__ C,
                                                 int M, int N, int K) {
    extern __shared__ __half sh[];
    __half* As = sh;
    __half* Bs = sh + 2 * STGH;

    const int tid = threadIdx.x, wid = tid >> 5, lane = tid & 31;
    const int g = lane >> 2, tg = lane & 3;
    const int wm = (wid >> 2) * 64, wn = (wid & 3) * 32;
    const int bm = blockIdx.y * 128, bn = blockIdx.x * 128;
    const int ar = tid >> 2, ac = (tid & 3) * 8;

    float acc[4][4][4] = {};

    const __half* Ag = A + (size_t)(bm + ar) * K + ac;
    const __half* Bg = B + (size_t)(bn + ar) * K + ac;
    uint32_t sA = smem_u32(As), sB = smem_u32(Bs);

    // ldmatrix lane address pieces (halves)
    const int lrA = wm + (lane & 15), lcA = (lane >> 4) << 3;
    const int lrB = wn + (lane & 7) + ((lane >> 4) << 3), lcB = ((lane >> 3) & 1) << 3;

#define LOAD_STAGE(s, k0)                                                          \
    do {                                                                           \
        uint32_t so = (uint32_t)(s) * STGB;                                        \
        _Pragma("unroll")                                                          \
        for (int i = 0; i < 2; i++) {                                              \
            uint32_t d = (uint32_t)(((ar + i * 64) * GS2 + ac) * 2);               \
            const __half* pa = Ag + (size_t)i * 64 * K + (k0);                     \
            const __half* pb = Bg + (size_t)i * 64 * K + (k0);                     \
            asm volatile("cp.async.cg.shared.global [%0], [%1], 16;"               \
                         ::"r"(sA + so + d), "l"(pa));                             \
            asm volatile("cp.async.cg.shared.global [%0], [%1], 16;"               \
                         ::"r"(sB + so + d), "l"(pb));                             \
        }                                                                          \
        asm volatile("cp.async.commit_group;");                                    \
    } while (0)

    LOAD_STAGE(0, 0);

    const int nk = K >> 5;
    for (int t = 0; t < nk; t++) {
        int s = t & 1;
        if (t + 1 < nk) LOAD_STAGE(s ^ 1, (t + 1) * 32);
        else asm volatile("cp.async.commit_group;");
        asm volatile("cp.async.wait_group 1;");
        __syncthreads();

        uint32_t a_s = sA + (uint32_t)s * STGB;
        uint32_t b_s = sB + (uint32_t)s * STGB;
#pragma unroll
        for (int ks = 0; ks < 2; ks++) {
            int kb = ks * 16;
            uint32_t bt[2][4];
            ldm_x4(bt[0], b_s + (uint32_t)((lrB * GS2 + lcB + kb) * 2));
            ldm_x4(bt[1], b_s + (uint32_t)(((lrB + 16) * GS2 + lcB + kb) * 2));
#pragma unroll
            for (int mi = 0; mi < 4; mi++) {
                uint32_t af[4];
                ldm_x4(af, a_s + (uint32_t)(((lrA + mi * 16) * GS2 + lcA + kb) * 2));
#pragma unroll
                for (int nb = 0; nb < 2; nb++) {
                    mma_fp16(acc[mi][2 * nb], af[0], af[1], af[2], af[3],
                             bt[nb][0], bt[nb][1]);
                    mma_fp16(acc[mi][2 * nb + 1], af[0], af[1], af[2], af[3],
                             bt[nb][2], bt[nb][3]);
                }
            }
        }
        __syncthreads();
    }

#pragma unroll
    for (int mi = 0; mi < 4; mi++)
#pragma unroll
        for (int ni = 0; ni < 4; ni++) {
            int row = bm + wm + mi * 16 + g;
            int col = bn + wn + ni * 8 + tg * 2;
            *(float2*)&C[(size_t)row * N + col] =
                make_float2(acc[mi][ni][0], acc[mi][ni][1]);
            *(float2*)&C[(size_t)(row + 8) * N + col] =
                make_float2(acc[mi][ni][2], acc[mi][ni][3]);
        }
#undef LOAD_STAGE
}

// ---------------- RoPE (in place, paired halves, fp32) ----------------
__global__ void rope_kernel(float* __restrict__ X, const float* __restrict__ cosT,
                            const float* __restrict__ sinT, int nheads) {
    int idx = blockIdx.x * blockDim.x + threadIdx.x;
    int total = SEQ * nheads * 64;
    if (idx >= total) return;
    int d = idx & 63;
    int h = (idx >> 6) % nheads;
    int s = idx / (64 * nheads);
    float* p = X + (size_t)s * nheads * HD + h * HD + d;
    float x1 = p[0], x2 = p[64];
    float c1 = cosT[s * HD + d],      s1 = sinT[s * HD + d];
    float c2 = cosT[s * HD + 64 + d], s2 = sinT[s * HD + 64 + d];
    p[0]  = fmaf(x1, c1, -x2 * s1);
    p[64] = fmaf(x2, c2,  x1 * s2);
}

// ---------------- fp16 tensor-core causal flash attention ----------------
// CTA: 128 q-rows x one head, 8 warps (16 rows each), kv-blocks of 64.
#define QSTR 136                        // halves; 272B = 17x16B (odd)
#define FL3_SMEM ((128 + 64 + 64) * QSTR * 2)

__global__ void __launch_bounds__(256) flash_fp16(const float* __restrict__ Qg,
                                                  const float* __restrict__ Kg,
                                                  const float* __restrict__ Vg,
                                                  __half* __restrict__ Og) {
    extern __shared__ __half sm[];
    __half* Qs = sm;                    // [128][QSTR]
    __half* Ks = Qs + 128 * QSTR;       // [64][QSTR]
    __half* Vs = Ks + 64 * QSTR;        // [64][QSTR]

    const int tid = threadIdx.x, wid = tid >> 5, lane = tid & 31;
    const int g = lane >> 2, tg = lane & 3;
    const int qb = blockIdx.x, head = blockIdx.y, kvh = head >> 2;
    const float* Qh = Qg + head * HD;
    const float* Kh = Kg + kvh * HD;
    const float* Vh = Vg + kvh * HD;

    uint32_t sQ = smem_u32(Qs), sK = smem_u32(Ks), sV = smem_u32(Vs);

    // fill Q tile (fp32 -> fp16)
#pragma unroll
    for (int i = 0; i < 16; i++) {
        int lin = tid + i * 256;
        int r = lin >> 5, c4 = lin & 31;
        float4 v = *(const float4*)&Qh[(size_t)(qb * 128 + r) * HID + c4 * 4];
        uint2 o; o.x = packh2(v.x, v.y); o.y = packh2(v.z, v.w);
        *(uint2*)&Qs[r * QSTR + c4 * 4] = o;
    }

    const int wm = wid * 16;
    const int row0 = qb * 128 + wm + g, row1 = row0 + 8;
    const int rowTop = qb * 128 + wm + 15;
    float m0 = -1e30f, m1 = -1e30f, l0 = 0.f, l1 = 0.f;
    float oacc[16][4];
#pragma unroll
    for (int i = 0; i < 16; i++)
#pragma unroll
        for (int j = 0; j < 4; j++) oacc[i][j] = 0.f;

    const float scale = 0.08838834764831845f;
    const int nkb = 2 * qb + 2;

    // ldmatrix lane pieces
    const int lrA = wm + (lane & 15), lcA = (lane >> 4) << 3;   // Q (A, non-trans)
    const int lrK = (lane & 7) + ((lane >> 4) << 3), lcK = ((lane >> 3) & 1) << 3; // K (B)
    const int lrV = (lane & 7) + (((lane >> 3) & 1) << 3), lcV = (lane >> 4) << 3; // V (.trans)

    for (int kb = 0; kb < nkb; kb++) {
        __syncthreads();
#pragma unroll
        for (int i = 0; i < 8; i++) {
            int lin = tid + i * 256;
            int r = lin >> 5, c4 = lin & 31;
            float4 kv = *(const float4*)&Kh[(size_t)(kb * 64 + r) * KVD + c4 * 4];
            uint2 ok; ok.x = packh2(kv.x, kv.y); ok.y = packh2(kv.z, kv.w);
            *(uint2*)&Ks[r * QSTR + c4 * 4] = ok;
            float4 vv = *(const float4*)&Vh[(size_t)(kb * 64 + r) * KVD + c4 * 4];
            uint2 ov; ov.x = packh2(vv.x, vv.y); ov.y = packh2(vv.z, vv.w);
            *(uint2*)&Vs[r * QSTR + c4 * 4] = ov;
        }
        __syncthreads();
        if (kb * 64 > rowTop) continue;

        // S = Q K^T : 16 x 64 per warp
        float sacc[8][4];
#pragma unroll
        for (int ni = 0; ni < 8; ni++)
#pragma unroll
            for (int j = 0; j < 4; j++) sacc[ni][j] = 0.f;
#pragma unroll
        for (int ks = 0; ks < 8; ks++) {
            int kk = ks * 16;
            uint32_t af[4];
            ldm_x4(af, sQ + (uint32_t)((lrA * QSTR + kk + lcA) * 2));
#pragma unroll
            for (int nb = 0; nb < 4; nb++) {
                uint32_t bt[4];
                ldm_x4(bt, sK + (uint32_t)(((nb * 16 + lrK) * QSTR + kk + lcK) * 2));
                mma_fp16(sacc[2 * nb], af[0], af[1], af[2], af[3], bt[0], bt[1]);
                mma_fp16(sacc[2 * nb + 1], af[0], af[1], af[2], af[3], bt[2], bt[3]);
            }
        }

        // scale + causal mask
#pragma unroll
        for (int ni = 0; ni < 8; ni++) {
            int c0 = kb * 64 + ni * 8 + 2 * tg, c1 = c0 + 1;
            sacc[ni][0] = (c0 <= row0) ? sacc[ni][0] * scale : -1e30f;
            sacc[ni][1] = (c1 <= row0) ? sacc[ni][1] * scale : -1e30f;
            sacc[ni][2] = (c0 <= row1) ? sacc[ni][2] * scale : -1e30f;
            sacc[ni][3] = (c1 <= row1) ? sacc[ni][3] * scale : -1e30f;
        }

        // online softmax (fp32, quad shuffles)
        float mx0 = -1e30f, mx1 = -1e30f;
#pragma unroll
        for (int ni = 0; ni < 8; ni++) {
            mx0 = fmaxf(mx0, fmaxf(sacc[ni][0], sacc[ni][1]));
            mx1 = fmaxf(mx1, fmaxf(sacc[ni][2], sacc[ni][3]));
        }
        mx0 = fmaxf(mx0, __shfl_xor_sync(0xffffffffu, mx0, 1));
        mx0 = fmaxf(mx0, __shfl_xor_sync(0xffffffffu, mx0, 2));
        mx1 = fmaxf(mx1, __shfl_xor_sync(0xffffffffu, mx1, 1));
        mx1 = fmaxf(mx1, __shfl_xor_sync(0xffffffffu, mx1, 2));
        float mn0 = fmaxf(m0, mx0), mn1 = fmaxf(m1, mx1);
        float fs0 = __expf(m0 - mn0), fs1 = __expf(m1 - mn1);

        float ps0 = 0.f, ps1 = 0.f;
#pragma unroll
        for (int ni = 0; ni < 8; ni++) {
            float p0 = (sacc[ni][0] > -1e29f) ? __expf(sacc[ni][0] - mn0) : 0.f;
            float p1 = (sacc[ni][1] > -1e29f) ? __expf(sacc[ni][1] - mn0) : 0.f;
            float p2 = (sacc[ni][2] > -1e29f) ? __expf(sacc[ni][2] - mn1) : 0.f;
            float p3 = (sacc[ni][3] > -1e29f) ? __expf(sacc[ni][3] - mn1) : 0.f;
            sacc[ni][0] = p0; sacc[ni][1] = p1; sacc[ni][2] = p2; sacc[ni][3] = p3;
            ps0 += p0 + p1; ps1 += p2 + p3;
        }
        ps0 += __shfl_xor_sync(0xffffffffu, ps0, 1);
        ps0 += __shfl_xor_sync(0xffffffffu, ps0, 2);
        ps1 += __shfl_xor_sync(0xffffffffu, ps1, 1);
        ps1 += __shfl_xor_sync(0xffffffffu, ps1, 2);
        l0 = l0 * fs0 + ps0; l1 = l1 * fs1 + ps1;
        m0 = mn0; m1 = mn1;

#pragma unroll
        for (int nd = 0; nd < 16; nd++) {
            oacc[nd][0] *= fs0; oacc[nd][1] *= fs0;
            oacc[nd][2] *= fs1; oacc[nd][3] *= fs1;
        }

        // O += P V : P fragments pack directly into A-fragments
#pragma unroll
        for (int s = 0; s < 4; s++) {
            uint32_t a0 = packh2(sacc[2 * s][0], sacc[2 * s][1]);
            uint32_t a1 = packh2(sacc[2 * s][2], sacc[2 * s][3]);
            uint32_t a2 = packh2(sacc[2 * s + 1][0], sacc[2 * s + 1][1]);
            uint32_t a3 = packh2(sacc[2 * s + 1][2], sacc[2 * s + 1][3]);
            int kk = s * 16;
#pragma unroll
            for (int t8 = 0; t8 < 8; t8++) {
                uint32_t vt[4];
                ldm_x4_t(vt, sV + (uint32_t)(((kk + lrV) * QSTR + t8 * 16 + lcV) * 2));
                mma_fp16(oacc[2 * t8], a0, a1, a2, a3, vt[0], vt[1]);
                mma_fp16(oacc[2 * t8 + 1], a0, a1, a2, a3, vt[2], vt[3]);
            }
        }
    }

    // epilogue: normalize -> fp16 output (natural layout)
    float li0 = 1.f / l0, li1 = 1.f / l1;
#pragma unroll
    for (int nd = 0; nd < 16; nd++) {
        int col = head * HD + nd * 8 + 2 * tg;
        *(uint32_t*)&Og[(size_t)row0 * HID + col] =
            packh2(oacc[nd][0] * li0, oacc[nd][1] * li0);
        *(uint32_t*)&Og[(size_t)row1 * HID + col] =
            packh2(oacc[nd][2] * li1, oacc[nd][3] * li1);
    }
}

// ---------------- launch ----------------
extern "C" void kernel_launch(void* const* d_in, const int* in_sizes, int n_in,
                              void* d_out, int out_size) {
    const float* hs   = (const float*)d_in[0];
    const float* wq   = (const float*)d_in[1];
    const float* wk   = (const float*)d_in[2];
    const float* wv   = (const float*)d_in[3];
    const float* wo   = (const float*)d_in[4];
    const float* scq  = (const float*)d_in[5];
    const float* sck  = (const float*)d_in[6];
    const float* scv  = (const float*)d_in[7];
    const float* sco  = (const float*)d_in[8];
    const float* pqkv = (const float*)d_in[9];
    const float* po   = (const float*)d_in[10];
    const float* cosT = (const float*)d_in[11];
    const float* sinT = (const float*)d_in[12];
    float* out = (float*)d_out;

    __half *wmq, *wmk, *wmv, *wmo, *hst, *ao;
    float *q, *k, *v;
    int *ipq, *ipo;
    cudaGetSymbolAddress((void**)&wmq, g_wmq);
    cudaGetSymbolAddress((void**)&wmk, g_wmk);
    cudaGetSymbolAddress((void**)&wmv, g_wmv);
    cudaGetSymbolAddress((void**)&wmo, g_wmo);
    cudaGetSymbolAddress((void**)&hst, g_hst);
    cudaGetSymbolAddress((void**)&q,   g_q);
    cudaGetSymbolAddress((void**)&k,   g_k);
    cudaGetSymbolAddress((void**)&v,   g_v);
    cudaGetSymbolAddress((void**)&ao,  g_ao);
    cudaGetSymbolAddress((void**)&ipq, g_invp_qkv);
    cudaGetSymbolAddress((void**)&ipo, g_invp_o);

    cudaFuncSetAttribute(gemm_fp16, cudaFuncAttributeMaxDynamicSharedMemorySize, GEMM_SMEM);
    cudaFuncSetAttribute(flash_fp16, cudaFuncAttributeMaxDynamicSharedMemorySize, FL3_SMEM);

    round_half<<<(SEQ * HID / 8 + 255) / 256, 256>>>(hs, hst, SEQ * HID / 8);           // 1
    perm_extract<<<(HID * HID + 255) / 256, 256>>>(pqkv, ipq, HID);                     // 2
    mask_weights<<<(HID * (HID / 4) + 255) / 256, 256>>>(wq, scq, ipq, wmq, HID, HID);  // 3
    gemm_fp16<<<dim3(HID / 128, SEQ / 128), 256, GEMM_SMEM>>>(hst, wmq, q, SEQ, HID, HID); // 4 (profiled)
    mask_weights<<<(KVD * (HID / 4) + 255) / 256, 256>>>(wk, sck, ipq, wmk, KVD, HID);
    gemm_fp16<<<dim3(KVD / 128, SEQ / 128), 256, GEMM_SMEM>>>(hst, wmk, k, SEQ, KVD, HID);
    mask_weights<<<(KVD * (HID / 4) + 255) / 256, 256>>>(wv, scv, ipq, wmv, KVD, HID);
    gemm_fp16<<<dim3(KVD / 128, SEQ / 128), 256, GEMM_SMEM>>>(hst, wmv, v, SEQ, KVD, HID);
    perm_extract<<<(HID * HID + 255) / 256, 256>>>(po, ipo, HID);
    mask_weights<<<(HID * (HID / 4) + 255) / 256, 256>>>(wo, sco, ipo, wmo, HID, HID);

    rope_kernel<<<(SEQ * NHEADS * 64 + 255) / 256, 256>>>(q, cosT, sinT, NHEADS);
    rope_kernel<<<(SEQ * NKVH * 64 + 255) / 256, 256>>>(k, cosT, sinT, NKVH);

    flash_fp16<<<dim3(SEQ / 128, NHEADS), 256, FL3_SMEM>>>(q, k, v, ao);

    gemm_fp16<<<dim3(HID / 128, SEQ / 128), 256, GEMM_SMEM>>>(ao, wmo, out, SEQ, HID, HID);
}

// round 8
// speedup vs baseline: 7.0577x; 1.3860x over previous
#include <cuda_runtime.h>
#include <cuda_fp16.h>
#include <cstdint>

#define HID 4096
#define KVD 1024
#define SEQ 2048
#define NHEADS 32
#define NKVH 8
#define HD 128

// ---------------- scratch ----------------
__device__ __half g_wmq[HID * HID];
__device__ __half g_wmo[HID * HID];
__device__ __half g_wmk[KVD * HID];
__device__ __half g_wmv[KVD * HID];
__device__ __half g_hst[SEQ * HID];
__device__ float  g_q[SEQ * HID];
__device__ float  g_k[SEQ * KVD];
__device__ float  g_v[SEQ * KVD];
__device__ __half g_ao[SEQ * HID];
__device__ int    g_invp_qkv[HID];
__device__ int    g_invp_o[HID];

__device__ __forceinline__ uint32_t smem_u32(const void* p) {
    return (uint32_t)__cvta_generic_to_shared((void*)p);
}
__device__ __forceinline__ uint32_t packh2(float x, float y) {
    __half2 h = __floats2half2_rn(x, y);
    return *(uint32_t*)&h;
}
__device__ __forceinline__ void ldm_x4(uint32_t (&r)[4], uint32_t addr) {
    asm volatile("ldmatrix.sync.aligned.m8n8.x4.shared.b16 {%0,%1,%2,%3}, [%4];"
                 : "=r"(r[0]), "=r"(r[1]), "=r"(r[2]), "=r"(r[3]) : "r"(addr));
}
__device__ __forceinline__ void ldm_x4_t(uint32_t (&r)[4], uint32_t addr) {
    asm volatile("ldmatrix.sync.aligned.m8n8.x4.trans.shared.b16 {%0,%1,%2,%3}, [%4];"
                 : "=r"(r[0]), "=r"(r[1]), "=r"(r[2]), "=r"(r[3]) : "r"(addr));
}
__device__ __forceinline__ void mma_fp16(float c[4], uint32_t a0, uint32_t a1,
                                         uint32_t a2, uint32_t a3,
                                         uint32_t b0, uint32_t b1) {
    asm volatile(
        "mma.sync.aligned.m16n8k16.row.col.f32.f16.f16.f32 "
        "{%0,%1,%2,%3}, {%4,%5,%6,%7}, {%8,%9}, {%0,%1,%2,%3};"
        : "+f"(c[0]), "+f"(c[1]), "+f"(c[2]), "+f"(c[3])
        : "r"(a0), "r"(a1), "r"(a2), "r"(a3), "r"(b0), "r"(b1));
}

// ---------------- permutation extraction ----------------
__global__ void perm_extract(const float* __restrict__ P, int* __restrict__ invp, int n) {
    int idx = blockIdx.x * blockDim.x + threadIdx.x;
    if (idx >= n * n) return;
    if (P[idx] > 0.5f) invp[idx % n] = idx / n;
}

// ---------------- hidden states: fp32 -> fp16 ----------------
__global__ void round_half(const float* __restrict__ X, __half* __restrict__ Y, int n8) {
    int i = blockIdx.x * blockDim.x + threadIdx.x;
    if (i >= n8) return;
    const float4* p = (const float4*)(X + (size_t)i * 8);
    float4 a = p[0], b = p[1];
    uint4 o;
    o.x = packh2(a.x, a.y); o.y = packh2(a.z, a.w);
    o.z = packh2(b.x, b.y); o.w = packh2(b.z, b.w);
    *(uint4*)(Y + (size_t)i * 8) = o;
}

// ---------------- 2:4 hard mask v2: block-per-row, smem staged ----------------
__global__ void __launch_bounds__(256) mask_weights_v2(const float* __restrict__ W,
                                                       const float* __restrict__ scaler,
                                                       const int* __restrict__ invp,
                                                       __half* __restrict__ Wm, int H) {
    extern __shared__ float smr[];            // [H] floats, then [H] halves
    __half* smo = (__half*)(smr + H);
    const int r = blockIdx.x;
    const float* Wr = W + (size_t)r * H;
    for (int i = threadIdx.x; i < H / 4; i += 256)
        ((float4*)smr)[i] = ((const float4*)Wr)[i];
    __syncthreads();
    const int G = H >> 2;
    for (int g = threadIdx.x; g < G; g += 256) {
        int4 c = ((const int4*)invp)[g];
        float w0 = smr[c.x], w1 = smr[c.y], w2 = smr[c.z], w3 = smr[c.w];
        float m0 = fabsf(w0) * sqrtf(__ldg(scaler + c.x));
        float m1 = fabsf(w1) * sqrtf(__ldg(scaler + c.y));
        float m2 = fabsf(w2) * sqrtf(__ldg(scaler + c.z));
        float m3 = fabsf(w3) * sqrtf(__ldg(scaler + c.w));
        int r0 = (m1 > m0) + (m2 > m0) + (m3 > m0);
        int r1 = (m0 >= m1) + (m2 > m1) + (m3 > m1);
        int r2 = (m0 >= m2) + (m1 >= m2) + (m3 > m2);
        int r3 = (m0 >= m3) + (m1 >= m3) + (m2 >= m3);
        smo[c.x] = __float2half_rn(r0 < 2 ? w0 : 0.f);
        smo[c.y] = __float2half_rn(r1 < 2 ? w1 : 0.f);
        smo[c.z] = __float2half_rn(r2 < 2 ? w2 : 0.f);
        smo[c.w] = __float2half_rn(r3 < 2 ? w3 : 0.f);
    }
    __syncthreads();
    __half* Wo = Wm + (size_t)r * H;
    for (int i = threadIdx.x; i < H / 8; i += 256)
        ((uint4*)Wo)[i] = ((const uint4*)smo)[i];
}

// ---------------- fp16 NT GEMM v3b: 3-slot / 2-ahead cp.async, BK=64 -----------
// Per-iteration order: wait_group 1 -> __syncthreads -> load t+2 -> commit ->
// compute t.  The barrier sits AFTER every thread's own wait (stage t fully
// resident for all threads) and BEFORE the slot (t-1)%3 overwrite (all threads
// done computing t-1).
#define GSH 72                       // smem row stride in halves (144B = 9x16B)
#define GEMM_SMEM_BM(BM) (3 * ((BM) + 128) * GSH * 2)

template <int BM, int NTHR>
__global__ void __launch_bounds__(NTHR, 2) gemm_v3(const __half* __restrict__ A,
                                                   const __half* __restrict__ B,
                                                   float* __restrict__ C,
                                                   int M, int N, int K) {
    extern __shared__ __half sh[];
    constexpr int STGH = (BM + 128) * GSH;         // halves per stage
    constexpr uint32_t STGB = STGH * 2;            // bytes per stage
    constexpr uint32_t ABYTES = BM * GSH * 2;      // B region offset within stage
    constexpr int AIT = BM * 8 / NTHR;             // A 16B-chunks per thread
    constexpr int BIT = 128 * 8 / NTHR;            // B 16B-chunks per thread

    const int tid = threadIdx.x, wid = tid >> 5, lane = tid & 31;
    const int g = lane >> 2, tg = lane & 3;
    const int wm = (wid >> 2) * 64, wn = (wid & 3) * 32;
    const int bm = blockIdx.y * BM, bn = blockIdx.x * 128;

    float acc[4][4][4] = {};
    uint32_t sA = smem_u32(sh);

    const uint32_t aoff = (uint32_t)((wm + (lane & 15)) * (GSH * 2) + (((lane >> 4) << 3) << 1));
    const uint32_t boff = ABYTES +
        (uint32_t)((wn + (lane & 7) + ((lane >> 4) << 3)) * (GSH * 2) +
                   ((((lane >> 3) & 1) << 3) << 1));

#define LOADSTAGE(slot, k0)                                                       \
    do {                                                                          \
        uint32_t so = sA + (uint32_t)(slot)*STGB;                                 \
        _Pragma("unroll")                                                         \
        for (int i = 0; i < AIT; i++) {                                           \
            int id = tid + i * NTHR;                                              \
            int row = id >> 3, ch = id & 7;                                       \
            const __half* pa = A + (size_t)(bm + row) * K + (k0) + ch * 8;        \
            asm volatile("cp.async.cg.shared.global [%0], [%1], 16;"              \
                         ::"r"(so + (uint32_t)((row * 9 + ch) * 16)), "l"(pa));   \
        }                                                                         \
        _Pragma("unroll")                                                         \
        for (int i = 0; i < BIT; i++) {                                           \
            int id = tid + i * NTHR;                                              \
            int row = id >> 3, ch = id & 7;                                       \
            const __half* pb = B + (size_t)(bn + row) * K + (k0) + ch * 8;        \
            asm volatile("cp.async.cg.shared.global [%0], [%1], 16;"              \
                         ::"r"(so + ABYTES + (uint32_t)((row * 9 + ch) * 16)),    \
                           "l"(pb));                                              \
        }                                                                         \
    } while (0)

    const int nk = K >> 6;            // BK = 64
    LOADSTAGE(0, 0);
    asm volatile("cp.async.commit_group;");
    LOADSTAGE(1, 64);
    asm volatile("cp.async.commit_group;");

    for (int t = 0; t < nk; t++) {
        asm volatile("cp.async.wait_group 1;");   // own g(t) complete
        __syncthreads();                          // => ALL threads' g(t) complete;
                                                  //    all done computing t-1
        if (t + 2 < nk) LOADSTAGE((t + 2) % 3, (t + 2) * 64);
        asm volatile("cp.async.commit_group;");

        uint32_t base = sA + (uint32_t)(t % 3) * STGB;
#pragma unroll
        for (int ks = 0; ks < 4; ks++) {
            uint32_t kadd = (uint32_t)(ks * 32);
            uint32_t bt[2][4];
            ldm_x4(bt[0], base + boff + kadd);
            ldm_x4(bt[1], base + boff + kadd + 16 * (GSH * 2));
#pragma unroll
            for (int mi = 0; mi < 4; mi++) {
                uint32_t af[4];
                ldm_x4(af, base + aoff + kadd + (uint32_t)(mi * 16 * (GSH * 2)));
#pragma unroll
                for (int nb = 0; nb < 2; nb++) {
                    mma_fp16(acc[mi][2 * nb], af[0], af[1], af[2], af[3],
                             bt[nb][0], bt[nb][1]);
                    mma_fp16(acc[mi][2 * nb + 1], af[0], af[1], af[2], af[3],
                             bt[nb][2], bt[nb][3]);
                }
            }
        }
    }

#pragma unroll
    for (int mi = 0; mi < 4; mi++)
#pragma unroll
        for (int ni = 0; ni < 4; ni++) {
            int row = bm + wm + mi * 16 + g;
            int col = bn + wn + ni * 8 + tg * 2;
            *(float2*)&C[(size_t)row * N + col] =
                make_float2(acc[mi][ni][0], acc[mi][ni][1]);
            *(float2*)&C[(size_t)(row + 8) * N + col] =
                make_float2(acc[mi][ni][2], acc[mi][ni][3]);
        }
#undef LOADSTAGE
}

// ---------------- RoPE (in place, paired halves, fp32) ----------------
__global__ void rope_kernel(float* __restrict__ X, const float* __restrict__ cosT,
                            const float* __restrict__ sinT, int nheads) {
    int idx = blockIdx.x * blockDim.x + threadIdx.x;
    int total = SEQ * nheads * 64;
    if (idx >= total) return;
    int d = idx & 63;
    int h = (idx >> 6) % nheads;
    int s = idx / (64 * nheads);
    float* p = X + (size_t)s * nheads * HD + h * HD + d;
    float x1 = p[0], x2 = p[64];
    float c1 = cosT[s * HD + d],      s1 = sinT[s * HD + d];
    float c2 = cosT[s * HD + 64 + d], s2 = sinT[s * HD + 64 + d];
    p[0]  = fmaf(x1, c1, -x2 * s1);
    p[64] = fmaf(x2, c2,  x1 * s2);
}

// ---------------- fp16 tensor-core causal flash attention ----------------
#define QSTR 136
#define FL3_SMEM ((128 + 64 + 64) * QSTR * 2)

__global__ void __launch_bounds__(256) flash_fp16(const float* __restrict__ Qg,
                                                  const float* __restrict__ Kg,
                                                  const float* __restrict__ Vg,
                                                  __half* __restrict__ Og) {
    extern __shared__ __half sm[];
    __half* Qs = sm;
    __half* Ks = Qs + 128 * QSTR;
    __half* Vs = Ks + 64 * QSTR;

    const int tid = threadIdx.x, wid = tid >> 5, lane = tid & 31;
    const int g = lane >> 2, tg = lane & 3;
    const int qb = gridDim.x - 1 - blockIdx.x;   // heavy CTAs first
    const int head = blockIdx.y, kvh = head >> 2;
    const float* Qh = Qg + head * HD;
    const float* Kh = Kg + kvh * HD;
    const float* Vh = Vg + kvh * HD;

    uint32_t sQ = smem_u32(Qs), sK = smem_u32(Ks), sV = smem_u32(Vs);

#pragma unroll
    for (int i = 0; i < 16; i++) {
        int lin = tid + i * 256;
        int r = lin >> 5, c4 = lin & 31;
        float4 v = *(const float4*)&Qh[(size_t)(qb * 128 + r) * HID + c4 * 4];
        uint2 o; o.x = packh2(v.x, v.y); o.y = packh2(v.z, v.w);
        *(uint2*)&Qs[r * QSTR + c4 * 4] = o;
    }

    const int wm = wid * 16;
    const int row0 = qb * 128 + wm + g, row1 = row0 + 8;
    const int rowTop = qb * 128 + wm + 15;
    float m0 = -1e30f, m1 = -1e30f, l0 = 0.f, l1 = 0.f;
    float oacc[16][4];
#pragma unroll
    for (int i = 0; i < 16; i++)
#pragma unroll
        for (int j = 0; j < 4; j++) oacc[i][j] = 0.f;

    const float scale = 0.08838834764831845f;
    const int nkb = 2 * qb + 2;

    const int lrA = wm + (lane & 15), lcA = (lane >> 4) << 3;
    const int lrK = (lane & 7) + ((lane >> 4) << 3), lcK = ((lane >> 3) & 1) << 3;
    const int lrV = (lane & 7) + (((lane >> 3) & 1) << 3), lcV = (lane >> 4) << 3;

    for (int kb = 0; kb < nkb; kb++) {
        __syncthreads();
#pragma unroll
        for (int i = 0; i < 8; i++) {
            int lin = tid + i * 256;
            int r = lin >> 5, c4 = lin & 31;
            float4 kv = *(const float4*)&Kh[(size_t)(kb * 64 + r) * KVD + c4 * 4];
            uint2 ok; ok.x = packh2(kv.x, kv.y); ok.y = packh2(kv.z, kv.w);
            *(uint2*)&Ks[r * QSTR + c4 * 4] = ok;
            float4 vv = *(const float4*)&Vh[(size_t)(kb * 64 + r) * KVD + c4 * 4];
            uint2 ov; ov.x = packh2(vv.x, vv.y); ov.y = packh2(vv.z, vv.w);
            *(uint2*)&Vs[r * QSTR + c4 * 4] = ov;
        }
        __syncthreads();
        if (kb * 64 > rowTop) continue;

        float sacc[8][4];
#pragma unroll
        for (int ni = 0; ni < 8; ni++)
#pragma unroll
            for (int j = 0; j < 4; j++) sacc[ni][j] = 0.f;
#pragma unroll
        for (int ks = 0; ks < 8; ks++) {
            int kk = ks * 16;
            uint32_t af[4];
            ldm_x4(af, sQ + (uint32_t)((lrA * QSTR + kk + lcA) * 2));
#pragma unroll
            for (int nb = 0; nb < 4; nb++) {
                uint32_t bt[4];
                ldm_x4(bt, sK + (uint32_t)(((nb * 16 + lrK) * QSTR + kk + lcK) * 2));
                mma_fp16(sacc[2 * nb], af[0], af[1], af[2], af[3], bt[0], bt[1]);
                mma_fp16(sacc[2 * nb + 1], af[0], af[1], af[2], af[3], bt[2], bt[3]);
            }
        }

#pragma unroll
        for (int ni = 0; ni < 8; ni++) {
            int c0 = kb * 64 + ni * 8 + 2 * tg, c1 = c0 + 1;
            sacc[ni][0] = (c0 <= row0) ? sacc[ni][0] * scale : -1e30f;
            sacc[ni][1] = (c1 <= row0) ? sacc[ni][1] * scale : -1e30f;
            sacc[ni][2] = (c0 <= row1) ? sacc[ni][2] * scale : -1e30f;
            sacc[ni][3] = (c1 <= row1) ? sacc[ni][3] * scale : -1e30f;
        }

        float mx0 = -1e30f, mx1 = -1e30f;
#pragma unroll
        for (int ni = 0; ni < 8; ni++) {
            mx0 = fmaxf(mx0, fmaxf(sacc[ni][0], sacc[ni][1]));
            mx1 = fmaxf(mx1, fmaxf(sacc[ni][2], sacc[ni][3]));
        }
        mx0 = fmaxf(mx0, __shfl_xor_sync(0xffffffffu, mx0, 1));
        mx0 = fmaxf(mx0, __shfl_xor_sync(0xffffffffu, mx0, 2));
        mx1 = fmaxf(mx1, __shfl_xor_sync(0xffffffffu, mx1, 1));
        mx1 = fmaxf(mx1, __shfl_xor_sync(0xffffffffu, mx1, 2));
        float mn0 = fmaxf(m0, mx0), mn1 = fmaxf(m1, mx1);
        float fs0 = __expf(m0 - mn0), fs1 = __expf(m1 - mn1);

        float ps0 = 0.f, ps1 = 0.f;
#pragma unroll
        for (int ni = 0; ni < 8; ni++) {
            float p0 = (sacc[ni][0] > -1e29f) ? __expf(sacc[ni][0] - mn0) : 0.f;
            float p1 = (sacc[ni][1] > -1e29f) ? __expf(sacc[ni][1] - mn0) : 0.f;
            float p2 = (sacc[ni][2] > -1e29f) ? __expf(sacc[ni][2] - mn1) : 0.f;
            float p3 = (sacc[ni][3] > -1e29f) ? __expf(sacc[ni][3] - mn1) : 0.f;
            sacc[ni][0] = p0; sacc[ni][1] = p1; sacc[ni][2] = p2; sacc[ni][3] = p3;
            ps0 += p0 + p1; ps1 += p2 + p3;
        }
        ps0 += __shfl_xor_sync(0xffffffffu, ps0, 1);
        ps0 += __shfl_xor_sync(0xffffffffu, ps0, 2);
        ps1 += __shfl_xor_sync(0xffffffffu, ps1, 1);
        ps1 += __shfl_xor_sync(0xffffffffu, ps1, 2);
        l0 = l0 * fs0 + ps0; l1 = l1 * fs1 + ps1;
        m0 = mn0; m1 = mn1;

#pragma unroll
        for (int nd = 0; nd < 16; nd++) {
            oacc[nd][0] *= fs0; oacc[nd][1] *= fs0;
            oacc[nd][2] *= fs1; oacc[nd][3] *= fs1;
        }

#pragma unroll
        for (int s = 0; s < 4; s++) {
            uint32_t a0 = packh2(sacc[2 * s][0], sacc[2 * s][1]);
            uint32_t a1 = packh2(sacc[2 * s][2], sacc[2 * s][3]);
            uint32_t a2 = packh2(sacc[2 * s + 1][0], sacc[2 * s + 1][1]);
            uint32_t a3 = packh2(sacc[2 * s + 1][2], sacc[2 * s + 1][3]);
            int kk = s * 16;
#pragma unroll
            for (int t8 = 0; t8 < 8; t8++) {
                uint32_t vt[4];
                ldm_x4_t(vt, sV + (uint32_t)(((kk + lrV) * QSTR + t8 * 16 + lcV) * 2));
                mma_fp16(oacc[2 * t8], a0, a1, a2, a3, vt[0], vt[1]);
                mma_fp16(oacc[2 * t8 + 1], a0, a1, a2, a3, vt[2], vt[3]);
            }
        }
    }

    float li0 = 1.f / l0, li1 = 1.f / l1;
#pragma unroll
    for (int nd = 0; nd < 16; nd++) {
        int col = head * HD + nd * 8 + 2 * tg;
        *(uint32_t*)&Og[(size_t)row0 * HID + col] =
            packh2(oacc[nd][0] * li0, oacc[nd][1] * li0);
        *(uint32_t*)&Og[(size_t)row1 * HID + col] =
            packh2(oacc[nd][2] * li1, oacc[nd][3] * li1);
    }
}

// ---------------- launch ----------------
extern "C" void kernel_launch(void* const* d_in, const int* in_sizes, int n_in,
                              void* d_out, int out_size) {
    const float* hs   = (const float*)d_in[0];
    const float* wq   = (const float*)d_in[1];
    const float* wk   = (const float*)d_in[2];
    const float* wv   = (const float*)d_in[3];
    const float* wo   = (const float*)d_in[4];
    const float* scq  = (const float*)d_in[5];
    const float* sck  = (const float*)d_in[6];
    const float* scv  = (const float*)d_in[7];
    const float* sco  = (const float*)d_in[8];
    const float* pqkv = (const float*)d_in[9];
    const float* po   = (const float*)d_in[10];
    const float* cosT = (const float*)d_in[11];
    const float* sinT = (const float*)d_in[12];
    float* out = (float*)d_out;

    __half *wmq, *wmk, *wmv, *wmo, *hst, *ao;
    float *q, *k, *v;
    int *ipq, *ipo;
    cudaGetSymbolAddress((void**)&wmq, g_wmq);
    cudaGetSymbolAddress((void**)&wmk, g_wmk);
    cudaGetSymbolAddress((void**)&wmv, g_wmv);
    cudaGetSymbolAddress((void**)&wmo, g_wmo);
    cudaGetSymbolAddress((void**)&hst, g_hst);
    cudaGetSymbolAddress((void**)&q,   g_q);
    cudaGetSymbolAddress((void**)&k,   g_k);
    cudaGetSymbolAddress((void**)&v,   g_v);
    cudaGetSymbolAddress((void**)&ao,  g_ao);
    cudaGetSymbolAddress((void**)&ipq, g_invp_qkv);
    cudaGetSymbolAddress((void**)&ipo, g_invp_o);

    const int smem128 = GEMM_SMEM_BM(128);
    const int smem64  = GEMM_SMEM_BM(64);
    cudaFuncSetAttribute(gemm_v3<128, 256>,
                         cudaFuncAttributeMaxDynamicSharedMemorySize, smem128);
    cudaFuncSetAttribute(gemm_v3<64, 128>,
                         cudaFuncAttributeMaxDynamicSharedMemorySize, smem64);
    cudaFuncSetAttribute(flash_fp16, cudaFuncAttributeMaxDynamicSharedMemorySize, FL3_SMEM);

    const int mw_smem = HID * 6;      // H floats + H halves

    round_half<<<(SEQ * HID / 8 + 255) / 256, 256>>>(hs, hst, SEQ * HID / 8);        // 1
    perm_extract<<<(HID * HID + 255) / 256, 256>>>(pqkv, ipq, HID);                  // 2
    mask_weights_v2<<<HID, 256, mw_smem>>>(wq, scq, ipq, wmq, HID);                  // 3
    gemm_v3<128, 256><<<dim3(HID / 128, SEQ / 128), 256, smem128>>>(hst, wmq, q,     // 4 (profiled)
                                                                    SEQ, HID, HID);
    mask_weights_v2<<<KVD, 256, mw_smem>>>(wk, sck, ipq, wmk, HID);
    gemm_v3<64, 128><<<dim3(KVD / 128, SEQ / 64), 128, smem64>>>(hst, wmk, k,
                                                                 SEQ, KVD, HID);
    mask_weights_v2<<<KVD, 256, mw_smem>>>(wv, scv, ipq, wmv, HID);
    gemm_v3<64, 128><<<dim3(KVD / 128, SEQ / 64), 128, smem64>>>(hst, wmv, v,
                                                                 SEQ, KVD, HID);
    perm_extract<<<(HID * HID + 255) / 256, 256>>>(po, ipo, HID);
    mask_weights_v2<<<HID, 256, mw_smem>>>(wo, sco, ipo, wmo, HID);

    rope_kernel<<<(SEQ * NHEADS * 64 + 255) / 256, 256>>>(q, cosT, sinT, NHEADS);
    rope_kernel<<<(SEQ * NKVH * 64 + 255) / 256, 256>>>(k, cosT, sinT, NKVH);

    flash_fp16<<<dim3(SEQ / 128, NHEADS), 256, FL3_SMEM>>>(q, k, v, ao);

    gemm_v3<128, 256><<<dim3(HID / 128, SEQ / 128), 256, smem128>>>(ao, wmo, out,
                                                                    SEQ, HID, HID);
}

// round 9
// speedup vs baseline: 7.6522x; 1.0842x over previous
#include <cuda_runtime.h>
#include <cuda_fp16.h>
#include <cstdint>

#define HID 4096
#define KVD 1024
#define SEQ 2048
#define NHEADS 32
#define NKVH 8
#define HD 128

// ---------------- scratch ----------------
__device__ __half g_wmq[HID * HID];
__device__ __half g_wmo[HID * HID];
__device__ __half g_wmk[KVD * HID];
__device__ __half g_wmv[KVD * HID];
__device__ __half g_hst[SEQ * HID];
__device__ float  g_q[SEQ * HID];
__device__ float  g_k[SEQ * KVD];
__device__ float  g_v[SEQ * KVD];
__device__ __half g_ao[SEQ * HID];
__device__ int    g_invp_qkv[HID];
__device__ int    g_invp_o[HID];

__device__ __forceinline__ uint32_t smem_u32(const void* p) {
    return (uint32_t)__cvta_generic_to_shared((void*)p);
}
__device__ __forceinline__ uint32_t packh2(float x, float y) {
    __half2 h = __floats2half2_rn(x, y);
    return *(uint32_t*)&h;
}
__device__ __forceinline__ void ldm_x4(uint32_t (&r)[4], uint32_t addr) {
    asm volatile("ldmatrix.sync.aligned.m8n8.x4.shared.b16 {%0,%1,%2,%3}, [%4];"
                 : "=r"(r[0]), "=r"(r[1]), "=r"(r[2]), "=r"(r[3]) : "r"(addr));
}
__device__ __forceinline__ void ldm_x4_t(uint32_t (&r)[4], uint32_t addr) {
    asm volatile("ldmatrix.sync.aligned.m8n8.x4.trans.shared.b16 {%0,%1,%2,%3}, [%4];"
                 : "=r"(r[0]), "=r"(r[1]), "=r"(r[2]), "=r"(r[3]) : "r"(addr));
}
__device__ __forceinline__ void mma_fp16(float c[4], uint32_t a0, uint32_t a1,
                                         uint32_t a2, uint32_t a3,
                                         uint32_t b0, uint32_t b1) {
    asm volatile(
        "mma.sync.aligned.m16n8k16.row.col.f32.f16.f16.f32 "
        "{%0,%1,%2,%3}, {%4,%5,%6,%7}, {%8,%9}, {%0,%1,%2,%3};"
        : "+f"(c[0]), "+f"(c[1]), "+f"(c[2]), "+f"(c[3])
        : "r"(a0), "r"(a1), "r"(a2), "r"(a3), "r"(b0), "r"(b1));
}

// ---------------- permutation extraction ----------------
__global__ void perm_extract(const float* __restrict__ P, int* __restrict__ invp, int n) {
    int idx = blockIdx.x * blockDim.x + threadIdx.x;
    if (idx >= n * n) return;
    if (P[idx] > 0.5f) invp[idx % n] = idx / n;
}

// ---------------- hidden states: fp32 -> fp16 ----------------
__global__ void round_half(const float* __restrict__ X, __half* __restrict__ Y, int n8) {
    int i = blockIdx.x * blockDim.x + threadIdx.x;
    if (i >= n8) return;
    const float4* p = (const float4*)(X + (size_t)i * 8);
    float4 a = p[0], b = p[1];
    uint4 o;
    o.x = packh2(a.x, a.y); o.y = packh2(a.z, a.w);
    o.z = packh2(b.x, b.y); o.w = packh2(b.z, b.w);
    *(uint4*)(Y + (size_t)i * 8) = o;
}

// ---------------- 2:4 hard mask v2: block-per-row, smem staged ----------------
__global__ void __launch_bounds__(256) mask_weights_v2(const float* __restrict__ W,
                                                       const float* __restrict__ scaler,
                                                       const int* __restrict__ invp,
                                                       __half* __restrict__ Wm, int H) {
    extern __shared__ float smr[];            // [H] floats, then [H] halves
    __half* smo = (__half*)(smr + H);
    const int r = blockIdx.x;
    const float* Wr = W + (size_t)r * H;
    for (int i = threadIdx.x; i < H / 4; i += 256)
        ((float4*)smr)[i] = ((const float4*)Wr)[i];
    __syncthreads();
    const int G = H >> 2;
    for (int g = threadIdx.x; g < G; g += 256) {
        int4 c = ((const int4*)invp)[g];
        float w0 = smr[c.x], w1 = smr[c.y], w2 = smr[c.z], w3 = smr[c.w];
        float m0 = fabsf(w0) * sqrtf(__ldg(scaler + c.x));
        float m1 = fabsf(w1) * sqrtf(__ldg(scaler + c.y));
        float m2 = fabsf(w2) * sqrtf(__ldg(scaler + c.z));
        float m3 = fabsf(w3) * sqrtf(__ldg(scaler + c.w));
        int r0 = (m1 > m0) + (m2 > m0) + (m3 > m0);
        int r1 = (m0 >= m1) + (m2 > m1) + (m3 > m1);
        int r2 = (m0 >= m2) + (m1 >= m2) + (m3 > m2);
        int r3 = (m0 >= m3) + (m1 >= m3) + (m2 >= m3);
        smo[c.x] = __float2half_rn(r0 < 2 ? w0 : 0.f);
        smo[c.y] = __float2half_rn(r1 < 2 ? w1 : 0.f);
        smo[c.z] = __float2half_rn(r2 < 2 ? w2 : 0.f);
        smo[c.w] = __float2half_rn(r3 < 2 ? w3 : 0.f);
    }
    __syncthreads();
    __half* Wo = Wm + (size_t)r * H;
    for (int i = threadIdx.x; i < H / 8; i += 256)
        ((uint4*)Wo)[i] = ((const uint4*)smo)[i];
}

// ---------------- fp16 NT GEMM v3: 3-slot/2-ahead, BK=64 (used for K/V) -------
#define GSH 72
#define GEMM_SMEM_BM(BM) (3 * ((BM) + 128) * GSH * 2)

template <int BM, int NTHR>
__global__ void __launch_bounds__(NTHR, 2) gemm_v3(const __half* __restrict__ A,
                                                   const __half* __restrict__ B,
                                                   float* __restrict__ C,
                                                   int M, int N, int K) {
    extern __shared__ __half sh[];
    constexpr int STGH = (BM + 128) * GSH;
    constexpr uint32_t STGB = STGH * 2;
    constexpr uint32_t ABYTES = BM * GSH * 2;
    constexpr int AIT = BM * 8 / NTHR;
    constexpr int BIT = 128 * 8 / NTHR;

    const int tid = threadIdx.x, wid = tid >> 5, lane = tid & 31;
    const int g = lane >> 2, tg = lane & 3;
    const int wm = (wid >> 2) * 64, wn = (wid & 3) * 32;
    const int bm = blockIdx.y * BM, bn = blockIdx.x * 128;

    float acc[4][4][4] = {};
    uint32_t sA = smem_u32(sh);

    const uint32_t aoff = (uint32_t)((wm + (lane & 15)) * (GSH * 2) + (((lane >> 4) << 3) << 1));
    const uint32_t boff = ABYTES +
        (uint32_t)((wn + (lane & 7) + ((lane >> 4) << 3)) * (GSH * 2) +
                   ((((lane >> 3) & 1) << 3) << 1));

#define LOADSTAGE(slot, k0)                                                       \
    do {                                                                          \
        uint32_t so = sA + (uint32_t)(slot)*STGB;                                 \
        _Pragma("unroll")                                                         \
        for (int i = 0; i < AIT; i++) {                                           \
            int id = tid + i * NTHR;                                              \
            int row = id >> 3, ch = id & 7;                                       \
            const __half* pa = A + (size_t)(bm + row) * K + (k0) + ch * 8;        \
            asm volatile("cp.async.cg.shared.global [%0], [%1], 16;"              \
                         ::"r"(so + (uint32_t)((row * 9 + ch) * 16)), "l"(pa));   \
        }                                                                         \
        _Pragma("unroll")                                                         \
        for (int i = 0; i < BIT; i++) {                                           \
            int id = tid + i * NTHR;                                              \
            int row = id >> 3, ch = id & 7;                                       \
            const __half* pb = B + (size_t)(bn + row) * K + (k0) + ch * 8;        \
            asm volatile("cp.async.cg.shared.global [%0], [%1], 16;"              \
                         ::"r"(so + ABYTES + (uint32_t)((row * 9 + ch) * 16)),    \
                           "l"(pb));                                              \
        }                                                                         \
    } while (0)

    const int nk = K >> 6;
    LOADSTAGE(0, 0);
    asm volatile("cp.async.commit_group;");
    LOADSTAGE(1, 64);
    asm volatile("cp.async.commit_group;");

    for (int t = 0; t < nk; t++) {
        asm volatile("cp.async.wait_group 1;");
        __syncthreads();
        if (t + 2 < nk) LOADSTAGE((t + 2) % 3, (t + 2) * 64);
        asm volatile("cp.async.commit_group;");

        uint32_t base = sA + (uint32_t)(t % 3) * STGB;
#pragma unroll
        for (int ks = 0; ks < 4; ks++) {
            uint32_t kadd = (uint32_t)(ks * 32);
            uint32_t bt[2][4];
            ldm_x4(bt[0], base + boff + kadd);
            ldm_x4(bt[1], base + boff + kadd + 16 * (GSH * 2));
#pragma unroll
            for (int mi = 0; mi < 4; mi++) {
                uint32_t af[4];
                ldm_x4(af, base + aoff + kadd + (uint32_t)(mi * 16 * (GSH * 2)));
#pragma unroll
                for (int nb = 0; nb < 2; nb++) {
                    mma_fp16(acc[mi][2 * nb], af[0], af[1], af[2], af[3],
                             bt[nb][0], bt[nb][1]);
                    mma_fp16(acc[mi][2 * nb + 1], af[0], af[1], af[2], af[3],
                             bt[nb][2], bt[nb][3]);
                }
            }
        }
    }

#pragma unroll
    for (int mi = 0; mi < 4; mi++)
#pragma unroll
        for (int ni = 0; ni < 4; ni++) {
            int row = bm + wm + mi * 16 + g;
            int col = bn + wn + ni * 8 + tg * 2;
            *(float2*)&C[(size_t)row * N + col] =
                make_float2(acc[mi][ni][0], acc[mi][ni][1]);
            *(float2*)&C[(size_t)(row + 8) * N + col] =
                make_float2(acc[mi][ni][2], acc[mi][ni][3]);
        }
#undef LOADSTAGE
}

// ---------------- fp16 NT GEMM v4: 128x128 CTA, 4 warps, 64x64 warptile -------
// XOR-swizzled smem (no padding): stage = 256 rows x 128B,
// off(row, chunk) = row*128 + ((chunk ^ (row & 7)) * 16).  3 stages = 96 KB
// -> 2 CTAs/SM.  Per k16-step: 8 ldmatrix feed 32 independent mmas.
#define V4_STGB 32768u
#define V4_SMEM (3 * 32768)

__global__ void __launch_bounds__(128, 2) gemm_v4(const __half* __restrict__ A,
                                                  const __half* __restrict__ B,
                                                  float* __restrict__ C,
                                                  int M, int N, int K) {
    extern __shared__ __half sh[];
    const int tid = threadIdx.x, wid = tid >> 5, lane = tid & 31;
    const int g = lane >> 2, tg = lane & 3;
    const int wm = (wid >> 1) * 64, wn = (wid & 1) * 64;
    const int bm = blockIdx.y * 128, bn = blockIdx.x * 128;

    float acc[4][8][4] = {};
    uint32_t sA = smem_u32(sh);

    // ldmatrix lane pieces
    const int arow = lane & 15;               // A row within m16 tile
    const int apar = lane >> 4;               // A chunk parity
    const int brow = (lane & 7) + ((lane >> 4) << 3);   // B row within n16 tile
    const int bpar = (lane >> 3) & 1;         // B chunk parity

#define V4LOAD(slot, k0)                                                          \
    do {                                                                          \
        uint32_t so = sA + (uint32_t)(slot)*V4_STGB;                              \
        _Pragma("unroll")                                                         \
        for (int i = 0; i < 16; i++) {                                            \
            int id = tid + i * 128;                                               \
            int row = id >> 3, ch = id & 7;                                       \
            const __half* gp = (row < 128)                                        \
                ? A + (size_t)(bm + row) * K + (k0) + ch * 8                      \
                : B + (size_t)(bn + row - 128) * K + (k0) + ch * 8;               \
            asm volatile("cp.async.cg.shared.global [%0], [%1], 16;"              \
                         ::"r"(so + (uint32_t)(row * 128 +                        \
                                               ((ch ^ (row & 7)) * 16))),         \
                           "l"(gp));                                              \
        }                                                                         \
    } while (0)

    const int nk = K >> 6;
    V4LOAD(0, 0);
    asm volatile("cp.async.commit_group;");
    V4LOAD(1, 64);
    asm volatile("cp.async.commit_group;");

    for (int t = 0; t < nk; t++) {
        asm volatile("cp.async.wait_group 1;");
        __syncthreads();
        if (t + 2 < nk) V4LOAD((t + 2) % 3, (t + 2) * 64);
        asm volatile("cp.async.commit_group;");

        uint32_t base = sA + (uint32_t)(t % 3) * V4_STGB;
#pragma unroll
        for (int ks = 0; ks < 4; ks++) {
            uint32_t af[4][4], bt[4][4];
#pragma unroll
            for (int mi = 0; mi < 4; mi++) {
                int row = wm + mi * 16 + arow;
                int ch = 2 * ks + apar;
                ldm_x4(af[mi], base + (uint32_t)(row * 128 + ((ch ^ (row & 7)) * 16)));
            }
#pragma unroll
            for (int nb = 0; nb < 4; nb++) {
                int row = 128 + wn + nb * 16 + brow;
                int ch = 2 * ks + bpar;
                ldm_x4(bt[nb], base + (uint32_t)(row * 128 + ((ch ^ (row & 7)) * 16)));
            }
#pragma unroll
            for (int mi = 0; mi < 4; mi++)
#pragma unroll
                for (int nb = 0; nb < 4; nb++) {
                    mma_fp16(acc[mi][2 * nb], af[mi][0], af[mi][1], af[mi][2],
                             af[mi][3], bt[nb][0], bt[nb][1]);
                    mma_fp16(acc[mi][2 * nb + 1], af[mi][0], af[mi][1], af[mi][2],
                             af[mi][3], bt[nb][2], bt[nb][3]);
                }
        }
    }

#pragma unroll
    for (int mi = 0; mi < 4; mi++)
#pragma unroll
        for (int ni = 0; ni < 8; ni++) {
            int row = bm + wm + mi * 16 + g;
            int col = bn + wn + ni * 8 + tg * 2;
            *(float2*)&C[(size_t)row * N + col] =
                make_float2(acc[mi][ni][0], acc[mi][ni][1]);
            *(float2*)&C[(size_t)(row + 8) * N + col] =
                make_float2(acc[mi][ni][2], acc[mi][ni][3]);
        }
#undef V4LOAD
}

// ---------------- RoPE (in place, paired halves, fp32) ----------------
__global__ void rope_kernel(float* __restrict__ X, const float* __restrict__ cosT,
                            const float* __restrict__ sinT, int nheads) {
    int idx = blockIdx.x * blockDim.x + threadIdx.x;
    int total = SEQ * nheads * 64;
    if (idx >= total) return;
    int d = idx & 63;
    int h = (idx >> 6) % nheads;
    int s = idx / (64 * nheads);
    float* p = X + (size_t)s * nheads * HD + h * HD + d;
    float x1 = p[0], x2 = p[64];
    float c1 = cosT[s * HD + d],      s1 = sinT[s * HD + d];
    float c2 = cosT[s * HD + 64 + d], s2 = sinT[s * HD + 64 + d];
    p[0]  = fmaf(x1, c1, -x2 * s1);
    p[64] = fmaf(x2, c2,  x1 * s2);
}

// ---------------- fp16 tensor-core causal flash attention ----------------
#define QSTR 136
#define FL3_SMEM ((128 + 64 + 64) * QSTR * 2)

__global__ void __launch_bounds__(256) flash_fp16(const float* __restrict__ Qg,
                                                  const float* __restrict__ Kg,
                                                  const float* __restrict__ Vg,
                                                  __half* __restrict__ Og) {
    extern __shared__ __half sm[];
    __half* Qs = sm;
    __half* Ks = Qs + 128 * QSTR;
    __half* Vs = Ks + 64 * QSTR;

    const int tid = threadIdx.x, wid = tid >> 5, lane = tid & 31;
    const int g = lane >> 2, tg = lane & 3;
    const int qb = gridDim.x - 1 - blockIdx.x;   // heavy CTAs first
    const int head = blockIdx.y, kvh = head >> 2;
    const float* Qh = Qg + head * HD;
    const float* Kh = Kg + kvh * HD;
    const float* Vh = Vg + kvh * HD;

    uint32_t sQ = smem_u32(Qs), sK = smem_u32(Ks), sV = smem_u32(Vs);

#pragma unroll
    for (int i = 0; i < 16; i++) {
        int lin = tid + i * 256;
        int r = lin >> 5, c4 = lin & 31;
        float4 v = *(const float4*)&Qh[(size_t)(qb * 128 + r) * HID + c4 * 4];
        uint2 o; o.x = packh2(v.x, v.y); o.y = packh2(v.z, v.w);
        *(uint2*)&Qs[r * QSTR + c4 * 4] = o;
    }

    const int wm = wid * 16;
    const int row0 = qb * 128 + wm + g, row1 = row0 + 8;
    const int rowTop = qb * 128 + wm + 15;
    float m0 = -1e30f, m1 = -1e30f, l0 = 0.f, l1 = 0.f;
    float oacc[16][4];
#pragma unroll
    for (int i = 0; i < 16; i++)
#pragma unroll
        for (int j = 0; j < 4; j++) oacc[i][j] = 0.f;

    const float scale = 0.08838834764831845f;
    const int nkb = 2 * qb + 2;

    const int lrA = wm + (lane & 15), lcA = (lane >> 4) << 3;
    const int lrK = (lane & 7) + ((lane >> 4) << 3), lcK = ((lane >> 3) & 1) << 3;
    const int lrV = (lane & 7) + (((lane >> 3) & 1) << 3), lcV = (lane >> 4) << 3;

    for (int kb = 0; kb < nkb; kb++) {
        __syncthreads();
#pragma unroll
        for (int i = 0; i < 8; i++) {
            int lin = tid + i * 256;
            int r = lin >> 5, c4 = lin & 31;
            float4 kv = *(const float4*)&Kh[(size_t)(kb * 64 + r) * KVD + c4 * 4];
            uint2 ok; ok.x = packh2(kv.x, kv.y); ok.y = packh2(kv.z, kv.w);
            *(uint2*)&Ks[r * QSTR + c4 * 4] = ok;
            float4 vv = *(const float4*)&Vh[(size_t)(kb * 64 + r) * KVD + c4 * 4];
            uint2 ov; ov.x = packh2(vv.x, vv.y); ov.y = packh2(vv.z, vv.w);
            *(uint2*)&Vs[r * QSTR + c4 * 4] = ov;
        }
        __syncthreads();
        if (kb * 64 > rowTop) continue;

        float sacc[8][4];
#pragma unroll
        for (int ni = 0; ni < 8; ni++)
#pragma unroll
            for (int j = 0; j < 4; j++) sacc[ni][j] = 0.f;
#pragma unroll
        for (int ks = 0; ks < 8; ks++) {
            int kk = ks * 16;
            uint32_t af[4];
            ldm_x4(af, sQ + (uint32_t)((lrA * QSTR + kk + lcA) * 2));
#pragma unroll
            for (int nb = 0; nb < 4; nb++) {
                uint32_t bt[4];
                ldm_x4(bt, sK + (uint32_t)(((nb * 16 + lrK) * QSTR + kk + lcK) * 2));
                mma_fp16(sacc[2 * nb], af[0], af[1], af[2], af[3], bt[0], bt[1]);
                mma_fp16(sacc[2 * nb + 1], af[0], af[1], af[2], af[3], bt[2], bt[3]);
            }
        }

#pragma unroll
        for (int ni = 0; ni < 8; ni++) {
            int c0 = kb * 64 + ni * 8 + 2 * tg, c1 = c0 + 1;
            sacc[ni][0] = (c0 <= row0) ? sacc[ni][0] * scale : -1e30f;
            sacc[ni][1] = (c1 <= row0) ? sacc[ni][1] * scale : -1e30f;
            sacc[ni][2] = (c0 <= row1) ? sacc[ni][2] * scale : -1e30f;
            sacc[ni][3] = (c1 <= row1) ? sacc[ni][3] * scale : -1e30f;
        }

        float mx0 = -1e30f, mx1 = -1e30f;
#pragma unroll
        for (int ni = 0; ni < 8; ni++) {
            mx0 = fmaxf(mx0, fmaxf(sacc[ni][0], sacc[ni][1]));
            mx1 = fmaxf(mx1, fmaxf(sacc[ni][2], sacc[ni][3]));
        }
        mx0 = fmaxf(mx0, __shfl_xor_sync(0xffffffffu, mx0, 1));
        mx0 = fmaxf(mx0, __shfl_xor_sync(0xffffffffu, mx0, 2));
        mx1 = fmaxf(mx1, __shfl_xor_sync(0xffffffffu, mx1, 1));
        mx1 = fmaxf(mx1, __shfl_xor_sync(0xffffffffu, mx1, 2));
        float mn0 = fmaxf(m0, mx0), mn1 = fmaxf(m1, mx1);
        float fs0 = __expf(m0 - mn0), fs1 = __expf(m1 - mn1);

        float ps0 = 0.f, ps1 = 0.f;
#pragma unroll
        for (int ni = 0; ni < 8; ni++) {
            float p0 = (sacc[ni][0] > -1e29f) ? __expf(sacc[ni][0] - mn0) : 0.f;
            float p1 = (sacc[ni][1] > -1e29f) ? __expf(sacc[ni][1] - mn0) : 0.f;
            float p2 = (sacc[ni][2] > -1e29f) ? __expf(sacc[ni][2] - mn1) : 0.f;
            float p3 = (sacc[ni][3] > -1e29f) ? __expf(sacc[ni][3] - mn1) : 0.f;
            sacc[ni][0] = p0; sacc[ni][1] = p1; sacc[ni][2] = p2; sacc[ni][3] = p3;
            ps0 += p0 + p1; ps1 += p2 + p3;
        }
        ps0 += __shfl_xor_sync(0xffffffffu, ps0, 1);
        ps0 += __shfl_xor_sync(0xffffffffu, ps0, 2);
        ps1 += __shfl_xor_sync(0xffffffffu, ps1, 1);
        ps1 += __shfl_xor_sync(0xffffffffu, ps1, 2);
        l0 = l0 * fs0 + ps0; l1 = l1 * fs1 + ps1;
        m0 = mn0; m1 = mn1;

#pragma unroll
        for (int nd = 0; nd < 16; nd++) {
            oacc[nd][0] *= fs0; oacc[nd][1] *= fs0;
            oacc[nd][2] *= fs1; oacc[nd][3] *= fs1;
        }

#pragma unroll
        for (int s = 0; s < 4; s++) {
            uint32_t a0 = packh2(sacc[2 * s][0], sacc[2 * s][1]);
            uint32_t a1 = packh2(sacc[2 * s][2], sacc[2 * s][3]);
            uint32_t a2 = packh2(sacc[2 * s + 1][0], sacc[2 * s + 1][1]);
            uint32_t a3 = packh2(sacc[2 * s + 1][2], sacc[2 * s + 1][3]);
            int kk = s * 16;
#pragma unroll
            for (int t8 = 0; t8 < 8; t8++) {
                uint32_t vt[4];
                ldm_x4_t(vt, sV + (uint32_t)(((kk + lrV) * QSTR + t8 * 16 + lcV) * 2));
                mma_fp16(oacc[2 * t8], a0, a1, a2, a3, vt[0], vt[1]);
                mma_fp16(oacc[2 * t8 + 1], a0, a1, a2, a3, vt[2], vt[3]);
            }
        }
    }

    float li0 = 1.f / l0, li1 = 1.f / l1;
#pragma unroll
    for (int nd = 0; nd < 16; nd++) {
        int col = head * HD + nd * 8 + 2 * tg;
        *(uint32_t*)&Og[(size_t)row0 * HID + col] =
            packh2(oacc[nd][0] * li0, oacc[nd][1] * li0);
        *(uint32_t*)&Og[(size_t)row1 * HID + col] =
            packh2(oacc[nd][2] * li1, oacc[nd][3] * li1);
    }
}

// ---------------- launch ----------------
extern "C" void kernel_launch(void* const* d_in, const int* in_sizes, int n_in,
                              void* d_out, int out_size) {
    const float* hs   = (const float*)d_in[0];
    const float* wq   = (const float*)d_in[1];
    const float* wk   = (const float*)d_in[2];
    const float* wv   = (const float*)d_in[3];
    const float* wo   = (const float*)d_in[4];
    const float* scq  = (const float*)d_in[5];
    const float* sck  = (const float*)d_in[6];
    const float* scv  = (const float*)d_in[7];
    const float* sco  = (const float*)d_in[8];
    const float* pqkv = (const float*)d_in[9];
    const float* po   = (const float*)d_in[10];
    const float* cosT = (const float*)d_in[11];
    const float* sinT = (const float*)d_in[12];
    float* out = (float*)d_out;

    __half *wmq, *wmk, *wmv, *wmo, *hst, *ao;
    float *q, *k, *v;
    int *ipq, *ipo;
    cudaGetSymbolAddress((void**)&wmq, g_wmq);
    cudaGetSymbolAddress((void**)&wmk, g_wmk);
    cudaGetSymbolAddress((void**)&wmv, g_wmv);
    cudaGetSymbolAddress((void**)&wmo, g_wmo);
    cudaGetSymbolAddress((void**)&hst, g_hst);
    cudaGetSymbolAddress((void**)&q,   g_q);
    cudaGetSymbolAddress((void**)&k,   g_k);
    cudaGetSymbolAddress((void**)&v,   g_v);
    cudaGetSymbolAddress((void**)&ao,  g_ao);
    cudaGetSymbolAddress((void**)&ipq, g_invp_qkv);
    cudaGetSymbolAddress((void**)&ipo, g_invp_o);

    const int smem64 = GEMM_SMEM_BM(64);
    cudaFuncSetAttribute(gemm_v4, cudaFuncAttributeMaxDynamicSharedMemorySize, V4_SMEM);
    cudaFuncSetAttribute(gemm_v3<64, 128>,
                         cudaFuncAttributeMaxDynamicSharedMemorySize, smem64);
    cudaFuncSetAttribute(flash_fp16, cudaFuncAttributeMaxDynamicSharedMemorySize, FL3_SMEM);

    const int mw_smem = HID * 6;      // H floats + H halves

    round_half<<<(SEQ * HID / 8 + 255) / 256, 256>>>(hs, hst, SEQ * HID / 8);        // 1
    perm_extract<<<(HID * HID + 255) / 256, 256>>>(pqkv, ipq, HID);                  // 2
    mask_weights_v2<<<HID, 256, mw_smem>>>(wq, scq, ipq, wmq, HID);                  // 3
    gemm_v4<<<dim3(HID / 128, SEQ / 128), 128, V4_SMEM>>>(hst, wmq, q,               // 4 (profiled)
                                                          SEQ, HID, HID);
    mask_weights_v2<<<KVD, 256, mw_smem>>>(wk, sck, ipq, wmk, HID);
    gemm_v3<64, 128><<<dim3(KVD / 128, SEQ / 64), 128, smem64>>>(hst, wmk, k,
                                                                 SEQ, KVD, HID);
    mask_weights_v2<<<KVD, 256, mw_smem>>>(wv, scv, ipq, wmv, HID);
    gemm_v3<64, 128><<<dim3(KVD / 128, SEQ / 64), 128, smem64>>>(hst, wmv, v,
                                                                 SEQ, KVD, HID);
    perm_extract<<<(HID * HID + 255) / 256, 256>>>(po, ipo, HID);
    mask_weights_v2<<<HID, 256, mw_smem>>>(wo, sco, ipo, wmo, HID);

    rope_kernel<<<(SEQ * NHEADS * 64 + 255) / 256, 256>>>(q, cosT, sinT, NHEADS);
    rope_kernel<<<(SEQ * NKVH * 64 + 255) / 256, 256>>>(k, cosT, sinT, NKVH);

    flash_fp16<<<dim3(SEQ / 128, NHEADS), 256, FL3_SMEM>>>(q, k, v, ao);

    gemm_v4<<<dim3(HID / 128, SEQ / 128), 128, V4_SMEM>>>(ao, wmo, out,
                                                          SEQ, HID, HID);
}

// round 10
// speedup vs baseline: 7.6712x; 1.0025x over previous
#include <cuda_runtime.h>
#include <cuda_fp16.h>
#include <cstdint>

#define HID 4096
#define KVD 1024
#define SEQ 2048
#define NHEADS 32
#define NKVH 8
#define HD 128

// ---------------- scratch ----------------
__device__ __half g_wmq[HID * HID];
__device__ __half g_wmo[HID * HID];
__device__ __half g_wmk[KVD * HID];
__device__ __half g_wmv[KVD * HID];
__device__ __half g_hst[SEQ * HID];
__device__ float  g_q[SEQ * HID];
__device__ float  g_k[SEQ * KVD];
__device__ __half g_qh[SEQ * HID];
__device__ __half g_kh[SEQ * KVD];
__device__ __half g_vh[SEQ * KVD];
__device__ __half g_ao[SEQ * HID];
__device__ int    g_invp_qkv[HID];
__device__ int    g_invp_o[HID];

__device__ __forceinline__ uint32_t smem_u32(const void* p) {
    return (uint32_t)__cvta_generic_to_shared((void*)p);
}
__device__ __forceinline__ uint32_t packh2(float x, float y) {
    __half2 h = __floats2half2_rn(x, y);
    return *(uint32_t*)&h;
}
__device__ __forceinline__ void ldm_x4(uint32_t (&r)[4], uint32_t addr) {
    asm volatile("ldmatrix.sync.aligned.m8n8.x4.shared.b16 {%0,%1,%2,%3}, [%4];"
                 : "=r"(r[0]), "=r"(r[1]), "=r"(r[2]), "=r"(r[3]) : "r"(addr));
}
__device__ __forceinline__ void ldm_x4_t(uint32_t (&r)[4], uint32_t addr) {
    asm volatile("ldmatrix.sync.aligned.m8n8.x4.trans.shared.b16 {%0,%1,%2,%3}, [%4];"
                 : "=r"(r[0]), "=r"(r[1]), "=r"(r[2]), "=r"(r[3]) : "r"(addr));
}
__device__ __forceinline__ void mma_fp16(float c[4], uint32_t a0, uint32_t a1,
                                         uint32_t a2, uint32_t a3,
                                         uint32_t b0, uint32_t b1) {
    asm volatile(
        "mma.sync.aligned.m16n8k16.row.col.f32.f16.f16.f32 "
        "{%0,%1,%2,%3}, {%4,%5,%6,%7}, {%8,%9}, {%0,%1,%2,%3};"
        : "+f"(c[0]), "+f"(c[1]), "+f"(c[2]), "+f"(c[3])
        : "r"(a0), "r"(a1), "r"(a2), "r"(a3), "r"(b0), "r"(b1));
}

// ---------------- permutation extraction ----------------
__global__ void perm_extract(const float* __restrict__ P, int* __restrict__ invp, int n) {
    int idx = blockIdx.x * blockDim.x + threadIdx.x;
    if (idx >= n * n) return;
    if (P[idx] > 0.5f) invp[idx % n] = idx / n;
}

// ---------------- hidden states: fp32 -> fp16 ----------------
__global__ void round_half(const float* __restrict__ X, __half* __restrict__ Y, int n8) {
    int i = blockIdx.x * blockDim.x + threadIdx.x;
    if (i >= n8) return;
    const float4* p = (const float4*)(X + (size_t)i * 8);
    float4 a = p[0], b = p[1];
    uint4 o;
    o.x = packh2(a.x, a.y); o.y = packh2(a.z, a.w);
    o.z = packh2(b.x, b.y); o.w = packh2(b.z, b.w);
    *(uint4*)(Y + (size_t)i * 8) = o;
}

// ---------------- 2:4 hard mask v2: block-per-row, smem staged ----------------
__global__ void __launch_bounds__(256) mask_weights_v2(const float* __restrict__ W,
                                                       const float* __restrict__ scaler,
                                                       const int* __restrict__ invp,
                                                       __half* __restrict__ Wm, int H) {
    extern __shared__ float smr[];            // [H] floats, then [H] halves
    __half* smo = (__half*)(smr + H);
    const int r = blockIdx.x;
    const float* Wr = W + (size_t)r * H;
    for (int i = threadIdx.x; i < H / 4; i += 256)
        ((float4*)smr)[i] = ((const float4*)Wr)[i];
    __syncthreads();
    const int G = H >> 2;
    for (int g = threadIdx.x; g < G; g += 256) {
        int4 c = ((const int4*)invp)[g];
        float w0 = smr[c.x], w1 = smr[c.y], w2 = smr[c.z], w3 = smr[c.w];
        float m0 = fabsf(w0) * sqrtf(__ldg(scaler + c.x));
        float m1 = fabsf(w1) * sqrtf(__ldg(scaler + c.y));
        float m2 = fabsf(w2) * sqrtf(__ldg(scaler + c.z));
        float m3 = fabsf(w3) * sqrtf(__ldg(scaler + c.w));
        int r0 = (m1 > m0) + (m2 > m0) + (m3 > m0);
        int r1 = (m0 >= m1) + (m2 > m1) + (m3 > m1);
        int r2 = (m0 >= m2) + (m1 >= m2) + (m3 > m2);
        int r3 = (m0 >= m3) + (m1 >= m3) + (m2 >= m3);
        smo[c.x] = __float2half_rn(r0 < 2 ? w0 : 0.f);
        smo[c.y] = __float2half_rn(r1 < 2 ? w1 : 0.f);
        smo[c.z] = __float2half_rn(r2 < 2 ? w2 : 0.f);
        smo[c.w] = __float2half_rn(r3 < 2 ? w3 : 0.f);
    }
    __syncthreads();
    __half* Wo = Wm + (size_t)r * H;
    for (int i = threadIdx.x; i < H / 8; i += 256)
        ((uint4*)Wo)[i] = ((const uint4*)smo)[i];
}

// ---------------- fp16 NT GEMM v3: 3-slot/2-ahead, BK=64 (K/V projections) ----
#define GSH 72
#define GEMM_SMEM_BM(BM) (3 * ((BM) + 128) * GSH * 2)

template <int BM, int NTHR, bool HOUT>
__global__ void __launch_bounds__(NTHR, 2) gemm_v3(const __half* __restrict__ A,
                                                   const __half* __restrict__ B,
                                                   void* __restrict__ Cv,
                                                   int M, int N, int K) {
    extern __shared__ __half sh[];
    constexpr int STGH = (BM + 128) * GSH;
    constexpr uint32_t STGB = STGH * 2;
    constexpr uint32_t ABYTES = BM * GSH * 2;
    constexpr int AIT = BM * 8 / NTHR;
    constexpr int BIT = 128 * 8 / NTHR;

    const int tid = threadIdx.x, wid = tid >> 5, lane = tid & 31;
    const int g = lane >> 2, tg = lane & 3;
    const int wm = (wid >> 2) * 64, wn = (wid & 3) * 32;
    const int bm = blockIdx.y * BM, bn = blockIdx.x * 128;

    float acc[4][4][4] = {};
    uint32_t sA = smem_u32(sh);

    const uint32_t aoff = (uint32_t)((wm + (lane & 15)) * (GSH * 2) + (((lane >> 4) << 3) << 1));
    const uint32_t boff = ABYTES +
        (uint32_t)((wn + (lane & 7) + ((lane >> 4) << 3)) * (GSH * 2) +
                   ((((lane >> 3) & 1) << 3) << 1));

#define LOADSTAGE(slot, k0)                                                       \
    do {                                                                          \
        uint32_t so = sA + (uint32_t)(slot)*STGB;                                 \
        _Pragma("unroll")                                                         \
        for (int i = 0; i < AIT; i++) {                                           \
            int id = tid + i * NTHR;                                              \
            int row = id >> 3, ch = id & 7;                                       \
            const __half* pa = A + (size_t)(bm + row) * K + (k0) + ch * 8;        \
            asm volatile("cp.async.cg.shared.global [%0], [%1], 16;"              \
                         ::"r"(so + (uint32_t)((row * 9 + ch) * 16)), "l"(pa));   \
        }                                                                         \
        _Pragma("unroll")                                                         \
        for (int i = 0; i < BIT; i++) {                                           \
            int id = tid + i * NTHR;                                              \
            int row = id >> 3, ch = id & 7;                                       \
            const __half* pb = B + (size_t)(bn + row) * K + (k0) + ch * 8;        \
            asm volatile("cp.async.cg.shared.global [%0], [%1], 16;"              \
                         ::"r"(so + ABYTES + (uint32_t)((row * 9 + ch) * 16)),    \
                           "l"(pb));                                              \
        }                                                                         \
    } while (0)

    const int nk = K >> 6;
    LOADSTAGE(0, 0);
    asm volatile("cp.async.commit_group;");
    LOADSTAGE(1, 64);
    asm volatile("cp.async.commit_group;");

    for (int t = 0; t < nk; t++) {
        asm volatile("cp.async.wait_group 1;");
        __syncthreads();
        if (t + 2 < nk) LOADSTAGE((t + 2) % 3, (t + 2) * 64);
        asm volatile("cp.async.commit_group;");

        uint32_t base = sA + (uint32_t)(t % 3) * STGB;
#pragma unroll
        for (int ks = 0; ks < 4; ks++) {
            uint32_t kadd = (uint32_t)(ks * 32);
            uint32_t bt[2][4];
            ldm_x4(bt[0], base + boff + kadd);
            ldm_x4(bt[1], base + boff + kadd + 16 * (GSH * 2));
#pragma unroll
            for (int mi = 0; mi < 4; mi++) {
                uint32_t af[4];
                ldm_x4(af, base + aoff + kadd + (uint32_t)(mi * 16 * (GSH * 2)));
#pragma unroll
                for (int nb = 0; nb < 2; nb++) {
                    mma_fp16(acc[mi][2 * nb], af[0], af[1], af[2], af[3],
                             bt[nb][0], bt[nb][1]);
                    mma_fp16(acc[mi][2 * nb + 1], af[0], af[1], af[2], af[3],
                             bt[nb][2], bt[nb][3]);
                }
            }
        }
    }

#pragma unroll
    for (int mi = 0; mi < 4; mi++)
#pragma unroll
        for (int ni = 0; ni < 4; ni++) {
            int row = bm + wm + mi * 16 + g;
            int col = bn + wn + ni * 8 + tg * 2;
            if constexpr (HOUT) {
                __half* Ch = (__half*)Cv;
                *(uint32_t*)&Ch[(size_t)row * N + col] =
                    packh2(acc[mi][ni][0], acc[mi][ni][1]);
                *(uint32_t*)&Ch[(size_t)(row + 8) * N + col] =
                    packh2(acc[mi][ni][2], acc[mi][ni][3]);
            } else {
                float* Cf = (float*)Cv;
                *(float2*)&Cf[(size_t)row * N + col] =
                    make_float2(acc[mi][ni][0], acc[mi][ni][1]);
                *(float2*)&Cf[(size_t)(row + 8) * N + col] =
                    make_float2(acc[mi][ni][2], acc[mi][ni][3]);
            }
        }
#undef LOADSTAGE
}

// ---------------- fp16 NT GEMM v4: 128x128 CTA, 4 warps, 64x64 warptile -------
#define V4_STGB 32768u
#define V4_SMEM (3 * 32768)

__global__ void __launch_bounds__(128, 2) gemm_v4(const __half* __restrict__ A,
                                                  const __half* __restrict__ B,
                                                  float* __restrict__ C,
                                                  int M, int N, int K) {
    extern __shared__ __half sh[];
    const int tid = threadIdx.x, wid = tid >> 5, lane = tid & 31;
    const int g = lane >> 2, tg = lane & 3;
    const int wm = (wid >> 1) * 64, wn = (wid & 1) * 64;
    const int bm = blockIdx.y * 128, bn = blockIdx.x * 128;

    float acc[4][8][4] = {};
    uint32_t sA = smem_u32(sh);

    const int arow = lane & 15;
    const int apar = lane >> 4;
    const int brow = (lane & 7) + ((lane >> 4) << 3);
    const int bpar = (lane >> 3) & 1;

#define V4LOAD(slot, k0)                                                          \
    do {                                                                          \
        uint32_t so = sA + (uint32_t)(slot)*V4_STGB;                              \
        _Pragma("unroll")                                                         \
        for (int i = 0; i < 16; i++) {                                            \
            int id = tid + i * 128;                                               \
            int row = id >> 3, ch = id & 7;                                       \
            const __half* gp = (row < 128)                                        \
                ? A + (size_t)(bm + row) * K + (k0) + ch * 8                      \
                : B + (size_t)(bn + row - 128) * K + (k0) + ch * 8;               \
            asm volatile("cp.async.cg.shared.global [%0], [%1], 16;"              \
                         ::"r"(so + (uint32_t)(row * 128 +                        \
                                               ((ch ^ (row & 7)) * 16))),         \
                           "l"(gp));                                              \
        }                                                                         \
    } while (0)

    const int nk = K >> 6;
    V4LOAD(0, 0);
    asm volatile("cp.async.commit_group;");
    V4LOAD(1, 64);
    asm volatile("cp.async.commit_group;");

    for (int t = 0; t < nk; t++) {
        asm volatile("cp.async.wait_group 1;");
        __syncthreads();
        if (t + 2 < nk) V4LOAD((t + 2) % 3, (t + 2) * 64);
        asm volatile("cp.async.commit_group;");

        uint32_t base = sA + (uint32_t)(t % 3) * V4_STGB;
#pragma unroll
        for (int ks = 0; ks < 4; ks++) {
            uint32_t af[4][4], bt[4][4];
#pragma unroll
            for (int mi = 0; mi < 4; mi++) {
                int row = wm + mi * 16 + arow;
                int ch = 2 * ks + apar;
                ldm_x4(af[mi], base + (uint32_t)(row * 128 + ((ch ^ (row & 7)) * 16)));
            }
#pragma unroll
            for (int nb = 0; nb < 4; nb++) {
                int row = 128 + wn + nb * 16 + brow;
                int ch = 2 * ks + bpar;
                ldm_x4(bt[nb], base + (uint32_t)(row * 128 + ((ch ^ (row & 7)) * 16)));
            }
#pragma unroll
            for (int mi = 0; mi < 4; mi++)
#pragma unroll
                for (int nb = 0; nb < 4; nb++) {
                    mma_fp16(acc[mi][2 * nb], af[mi][0], af[mi][1], af[mi][2],
                             af[mi][3], bt[nb][0], bt[nb][1]);
                    mma_fp16(acc[mi][2 * nb + 1], af[mi][0], af[mi][1], af[mi][2],
                             af[mi][3], bt[nb][2], bt[nb][3]);
                }
        }
    }

#pragma unroll
    for (int mi = 0; mi < 4; mi++)
#pragma unroll
        for (int ni = 0; ni < 8; ni++) {
            int row = bm + wm + mi * 16 + g;
            int col = bn + wn + ni * 8 + tg * 2;
            *(float2*)&C[(size_t)row * N + col] =
                make_float2(acc[mi][ni][0], acc[mi][ni][1]);
            *(float2*)&C[(size_t)(row + 8) * N + col] =
                make_float2(acc[mi][ni][2], acc[mi][ni][3]);
        }
#undef V4LOAD
}

// ---------------- RoPE: fp32 in -> rotated fp16 out ----------------
__global__ void rope_half(const float* __restrict__ X, __half* __restrict__ Y,
                          const float* __restrict__ cosT, const float* __restrict__ sinT,
                          int nheads) {
    int idx = blockIdx.x * blockDim.x + threadIdx.x;
    int total = SEQ * nheads * 64;
    if (idx >= total) return;
    int d = idx & 63;
    int h = (idx >> 6) % nheads;
    int s = idx / (64 * nheads);
    const float* p = X + (size_t)s * nheads * HD + h * HD + d;
    float x1 = p[0], x2 = p[64];
    float c1 = cosT[s * HD + d],      s1 = sinT[s * HD + d];
    float c2 = cosT[s * HD + 64 + d], s2 = sinT[s * HD + 64 + d];
    __half* o = Y + (size_t)s * nheads * HD + h * HD + d;
    o[0]  = __float2half_rn(fmaf(x1, c1, -x2 * s1));
    o[64] = __float2half_rn(fmaf(x2, c2,  x1 * s2));
}

// ---------------- fp16 flash attention v2: cp.async fills, fp16 gmem ----------
#define QSTR 136
#define FL3_SMEM ((128 + 64 + 64) * QSTR * 2)

__global__ void __launch_bounds__(256) flash_fp16_v2(const __half* __restrict__ Qg,
                                                     const __half* __restrict__ Kg,
                                                     const __half* __restrict__ Vg,
                                                     __half* __restrict__ Og) {
    extern __shared__ __half sm[];
    __half* Qs = sm;
    __half* Ks = Qs + 128 * QSTR;
    __half* Vs = Ks + 64 * QSTR;

    const int tid = threadIdx.x, wid = tid >> 5, lane = tid & 31;
    const int g = lane >> 2, tg = lane & 3;
    const int qb = gridDim.x - 1 - blockIdx.x;   // heavy CTAs first
    const int head = blockIdx.y, kvh = head >> 2;
    const __half* Qh = Qg + head * HD;    // row stride HID
    const __half* Kh = Kg + kvh * HD;     // row stride KVD
    const __half* Vh = Vg + kvh * HD;

    uint32_t sQ = smem_u32(Qs), sK = smem_u32(Ks), sV = smem_u32(Vs);

    // Q fill: 128 rows x 16 chunks of 16B, cp.async
#pragma unroll
    for (int i = 0; i < 8; i++) {
        int id = tid + i * 256;
        int r = id >> 4, ch = id & 15;
        const __half* src = Qh + (size_t)(qb * 128 + r) * HID + ch * 8;
        asm volatile("cp.async.cg.shared.global [%0], [%1], 16;"
                     ::"r"(sQ + (uint32_t)(r * (QSTR * 2) + ch * 16)), "l"(src));
    }
    asm volatile("cp.async.commit_group;");

    const int wm = wid * 16;
    const int row0 = qb * 128 + wm + g, row1 = row0 + 8;
    const int rowTop = qb * 128 + wm + 15;
    float m0 = -1e30f, m1 = -1e30f, l0 = 0.f, l1 = 0.f;
    float oacc[16][4];
#pragma unroll
    for (int i = 0; i < 16; i++)
#pragma unroll
        for (int j = 0; j < 4; j++) oacc[i][j] = 0.f;

    const float scale = 0.08838834764831845f;
    const int nkb = 2 * qb + 2;

    const int lrA = wm + (lane & 15), lcA = (lane >> 4) << 3;
    const int lrK = (lane & 7) + ((lane >> 4) << 3), lcK = ((lane >> 3) & 1) << 3;
    const int lrV = (lane & 7) + (((lane >> 3) & 1) << 3), lcV = (lane >> 4) << 3;

    for (int kb = 0; kb < nkb; kb++) {
        __syncthreads();              // prev compute done -> K/V smem reusable
        // K and V fill: 64 rows x 16 chunks each, cp.async
#pragma unroll
        for (int i = 0; i < 4; i++) {
            int id = tid + i * 256;
            int r = id >> 4, ch = id & 15;
            uint32_t d = (uint32_t)(r * (QSTR * 2) + ch * 16);
            const __half* srck = Kh + (size_t)(kb * 64 + r) * KVD + ch * 8;
            const __half* srcv = Vh + (size_t)(kb * 64 + r) * KVD + ch * 8;
            asm volatile("cp.async.cg.shared.global [%0], [%1], 16;"
                         ::"r"(sK + d), "l"(srck));
            asm volatile("cp.async.cg.shared.global [%0], [%1], 16;"
                         ::"r"(sV + d), "l"(srcv));
        }
        asm volatile("cp.async.commit_group;");
        asm volatile("cp.async.wait_group 0;");   // own copies (incl. Q) done
        __syncthreads();                          // all threads' copies done
        if (kb * 64 > rowTop) continue;

        float sacc[8][4];
#pragma unroll
        for (int ni = 0; ni < 8; ni++)
#pragma unroll
            for (int j = 0; j < 4; j++) sacc[ni][j] = 0.f;
#pragma unroll
        for (int ks = 0; ks < 8; ks++) {
            int kk = ks * 16;
            uint32_t af[4];
            ldm_x4(af, sQ + (uint32_t)((lrA * QSTR + kk + lcA) * 2));
#pragma unroll
            for (int nb = 0; nb < 4; nb++) {
                uint32_t bt[4];
                ldm_x4(bt, sK + (uint32_t)(((nb * 16 + lrK) * QSTR + kk + lcK) * 2));
                mma_fp16(sacc[2 * nb], af[0], af[1], af[2], af[3], bt[0], bt[1]);
                mma_fp16(sacc[2 * nb + 1], af[0], af[1], af[2], af[3], bt[2], bt[3]);
            }
        }

#pragma unroll
        for (int ni = 0; ni < 8; ni++) {
            int c0 = kb * 64 + ni * 8 + 2 * tg, c1 = c0 + 1;
            sacc[ni][0] = (c0 <= row0) ? sacc[ni][0] * scale : -1e30f;
            sacc[ni][1] = (c1 <= row0) ? sacc[ni][1] * scale : -1e30f;
            sacc[ni][2] = (c0 <= row1) ? sacc[ni][2] * scale : -1e30f;
            sacc[ni][3] = (c1 <= row1) ? sacc[ni][3] * scale : -1e30f;
        }

        float mx0 = -1e30f, mx1 = -1e30f;
#pragma unroll
        for (int ni = 0; ni < 8; ni++) {
            mx0 = fmaxf(mx0, fmaxf(sacc[ni][0], sacc[ni][1]));
            mx1 = fmaxf(mx1, fmaxf(sacc[ni][2], sacc[ni][3]));
        }
        mx0 = fmaxf(mx0, __shfl_xor_sync(0xffffffffu, mx0, 1));
        mx0 = fmaxf(mx0, __shfl_xor_sync(0xffffffffu, mx0, 2));
        mx1 = fmaxf(mx1, __shfl_xor_sync(0xffffffffu, mx1, 1));
        mx1 = fmaxf(mx1, __shfl_xor_sync(0xffffffffu, mx1, 2));
        float mn0 = fmaxf(m0, mx0), mn1 = fmaxf(m1, mx1);
        float fs0 = __expf(m0 - mn0), fs1 = __expf(m1 - mn1);

        float ps0 = 0.f, ps1 = 0.f;
#pragma unroll
        for (int ni = 0; ni < 8; ni++) {
            float p0 = (sacc[ni][0] > -1e29f) ? __expf(sacc[ni][0] - mn0) : 0.f;
            float p1 = (sacc[ni][1] > -1e29f) ? __expf(sacc[ni][1] - mn0) : 0.f;
            float p2 = (sacc[ni][2] > -1e29f) ? __expf(sacc[ni][2] - mn1) : 0.f;
            float p3 = (sacc[ni][3] > -1e29f) ? __expf(sacc[ni][3] - mn1) : 0.f;
            sacc[ni][0] = p0; sacc[ni][1] = p1; sacc[ni][2] = p2; sacc[ni][3] = p3;
            ps0 += p0 + p1; ps1 += p2 + p3;
        }
        ps0 += __shfl_xor_sync(0xffffffffu, ps0, 1);
        ps0 += __shfl_xor_sync(0xffffffffu, ps0, 2);
        ps1 += __shfl_xor_sync(0xffffffffu, ps1, 1);
        ps1 += __shfl_xor_sync(0xffffffffu, ps1, 2);
        l0 = l0 * fs0 + ps0; l1 = l1 * fs1 + ps1;
        m0 = mn0; m1 = mn1;

#pragma unroll
        for (int nd = 0; nd < 16; nd++) {
            oacc[nd][0] *= fs0; oacc[nd][1] *= fs0;
            oacc[nd][2] *= fs1; oacc[nd][3] *= fs1;
        }

#pragma unroll
        for (int s = 0; s < 4; s++) {
            uint32_t a0 = packh2(sacc[2 * s][0], sacc[2 * s][1]);
            uint32_t a1 = packh2(sacc[2 * s][2], sacc[2 * s][3]);
            uint32_t a2 = packh2(sacc[2 * s + 1][0], sacc[2 * s + 1][1]);
            uint32_t a3 = packh2(sacc[2 * s + 1][2], sacc[2 * s + 1][3]);
            int kk = s * 16;
#pragma unroll
            for (int t8 = 0; t8 < 8; t8++) {
                uint32_t vt[4];
                ldm_x4_t(vt, sV + (uint32_t)(((kk + lrV) * QSTR + t8 * 16 + lcV) * 2));
                mma_fp16(oacc[2 * t8], a0, a1, a2, a3, vt[0], vt[1]);
                mma_fp16(oacc[2 * t8 + 1], a0, a1, a2, a3, vt[2], vt[3]);
            }
        }
    }

    float li0 = 1.f / l0, li1 = 1.f / l1;
#pragma unroll
    for (int nd = 0; nd < 16; nd++) {
        int col = head * HD + nd * 8 + 2 * tg;
        *(uint32_t*)&Og[(size_t)row0 * HID + col] =
            packh2(oacc[nd][0] * li0, oacc[nd][1] * li0);
        *(uint32_t*)&Og[(size_t)row1 * HID + col] =
            packh2(oacc[nd][2] * li1, oacc[nd][3] * li1);
    }
}

// ---------------- launch ----------------
extern "C" void kernel_launch(void* const* d_in, const int* in_sizes, int n_in,
                              void* d_out, int out_size) {
    const float* hs   = (const float*)d_in[0];
    const float* wq   = (const float*)d_in[1];
    const float* wk   = (const float*)d_in[2];
    const float* wv   = (const float*)d_in[3];
    const float* wo   = (const float*)d_in[4];
    const float* scq  = (const float*)d_in[5];
    const float* sck  = (const float*)d_in[6];
    const float* scv  = (const float*)d_in[7];
    const float* sco  = (const float*)d_in[8];
    const float* pqkv = (const float*)d_in[9];
    const float* po   = (const float*)d_in[10];
    const float* cosT = (const float*)d_in[11];
    const float* sinT = (const float*)d_in[12];
    float* out = (float*)d_out;

    __half *wmq, *wmk, *wmv, *wmo, *hst, *qh, *kh, *vh, *ao;
    float *q, *k;
    int *ipq, *ipo;
    cudaGetSymbolAddress((void**)&wmq, g_wmq);
    cudaGetSymbolAddress((void**)&wmk, g_wmk);
    cudaGetSymbolAddress((void**)&wmv, g_wmv);
    cudaGetSymbolAddress((void**)&wmo, g_wmo);
    cudaGetSymbolAddress((void**)&hst, g_hst);
    cudaGetSymbolAddress((void**)&q,   g_q);
    cudaGetSymbolAddress((void**)&k,   g_k);
    cudaGetSymbolAddress((void**)&qh,  g_qh);
    cudaGetSymbolAddress((void**)&kh,  g_kh);
    cudaGetSymbolAddress((void**)&vh,  g_vh);
    cudaGetSymbolAddress((void**)&ao,  g_ao);
    cudaGetSymbolAddress((void**)&ipq, g_invp_qkv);
    cudaGetSymbolAddress((void**)&ipo, g_invp_o);

    const int smem64 = GEMM_SMEM_BM(64);
    cudaFuncSetAttribute(gemm_v4, cudaFuncAttributeMaxDynamicSharedMemorySize, V4_SMEM);
    cudaFuncSetAttribute(gemm_v3<64, 128, false>,
                         cudaFuncAttributeMaxDynamicSharedMemorySize, smem64);
    cudaFuncSetAttribute(gemm_v3<64, 128, true>,
                         cudaFuncAttributeMaxDynamicSharedMemorySize, smem64);
    cudaFuncSetAttribute(flash_fp16_v2, cudaFuncAttributeMaxDynamicSharedMemorySize,
                         FL3_SMEM);

    const int mw_smem = HID * 6;      // H floats + H halves

    round_half<<<(SEQ * HID / 8 + 255) / 256, 256>>>(hs, hst, SEQ * HID / 8);        // 1
    perm_extract<<<(HID * HID + 255) / 256, 256>>>(pqkv, ipq, HID);                  // 2
    mask_weights_v2<<<HID, 256, mw_smem>>>(wq, scq, ipq, wmq, HID);                  // 3
    gemm_v4<<<dim3(HID / 128, SEQ / 128), 128, V4_SMEM>>>(hst, wmq, q,               // 4 (profiled)
                                                          SEQ, HID, HID);
    mask_weights_v2<<<KVD, 256, mw_smem>>>(wk, sck, ipq, wmk, HID);
    gemm_v3<64, 128, false><<<dim3(KVD / 128, SEQ / 64), 128, smem64>>>(hst, wmk, k,
                                                                        SEQ, KVD, HID);
    mask_weights_v2<<<KVD, 256, mw_smem>>>(wv, scv, ipq, wmv, HID);
    gemm_v3<64, 128, true><<<dim3(KVD / 128, SEQ / 64), 128, smem64>>>(hst, wmv, vh,
                                                                       SEQ, KVD, HID);
    perm_extract<<<(HID * HID + 255) / 256, 256>>>(po, ipo, HID);
    mask_weights_v2<<<HID, 256, mw_smem>>>(wo, sco, ipo, wmo, HID);

    rope_half<<<(SEQ * NHEADS * 64 + 255) / 256, 256>>>(q, qh, cosT, sinT, NHEADS);
    rope_half<<<(SEQ * NKVH * 64 + 255) / 256, 256>>>(k, kh, cosT, sinT, NKVH);

    flash_fp16_v2<<<dim3(SEQ / 128, NHEADS), 256, FL3_SMEM>>>(qh, kh, vh, ao);

    gemm_v4<<<dim3(HID / 128, SEQ / 128), 128, V4_SMEM>>>(ao, wmo, out,
                                                          SEQ, HID, HID);
}

// round 11
// speedup vs baseline: 7.8618x; 1.0249x over previous
#include <cuda_runtime.h>
#include <cuda_fp16.h>
#include <cstdint>

#define HID 4096
#define KVD 1024
#define SEQ 2048
#define NHEADS 32
#define NKVH 8
#define HD 128

// ---------------- scratch ----------------
__device__ __half g_wmq[HID * HID];
__device__ __half g_wmo[HID * HID];
__device__ __half g_wmk[KVD * HID];
__device__ __half g_wmv[KVD * HID];
__device__ __half g_hst[SEQ * HID];
__device__ float  g_q[SEQ * HID];
__device__ float  g_k[SEQ * KVD];
__device__ __half g_qh[SEQ * HID];
__device__ __half g_kh[SEQ * KVD];
__device__ __half g_vh[SEQ * KVD];
__device__ __half g_ao[SEQ * HID];
__device__ int    g_invp_qkv[HID];
__device__ int    g_invp_o[HID];

__device__ __forceinline__ uint32_t smem_u32(const void* p) {
    return (uint32_t)__cvta_generic_to_shared((void*)p);
}
__device__ __forceinline__ uint32_t packh2(float x, float y) {
    __half2 h = __floats2half2_rn(x, y);
    return *(uint32_t*)&h;
}
__device__ __forceinline__ void ldm_x4(uint32_t (&r)[4], uint32_t addr) {
    asm volatile("ldmatrix.sync.aligned.m8n8.x4.shared.b16 {%0,%1,%2,%3}, [%4];"
                 : "=r"(r[0]), "=r"(r[1]), "=r"(r[2]), "=r"(r[3]) : "r"(addr));
}
__device__ __forceinline__ void ldm_x4_t(uint32_t (&r)[4], uint32_t addr) {
    asm volatile("ldmatrix.sync.aligned.m8n8.x4.trans.shared.b16 {%0,%1,%2,%3}, [%4];"
                 : "=r"(r[0]), "=r"(r[1]), "=r"(r[2]), "=r"(r[3]) : "r"(addr));
}
__device__ __forceinline__ void mma_fp16(float c[4], uint32_t a0, uint32_t a1,
                                         uint32_t a2, uint32_t a3,
                                         uint32_t b0, uint32_t b1) {
    asm volatile(
        "mma.sync.aligned.m16n8k16.row.col.f32.f16.f16.f32 "
        "{%0,%1,%2,%3}, {%4,%5,%6,%7}, {%8,%9}, {%0,%1,%2,%3};"
        : "+f"(c[0]), "+f"(c[1]), "+f"(c[2]), "+f"(c[3])
        : "r"(a0), "r"(a1), "r"(a2), "r"(a3), "r"(b0), "r"(b1));
}

// ---------------- permutation extraction ----------------
__global__ void perm_extract(const float* __restrict__ P, int* __restrict__ invp, int n) {
    int idx = blockIdx.x * blockDim.x + threadIdx.x;
    if (idx >= n * n) return;
    if (P[idx] > 0.5f) invp[idx % n] = idx / n;
}

// ---------------- hidden states: fp32 -> fp16 ----------------
__global__ void round_half(const float* __restrict__ X, __half* __restrict__ Y, int n8) {
    int i = blockIdx.x * blockDim.x + threadIdx.x;
    if (i >= n8) return;
    const float4* p = (const float4*)(X + (size_t)i * 8);
    float4 a = p[0], b = p[1];
    uint4 o;
    o.x = packh2(a.x, a.y); o.y = packh2(a.z, a.w);
    o.z = packh2(b.x, b.y); o.w = packh2(b.z, b.w);
    *(uint4*)(Y + (size_t)i * 8) = o;
}

// ---------------- 2:4 hard mask v2: block-per-row, smem staged ----------------
__global__ void __launch_bounds__(256) mask_weights_v2(const float* __restrict__ W,
                                                       const float* __restrict__ scaler,
                                                       const int* __restrict__ invp,
                                                       __half* __restrict__ Wm, int H) {
    extern __shared__ float smr[];            // [H] floats, then [H] halves
    __half* smo = (__half*)(smr + H);
    const int r = blockIdx.x;
    const float* Wr = W + (size_t)r * H;
    for (int i = threadIdx.x; i < H / 4; i += 256)
        ((float4*)smr)[i] = ((const float4*)Wr)[i];
    __syncthreads();
    const int G = H >> 2;
    for (int g = threadIdx.x; g < G; g += 256) {
        int4 c = ((const int4*)invp)[g];
        float w0 = smr[c.x], w1 = smr[c.y], w2 = smr[c.z], w3 = smr[c.w];
        float m0 = fabsf(w0) * sqrtf(__ldg(scaler + c.x));
        float m1 = fabsf(w1) * sqrtf(__ldg(scaler + c.y));
        float m2 = fabsf(w2) * sqrtf(__ldg(scaler + c.z));
        float m3 = fabsf(w3) * sqrtf(__ldg(scaler + c.w));
        int r0 = (m1 > m0) + (m2 > m0) + (m3 > m0);
        int r1 = (m0 >= m1) + (m2 > m1) + (m3 > m1);
        int r2 = (m0 >= m2) + (m1 >= m2) + (m3 > m2);
        int r3 = (m0 >= m3) + (m1 >= m3) + (m2 >= m3);
        smo[c.x] = __float2half_rn(r0 < 2 ? w0 : 0.f);
        smo[c.y] = __float2half_rn(r1 < 2 ? w1 : 0.f);
        smo[c.z] = __float2half_rn(r2 < 2 ? w2 : 0.f);
        smo[c.w] = __float2half_rn(r3 < 2 ? w3 : 0.f);
    }
    __syncthreads();
    __half* Wo = Wm + (size_t)r * H;
    for (int i = threadIdx.x; i < H / 8; i += 256)
        ((uint4*)Wo)[i] = ((const uint4*)smo)[i];
}

// ---------------- fp16 NT GEMM v3: 3-slot/2-ahead, BK=64 (K/V projections) ----
#define GSH 72
#define GEMM_SMEM_BM(BM) (3 * ((BM) + 128) * GSH * 2)

template <int BM, int NTHR, bool HOUT>
__global__ void __launch_bounds__(NTHR, 2) gemm_v3(const __half* __restrict__ A,
                                                   const __half* __restrict__ B,
                                                   void* __restrict__ Cv,
                                                   int M, int N, int K) {
    extern __shared__ __half sh[];
    constexpr int STGH = (BM + 128) * GSH;
    constexpr uint32_t STGB = STGH * 2;
    constexpr uint32_t ABYTES = BM * GSH * 2;
    constexpr int AIT = BM * 8 / NTHR;
    constexpr int BIT = 128 * 8 / NTHR;

    const int tid = threadIdx.x, wid = tid >> 5, lane = tid & 31;
    const int g = lane >> 2, tg = lane & 3;
    const int wm = (wid >> 2) * 64, wn = (wid & 3) * 32;
    const int bm = blockIdx.y * BM, bn = blockIdx.x * 128;

    float acc[4][4][4] = {};
    uint32_t sA = smem_u32(sh);

    const uint32_t aoff = (uint32_t)((wm + (lane & 15)) * (GSH * 2) + (((lane >> 4) << 3) << 1));
    const uint32_t boff = ABYTES +
        (uint32_t)((wn + (lane & 7) + ((lane >> 4) << 3)) * (GSH * 2) +
                   ((((lane >> 3) & 1) << 3) << 1));

#define LOADSTAGE(slot, k0)                                                       \
    do {                                                                          \
        uint32_t so = sA + (uint32_t)(slot)*STGB;                                 \
        _Pragma("unroll")                                                         \
        for (int i = 0; i < AIT; i++) {                                           \
            int id = tid + i * NTHR;                                              \
            int row = id >> 3, ch = id & 7;                                       \
            const __half* pa = A + (size_t)(bm + row) * K + (k0) + ch * 8;        \
            asm volatile("cp.async.cg.shared.global [%0], [%1], 16;"              \
                         ::"r"(so + (uint32_t)((row * 9 + ch) * 16)), "l"(pa));   \
        }                                                                         \
        _Pragma("unroll")                                                         \
        for (int i = 0; i < BIT; i++) {                                           \
            int id = tid + i * NTHR;                                              \
            int row = id >> 3, ch = id & 7;                                       \
            const __half* pb = B + (size_t)(bn + row) * K + (k0) + ch * 8;        \
            asm volatile("cp.async.cg.shared.global [%0], [%1], 16;"              \
                         ::"r"(so + ABYTES + (uint32_t)((row * 9 + ch) * 16)),    \
                           "l"(pb));                                              \
        }                                                                         \
    } while (0)

    const int nk = K >> 6;
    LOADSTAGE(0, 0);
    asm volatile("cp.async.commit_group;");
    LOADSTAGE(1, 64);
    asm volatile("cp.async.commit_group;");

    for (int t = 0; t < nk; t++) {
        asm volatile("cp.async.wait_group 1;");
        __syncthreads();
        if (t + 2 < nk) LOADSTAGE((t + 2) % 3, (t + 2) * 64);
        asm volatile("cp.async.commit_group;");

        uint32_t base = sA + (uint32_t)(t % 3) * STGB;
#pragma unroll
        for (int ks = 0; ks < 4; ks++) {
            uint32_t kadd = (uint32_t)(ks * 32);
            uint32_t bt[2][4];
            ldm_x4(bt[0], base + boff + kadd);
            ldm_x4(bt[1], base + boff + kadd + 16 * (GSH * 2));
#pragma unroll
            for (int mi = 0; mi < 4; mi++) {
                uint32_t af[4];
                ldm_x4(af, base + aoff + kadd + (uint32_t)(mi * 16 * (GSH * 2)));
#pragma unroll
                for (int nb = 0; nb < 2; nb++) {
                    mma_fp16(acc[mi][2 * nb], af[0], af[1], af[2], af[3],
                             bt[nb][0], bt[nb][1]);
                    mma_fp16(acc[mi][2 * nb + 1], af[0], af[1], af[2], af[3],
                             bt[nb][2], bt[nb][3]);
                }
            }
        }
    }

#pragma unroll
    for (int mi = 0; mi < 4; mi++)
#pragma unroll
        for (int ni = 0; ni < 4; ni++) {
            int row = bm + wm + mi * 16 + g;
            int col = bn + wn + ni * 8 + tg * 2;
            if constexpr (HOUT) {
                __half* Ch = (__half*)Cv;
                *(uint32_t*)&Ch[(size_t)row * N + col] =
                    packh2(acc[mi][ni][0], acc[mi][ni][1]);
                *(uint32_t*)&Ch[(size_t)(row + 8) * N + col] =
                    packh2(acc[mi][ni][2], acc[mi][ni][3]);
            } else {
                float* Cf = (float*)Cv;
                *(float2*)&Cf[(size_t)row * N + col] =
                    make_float2(acc[mi][ni][0], acc[mi][ni][1]);
                *(float2*)&Cf[(size_t)(row + 8) * N + col] =
                    make_float2(acc[mi][ni][2], acc[mi][ni][3]);
            }
        }
#undef LOADSTAGE
}

// ---------------- fp16 NT GEMM v4: 128x128 CTA, 4 warps, 64x64 warptile -------
#define V4_STGB 32768u
#define V4_SMEM (3 * 32768)

__global__ void __launch_bounds__(128, 2) gemm_v4(const __half* __restrict__ A,
                                                  const __half* __restrict__ B,
                                                  float* __restrict__ C,
                                                  int M, int N, int K) {
    extern __shared__ __half sh[];
    const int tid = threadIdx.x, wid = tid >> 5, lane = tid & 31;
    const int g = lane >> 2, tg = lane & 3;
    const int wm = (wid >> 1) * 64, wn = (wid & 1) * 64;
    const int bm = blockIdx.y * 128, bn = blockIdx.x * 128;

    float acc[4][8][4] = {};
    uint32_t sA = smem_u32(sh);

    const int arow = lane & 15;
    const int apar = lane >> 4;
    const int brow = (lane & 7) + ((lane >> 4) << 3);
    const int bpar = (lane >> 3) & 1;

#define V4LOAD(slot, k0)                                                          \
    do {                                                                          \
        uint32_t so = sA + (uint32_t)(slot)*V4_STGB;                              \
        _Pragma("unroll")                                                         \
        for (int i = 0; i < 16; i++) {                                            \
            int id = tid + i * 128;                                               \
            int row = id >> 3, ch = id & 7;                                       \
            const __half* gp = (row < 128)                                        \
                ? A + (size_t)(bm + row) * K + (k0) + ch * 8                      \
                : B + (size_t)(bn + row - 128) * K + (k0) + ch * 8;               \
            asm volatile("cp.async.cg.shared.global [%0], [%1], 16;"              \
                         ::"r"(so + (uint32_t)(row * 128 +                        \
                                               ((ch ^ (row & 7)) * 16))),         \
                           "l"(gp));                                              \
        }                                                                         \
    } while (0)

    const int nk = K >> 6;
    V4LOAD(0, 0);
    asm volatile("cp.async.commit_group;");
    V4LOAD(1, 64);
    asm volatile("cp.async.commit_group;");

    for (int t = 0; t < nk; t++) {
        asm volatile("cp.async.wait_group 1;");
        __syncthreads();
        if (t + 2 < nk) V4LOAD((t + 2) % 3, (t + 2) * 64);
        asm volatile("cp.async.commit_group;");

        uint32_t base = sA + (uint32_t)(t % 3) * V4_STGB;
#pragma unroll
        for (int ks = 0; ks < 4; ks++) {
            uint32_t af[4][4], bt[4][4];
#pragma unroll
            for (int mi = 0; mi < 4; mi++) {
                int row = wm + mi * 16 + arow;
                int ch = 2 * ks + apar;
                ldm_x4(af[mi], base + (uint32_t)(row * 128 + ((ch ^ (row & 7)) * 16)));
            }
#pragma unroll
            for (int nb = 0; nb < 4; nb++) {
                int row = 128 + wn + nb * 16 + brow;
                int ch = 2 * ks + bpar;
                ldm_x4(bt[nb], base + (uint32_t)(row * 128 + ((ch ^ (row & 7)) * 16)));
            }
#pragma unroll
            for (int mi = 0; mi < 4; mi++)
#pragma unroll
                for (int nb = 0; nb < 4; nb++) {
                    mma_fp16(acc[mi][2 * nb], af[mi][0], af[mi][1], af[mi][2],
                             af[mi][3], bt[nb][0], bt[nb][1]);
                    mma_fp16(acc[mi][2 * nb + 1], af[mi][0], af[mi][1], af[mi][2],
                             af[mi][3], bt[nb][2], bt[nb][3]);
                }
        }
    }

#pragma unroll
    for (int mi = 0; mi < 4; mi++)
#pragma unroll
        for (int ni = 0; ni < 8; ni++) {
            int row = bm + wm + mi * 16 + g;
            int col = bn + wn + ni * 8 + tg * 2;
            *(float2*)&C[(size_t)row * N + col] =
                make_float2(acc[mi][ni][0], acc[mi][ni][1]);
            *(float2*)&C[(size_t)(row + 8) * N + col] =
                make_float2(acc[mi][ni][2], acc[mi][ni][3]);
        }
#undef V4LOAD
}

// ---------------- RoPE: fp32 in -> rotated fp16 out ----------------
__global__ void rope_half(const float* __restrict__ X, __half* __restrict__ Y,
                          const float* __restrict__ cosT, const float* __restrict__ sinT,
                          int nheads) {
    int idx = blockIdx.x * blockDim.x + threadIdx.x;
    int total = SEQ * nheads * 64;
    if (idx >= total) return;
    int d = idx & 63;
    int h = (idx >> 6) % nheads;
    int s = idx / (64 * nheads);
    const float* p = X + (size_t)s * nheads * HD + h * HD + d;
    float x1 = p[0], x2 = p[64];
    float c1 = cosT[s * HD + d],      s1 = sinT[s * HD + d];
    float c2 = cosT[s * HD + 64 + d], s2 = sinT[s * HD + 64 + d];
    __half* o = Y + (size_t)s * nheads * HD + h * HD + d;
    o[0]  = __float2half_rn(fmaf(x1, c1, -x2 * s1));
    o[64] = __float2half_rn(fmaf(x2, c2,  x1 * s2));
}

// ---------------- fp16 flash attention v3: double-buffered K/V cp.async -------
// smem: Q[128] + 2 stages of (K[64] | V[64]).  Per-iter ring (gemm_v3 pattern):
// sync (closes compute kb-1, frees slot (kb+1)%2) -> issue KV(kb+1) -> commit
// -> wait_group 1 (kb resident; its load overlapped compute kb-1) -> sync ->
// compute kb.
#define QSTR 136
#define FL4_SMEM ((128 + 2 * 128) * QSTR * 2)

__global__ void __launch_bounds__(256) flash_fp16_v3(const __half* __restrict__ Qg,
                                                     const __half* __restrict__ Kg,
                                                     const __half* __restrict__ Vg,
                                                     __half* __restrict__ Og) {
    extern __shared__ __half sm[];
    __half* Qs = sm;                                  // [128][QSTR]
    // stage s: K rows at  Qs + (128 + s*128)*QSTR,  V rows 64 later
    const uint32_t sQ = smem_u32(Qs);
    const uint32_t sKV0 = sQ + 128 * (QSTR * 2);
    const uint32_t STG = 128 * (QSTR * 2);
    const uint32_t VOFF = 64 * (QSTR * 2);

    const int tid = threadIdx.x, wid = tid >> 5, lane = tid & 31;
    const int g = lane >> 2, tg = lane & 3;
    const int qb = gridDim.x - 1 - blockIdx.x;        // heavy CTAs first
    const int head = blockIdx.y, kvh = head >> 2;
    const __half* Qh = Qg + head * HD;                // row stride HID
    const __half* Kh = Kg + kvh * HD;                 // row stride KVD
    const __half* Vh = Vg + kvh * HD;

    const int nkb = 2 * qb + 2;

    // KV fill for block kb into slot: 64 K-rows + 64 V-rows, 16B chunks
#define KVLOAD(slot, kb)                                                          \
    do {                                                                          \
        uint32_t so = sKV0 + (uint32_t)(slot)*STG;                                \
        _Pragma("unroll")                                                         \
        for (int i = 0; i < 4; i++) {                                             \
            int id = tid + i * 256;                                               \
            int r = id >> 4, ch = id & 15;                                        \
            uint32_t d = (uint32_t)(r * (QSTR * 2) + ch * 16);                    \
            const __half* srck = Kh + (size_t)((kb)*64 + r) * KVD + ch * 8;       \
            const __half* srcv = Vh + (size_t)((kb)*64 + r) * KVD + ch * 8;       \
            asm volatile("cp.async.cg.shared.global [%0], [%1], 16;"              \
                         ::"r"(so + d), "l"(srck));                               \
            asm volatile("cp.async.cg.shared.global [%0], [%1], 16;"              \
                         ::"r"(so + VOFF + d), "l"(srcv));                        \
        }                                                                         \
    } while (0)

    // prologue: Q + KV(0) in group 0
#pragma unroll
    for (int i = 0; i < 8; i++) {
        int id = tid + i * 256;
        int r = id >> 4, ch = id & 15;
        const __half* src = Qh + (size_t)(qb * 128 + r) * HID + ch * 8;
        asm volatile("cp.async.cg.shared.global [%0], [%1], 16;"
                     ::"r"(sQ + (uint32_t)(r * (QSTR * 2) + ch * 16)), "l"(src));
    }
    KVLOAD(0, 0);
    asm volatile("cp.async.commit_group;");

    const int wm = wid * 16;
    const int row0 = qb * 128 + wm + g, row1 = row0 + 8;
    const int rowTop = qb * 128 + wm + 15;
    float m0 = -1e30f, m1 = -1e30f, l0 = 0.f, l1 = 0.f;
    float oacc[16][4];
#pragma unroll
    for (int i = 0; i < 16; i++)
#pragma unroll
        for (int j = 0; j < 4; j++) oacc[i][j] = 0.f;

    const float scale = 0.08838834764831845f;

    const int lrA = wm + (lane & 15), lcA = (lane >> 4) << 3;
    const int lrK = (lane & 7) + ((lane >> 4) << 3), lcK = ((lane >> 3) & 1) << 3;
    const int lrV = (lane & 7) + (((lane >> 3) & 1) << 3), lcV = (lane >> 4) << 3;

    for (int kb = 0; kb < nkb; kb++) {
        __syncthreads();              // all done computing kb-1 -> slot (kb+1)%2 free
        if (kb + 1 < nkb) KVLOAD((kb + 1) & 1, kb + 1);
        asm volatile("cp.async.commit_group;");
        asm volatile("cp.async.wait_group 1;");   // own KV(kb) (+Q) resident
        __syncthreads();                          // all threads' KV(kb) resident

        if (kb * 64 <= rowTop) {
            uint32_t sK = sKV0 + (uint32_t)(kb & 1) * STG;
            uint32_t sV = sK + VOFF;

            float sacc[8][4];
#pragma unroll
            for (int ni = 0; ni < 8; ni++)
#pragma unroll
                for (int j = 0; j < 4; j++) sacc[ni][j] = 0.f;
#pragma unroll
            for (int ks = 0; ks < 8; ks++) {
                int kk = ks * 16;
                uint32_t af[4];
                ldm_x4(af, sQ + (uint32_t)((lrA * QSTR + kk + lcA) * 2));
#pragma unroll
                for (int nb = 0; nb < 4; nb++) {
                    uint32_t bt[4];
                    ldm_x4(bt, sK + (uint32_t)(((nb * 16 + lrK) * QSTR + kk + lcK) * 2));
                    mma_fp16(sacc[2 * nb], af[0], af[1], af[2], af[3], bt[0], bt[1]);
                    mma_fp16(sacc[2 * nb + 1], af[0], af[1], af[2], af[3], bt[2], bt[3]);
                }
            }

#pragma unroll
            for (int ni = 0; ni < 8; ni++) {
                int c0 = kb * 64 + ni * 8 + 2 * tg, c1 = c0 + 1;
                sacc[ni][0] = (c0 <= row0) ? sacc[ni][0] * scale : -1e30f;
                sacc[ni][1] = (c1 <= row0) ? sacc[ni][1] * scale : -1e30f;
                sacc[ni][2] = (c0 <= row1) ? sacc[ni][2] * scale : -1e30f;
                sacc[ni][3] = (c1 <= row1) ? sacc[ni][3] * scale : -1e30f;
            }

            float mx0 = -1e30f, mx1 = -1e30f;
#pragma unroll
            for (int ni = 0; ni < 8; ni++) {
                mx0 = fmaxf(mx0, fmaxf(sacc[ni][0], sacc[ni][1]));
                mx1 = fmaxf(mx1, fmaxf(sacc[ni][2], sacc[ni][3]));
            }
            mx0 = fmaxf(mx0, __shfl_xor_sync(0xffffffffu, mx0, 1));
            mx0 = fmaxf(mx0, __shfl_xor_sync(0xffffffffu, mx0, 2));
            mx1 = fmaxf(mx1, __shfl_xor_sync(0xffffffffu, mx1, 1));
            mx1 = fmaxf(mx1, __shfl_xor_sync(0xffffffffu, mx1, 2));
            float mn0 = fmaxf(m0, mx0), mn1 = fmaxf(m1, mx1);
            float fs0 = __expf(m0 - mn0), fs1 = __expf(m1 - mn1);

            float ps0 = 0.f, ps1 = 0.f;
#pragma unroll
            for (int ni = 0; ni < 8; ni++) {
                float p0 = (sacc[ni][0] > -1e29f) ? __expf(sacc[ni][0] - mn0) : 0.f;
                float p1 = (sacc[ni][1] > -1e29f) ? __expf(sacc[ni][1] - mn0) : 0.f;
                float p2 = (sacc[ni][2] > -1e29f) ? __expf(sacc[ni][2] - mn1) : 0.f;
                float p3 = (sacc[ni][3] > -1e29f) ? __expf(sacc[ni][3] - mn1) : 0.f;
                sacc[ni][0] = p0; sacc[ni][1] = p1; sacc[ni][2] = p2; sacc[ni][3] = p3;
                ps0 += p0 + p1; ps1 += p2 + p3;
            }
            ps0 += __shfl_xor_sync(0xffffffffu, ps0, 1);
            ps0 += __shfl_xor_sync(0xffffffffu, ps0, 2);
            ps1 += __shfl_xor_sync(0xffffffffu, ps1, 1);
            ps1 += __shfl_xor_sync(0xffffffffu, ps1, 2);
            l0 = l0 * fs0 + ps0; l1 = l1 * fs1 + ps1;
            m0 = mn0; m1 = mn1;

#pragma unroll
            for (int nd = 0; nd < 16; nd++) {
                oacc[nd][0] *= fs0; oacc[nd][1] *= fs0;
                oacc[nd][2] *= fs1; oacc[nd][3] *= fs1;
            }

#pragma unroll
            for (int s = 0; s < 4; s++) {
                uint32_t a0 = packh2(sacc[2 * s][0], sacc[2 * s][1]);
                uint32_t a1 = packh2(sacc[2 * s][2], sacc[2 * s][3]);
                uint32_t a2 = packh2(sacc[2 * s + 1][0], sacc[2 * s + 1][1]);
                uint32_t a3 = packh2(sacc[2 * s + 1][2], sacc[2 * s + 1][3]);
                int kk = s * 16;
#pragma unroll
                for (int t8 = 0; t8 < 8; t8++) {
                    uint32_t vt[4];
                    ldm_x4_t(vt, sV + (uint32_t)(((kk + lrV) * QSTR + t8 * 16 + lcV) * 2));
                    mma_fp16(oacc[2 * t8], a0, a1, a2, a3, vt[0], vt[1]);
                    mma_fp16(oacc[2 * t8 + 1], a0, a1, a2, a3, vt[2], vt[3]);
                }
            }
        }
    }

    float li0 = 1.f / l0, li1 = 1.f / l1;
#pragma unroll
    for (int nd = 0; nd < 16; nd++) {
        int col = head * HD + nd * 8 + 2 * tg;
        *(uint32_t*)&Og[(size_t)row0 * HID + col] =
            packh2(oacc[nd][0] * li0, oacc[nd][1] * li0);
        *(uint32_t*)&Og[(size_t)row1 * HID + col] =
            packh2(oacc[nd][2] * li1, oacc[nd][3] * li1);
    }
#undef KVLOAD
}

// ---------------- launch ----------------
extern "C" void kernel_launch(void* const* d_in, const int* in_sizes, int n_in,
                              void* d_out, int out_size) {
    const float* hs   = (const float*)d_in[0];
    const float* wq   = (const float*)d_in[1];
    const float* wk   = (const float*)d_in[2];
    const float* wv   = (const float*)d_in[3];
    const float* wo   = (const float*)d_in[4];
    const float* scq  = (const float*)d_in[5];
    const float* sck  = (const float*)d_in[6];
    const float* scv  = (const float*)d_in[7];
    const float* sco  = (const float*)d_in[8];
    const float* pqkv = (const float*)d_in[9];
    const float* po   = (const float*)d_in[10];
    const float* cosT = (const float*)d_in[11];
    const float* sinT = (const float*)d_in[12];
    float* out = (float*)d_out;

    __half *wmq, *wmk, *wmv, *wmo, *hst, *qh, *kh, *vh, *ao;
    float *q, *k;
    int *ipq, *ipo;
    cudaGetSymbolAddress((void**)&wmq, g_wmq);
    cudaGetSymbolAddress((void**)&wmk, g_wmk);
    cudaGetSymbolAddress((void**)&wmv, g_wmv);
    cudaGetSymbolAddress((void**)&wmo, g_wmo);
    cudaGetSymbolAddress((void**)&hst, g_hst);
    cudaGetSymbolAddress((void**)&q,   g_q);
    cudaGetSymbolAddress((void**)&k,   g_k);
    cudaGetSymbolAddress((void**)&qh,  g_qh);
    cudaGetSymbolAddress((void**)&kh,  g_kh);
    cudaGetSymbolAddress((void**)&vh,  g_vh);
    cudaGetSymbolAddress((void**)&ao,  g_ao);
    cudaGetSymbolAddress((void**)&ipq, g_invp_qkv);
    cudaGetSymbolAddress((void**)&ipo, g_invp_o);

    const int smem64 = GEMM_SMEM_BM(64);
    cudaFuncSetAttribute(gemm_v4, cudaFuncAttributeMaxDynamicSharedMemorySize, V4_SMEM);
    cudaFuncSetAttribute(gemm_v3<64, 128, false>,
                         cudaFuncAttributeMaxDynamicSharedMemorySize, smem64);
    cudaFuncSetAttribute(gemm_v3<64, 128, true>,
                         cudaFuncAttributeMaxDynamicSharedMemorySize, smem64);
    cudaFuncSetAttribute(flash_fp16_v3, cudaFuncAttributeMaxDynamicSharedMemorySize,
                         FL4_SMEM);

    const int mw_smem = HID * 6;      // H floats + H halves

    round_half<<<(SEQ * HID / 8 + 255) / 256, 256>>>(hs, hst, SEQ * HID / 8);        // 1
    perm_extract<<<(HID * HID + 255) / 256, 256>>>(pqkv, ipq, HID);                  // 2
    mask_weights_v2<<<HID, 256, mw_smem>>>(wq, scq, ipq, wmq, HID);                  // 3
    gemm_v4<<<dim3(HID / 128, SEQ / 128), 128, V4_SMEM>>>(hst, wmq, q,               // 4 (profiled)
                                                          SEQ, HID, HID);
    mask_weights_v2<<<KVD, 256, mw_smem>>>(wk, sck, ipq, wmk, HID);
    gemm_v3<64, 128, false><<<dim3(KVD / 128, SEQ / 64), 128, smem64>>>(hst, wmk, k,
                                                                        SEQ, KVD, HID);
    mask_weights_v2<<<KVD, 256, mw_smem>>>(wv, scv, ipq, wmv, HID);
    gemm_v3<64, 128, true><<<dim3(KVD / 128, SEQ / 64), 128, smem64>>>(hst, wmv, vh,
                                                                       SEQ, KVD, HID);
    perm_extract<<<(HID * HID + 255) / 256, 256>>>(po, ipo, HID);
    mask_weights_v2<<<HID, 256, mw_smem>>>(wo, sco, ipo, wmo, HID);

    rope_half<<<(SEQ * NHEADS * 64 + 255) / 256, 256>>>(q, qh, cosT, sinT, NHEADS);
    rope_half<<<(SEQ * NKVH * 64 + 255) / 256, 256>>>(k, kh, cosT, sinT, NKVH);

    flash_fp16_v3<<<dim3(SEQ / 128, NHEADS), 256, FL4_SMEM>>>(qh, kh, vh, ao);

    gemm_v4<<<dim3(HID / 128, SEQ / 128), 128, V4_SMEM>>>(ao, wmo, out,
                                                          SEQ, HID, HID);
}

// round 12
// speedup vs baseline: 9.1438x; 1.1631x over previous
#include <cuda_runtime.h>
#include <cuda_fp16.h>
#include <cstdint>

#define HID 4096
#define KVD 1024
#define SEQ 2048
#define NHEADS 32
#define NKVH 8
#define HD 128

// ---------------- scratch ----------------
__device__ __half g_wmq[HID * HID];
__device__ __half g_wmo[HID * HID];
__device__ __half g_wmk[KVD * HID];
__device__ __half g_wmv[KVD * HID];
__device__ __half g_hst[SEQ * HID];
__device__ float  g_q[SEQ * HID];
__device__ float  g_k[SEQ * KVD];
__device__ __half g_qh[SEQ * HID];
__device__ __half g_kh[SEQ * KVD];
__device__ __half g_vh[SEQ * KVD];
__device__ __half g_ao[SEQ * HID];
__device__ int    g_invp_qkv[HID];
__device__ int    g_invp_o[HID];

__device__ __forceinline__ uint32_t smem_u32(const void* p) {
    return (uint32_t)__cvta_generic_to_shared((void*)p);
}
__device__ __forceinline__ uint32_t packh2(float x, float y) {
    __half2 h = __floats2half2_rn(x, y);
    return *(uint32_t*)&h;
}
__device__ __forceinline__ void ldm_x4(uint32_t (&r)[4], uint32_t addr) {
    asm volatile("ldmatrix.sync.aligned.m8n8.x4.shared.b16 {%0,%1,%2,%3}, [%4];"
                 : "=r"(r[0]), "=r"(r[1]), "=r"(r[2]), "=r"(r[3]) : "r"(addr));
}
__device__ __forceinline__ void ldm_x4_t(uint32_t (&r)[4], uint32_t addr) {
    asm volatile("ldmatrix.sync.aligned.m8n8.x4.trans.shared.b16 {%0,%1,%2,%3}, [%4];"
                 : "=r"(r[0]), "=r"(r[1]), "=r"(r[2]), "=r"(r[3]) : "r"(addr));
}
__device__ __forceinline__ void mma_fp16(float c[4], uint32_t a0, uint32_t a1,
                                         uint32_t a2, uint32_t a3,
                                         uint32_t b0, uint32_t b1) {
    asm volatile(
        "mma.sync.aligned.m16n8k16.row.col.f32.f16.f16.f32 "
        "{%0,%1,%2,%3}, {%4,%5,%6,%7}, {%8,%9}, {%0,%1,%2,%3};"
        : "+f"(c[0]), "+f"(c[1]), "+f"(c[2]), "+f"(c[3])
        : "r"(a0), "r"(a1), "r"(a2), "r"(a3), "r"(b0), "r"(b1));
}

// ---------------- permutation extraction ----------------
__global__ void perm_extract(const float* __restrict__ P, int* __restrict__ invp, int n) {
    int idx = blockIdx.x * blockDim.x + threadIdx.x;
    if (idx >= n * n) return;
    if (P[idx] > 0.5f) invp[idx % n] = idx / n;
}

// ---------------- hidden states: fp32 -> fp16 ----------------
__global__ void round_half(const float* __restrict__ X, __half* __restrict__ Y, int n8) {
    int i = blockIdx.x * blockDim.x + threadIdx.x;
    if (i >= n8) return;
    const float4* p = (const float4*)(X + (size_t)i * 8);
    float4 a = p[0], b = p[1];
    uint4 o;
    o.x = packh2(a.x, a.y); o.y = packh2(a.z, a.w);
    o.z = packh2(b.x, b.y); o.w = packh2(b.z, b.w);
    *(uint4*)(Y + (size_t)i * 8) = o;
}

// ---------------- 2:4 hard mask v2: block-per-row, smem staged ----------------
__global__ void __launch_bounds__(256) mask_weights_v2(const float* __restrict__ W,
                                                       const float* __restrict__ scaler,
                                                       const int* __restrict__ invp,
                                                       __half* __restrict__ Wm, int H) {
    extern __shared__ float smr[];            // [H] floats, then [H] halves
    __half* smo = (__half*)(smr + H);
    const int r = blockIdx.x;
    const float* Wr = W + (size_t)r * H;
    for (int i = threadIdx.x; i < H / 4; i += 256)
        ((float4*)smr)[i] = ((const float4*)Wr)[i];
    __syncthreads();
    const int G = H >> 2;
    for (int g = threadIdx.x; g < G; g += 256) {
        int4 c = ((const int4*)invp)[g];
        float w0 = smr[c.x], w1 = smr[c.y], w2 = smr[c.z], w3 = smr[c.w];
        float m0 = fabsf(w0) * sqrtf(__ldg(scaler + c.x));
        float m1 = fabsf(w1) * sqrtf(__ldg(scaler + c.y));
        float m2 = fabsf(w2) * sqrtf(__ldg(scaler + c.z));
        float m3 = fabsf(w3) * sqrtf(__ldg(scaler + c.w));
        int r0 = (m1 > m0) + (m2 > m0) + (m3 > m0);
        int r1 = (m0 >= m1) + (m2 > m1) + (m3 > m1);
        int r2 = (m0 >= m2) + (m1 >= m2) + (m3 > m2);
        int r3 = (m0 >= m3) + (m1 >= m3) + (m2 >= m3);
        smo[c.x] = __float2half_rn(r0 < 2 ? w0 : 0.f);
        smo[c.y] = __float2half_rn(r1 < 2 ? w1 : 0.f);
        smo[c.z] = __float2half_rn(r2 < 2 ? w2 : 0.f);
        smo[c.w] = __float2half_rn(r3 < 2 ? w3 : 0.f);
    }
    __syncthreads();
    __half* Wo = Wm + (size_t)r * H;
    for (int i = threadIdx.x; i < H / 8; i += 256)
        ((uint4*)Wo)[i] = ((const uint4*)smo)[i];
}

// ---------------- fp16 NT GEMM v3: 3-slot/2-ahead, BK=64 (K/V projections) ----
#define GSH 72
#define GEMM_SMEM_BM(BM) (3 * ((BM) + 128) * GSH * 2)

template <int BM, int NTHR, bool HOUT>
__global__ void __launch_bounds__(NTHR, 2) gemm_v3(const __half* __restrict__ A,
                                                   const __half* __restrict__ B,
                                                   void* __restrict__ Cv,
                                                   int M, int N, int K) {
    extern __shared__ __half sh[];
    constexpr int STGH = (BM + 128) * GSH;
    constexpr uint32_t STGB = STGH * 2;
    constexpr uint32_t ABYTES = BM * GSH * 2;
    constexpr int AIT = BM * 8 / NTHR;
    constexpr int BIT = 128 * 8 / NTHR;

    const int tid = threadIdx.x, wid = tid >> 5, lane = tid & 31;
    const int g = lane >> 2, tg = lane & 3;
    const int wm = (wid >> 2) * 64, wn = (wid & 3) * 32;
    const int bm = blockIdx.y * BM, bn = blockIdx.x * 128;

    float acc[4][4][4] = {};
    uint32_t sA = smem_u32(sh);

    const uint32_t aoff = (uint32_t)((wm + (lane & 15)) * (GSH * 2) + (((lane >> 4) << 3) << 1));
    const uint32_t boff = ABYTES +
        (uint32_t)((wn + (lane & 7) + ((lane >> 4) << 3)) * (GSH * 2) +
                   ((((lane >> 3) & 1) << 3) << 1));

#define LOADSTAGE(slot, k0)                                                       \
    do {                                                                          \
        uint32_t so = sA + (uint32_t)(slot)*STGB;                                 \
        _Pragma("unroll")                                                         \
        for (int i = 0; i < AIT; i++) {                                           \
            int id = tid + i * NTHR;                                              \
            int row = id >> 3, ch = id & 7;                                       \
            const __half* pa = A + (size_t)(bm + row) * K + (k0) + ch * 8;        \
            asm volatile("cp.async.cg.shared.global [%0], [%1], 16;"              \
                         ::"r"(so + (uint32_t)((row * 9 + ch) * 16)), "l"(pa));   \
        }                                                                         \
        _Pragma("unroll")                                                         \
        for (int i = 0; i < BIT; i++) {                                           \
            int id = tid + i * NTHR;                                              \
            int row = id >> 3, ch = id & 7;                                       \
            const __half* pb = B + (size_t)(bn + row) * K + (k0) + ch * 8;        \
            asm volatile("cp.async.cg.shared.global [%0], [%1], 16;"              \
                         ::"r"(so + ABYTES + (uint32_t)((row * 9 + ch) * 16)),    \
                           "l"(pb));                                              \
        }                                                                         \
    } while (0)

    const int nk = K >> 6;
    LOADSTAGE(0, 0);
    asm volatile("cp.async.commit_group;");
    LOADSTAGE(1, 64);
    asm volatile("cp.async.commit_group;");

    for (int t = 0; t < nk; t++) {
        asm volatile("cp.async.wait_group 1;");
        __syncthreads();
        if (t + 2 < nk) LOADSTAGE((t + 2) % 3, (t + 2) * 64);
        asm volatile("cp.async.commit_group;");

        uint32_t base = sA + (uint32_t)(t % 3) * STGB;
#pragma unroll
        for (int ks = 0; ks < 4; ks++) {
            uint32_t kadd = (uint32_t)(ks * 32);
            uint32_t bt[2][4];
            ldm_x4(bt[0], base + boff + kadd);
            ldm_x4(bt[1], base + boff + kadd + 16 * (GSH * 2));
#pragma unroll
            for (int mi = 0; mi < 4; mi++) {
                uint32_t af[4];
                ldm_x4(af, base + aoff + kadd + (uint32_t)(mi * 16 * (GSH * 2)));
#pragma unroll
                for (int nb = 0; nb < 2; nb++) {
                    mma_fp16(acc[mi][2 * nb], af[0], af[1], af[2], af[3],
                             bt[nb][0], bt[nb][1]);
                    mma_fp16(acc[mi][2 * nb + 1], af[0], af[1], af[2], af[3],
                             bt[nb][2], bt[nb][3]);
                }
            }
        }
    }

#pragma unroll
    for (int mi = 0; mi < 4; mi++)
#pragma unroll
        for (int ni = 0; ni < 4; ni++) {
            int row = bm + wm + mi * 16 + g;
            int col = bn + wn + ni * 8 + tg * 2;
            if constexpr (HOUT) {
                __half* Ch = (__half*)Cv;
                *(uint32_t*)&Ch[(size_t)row * N + col] =
                    packh2(acc[mi][ni][0], acc[mi][ni][1]);
                *(uint32_t*)&Ch[(size_t)(row + 8) * N + col] =
                    packh2(acc[mi][ni][2], acc[mi][ni][3]);
            } else {
                float* Cf = (float*)Cv;
                *(float2*)&Cf[(size_t)row * N + col] =
                    make_float2(acc[mi][ni][0], acc[mi][ni][1]);
                *(float2*)&Cf[(size_t)(row + 8) * N + col] =
                    make_float2(acc[mi][ni][2], acc[mi][ni][3]);
            }
        }
#undef LOADSTAGE
}

// ---------------- fp16 NT GEMM v4: 128x128 CTA, 4 warps, 64x64 warptile -------
#define V4_STGB 32768u
#define V4_SMEM (3 * 32768)

__global__ void __launch_bounds__(128, 2) gemm_v4(const __half* __restrict__ A,
                                                  const __half* __restrict__ B,
                                                  float* __restrict__ C,
                                                  int M, int N, int K) {
    extern __shared__ __half sh[];
    const int tid = threadIdx.x, wid = tid >> 5, lane = tid & 31;
    const int g = lane >> 2, tg = lane & 3;
    const int wm = (wid >> 1) * 64, wn = (wid & 1) * 64;
    const int bm = blockIdx.y * 128, bn = blockIdx.x * 128;

    float acc[4][8][4] = {};
    uint32_t sA = smem_u32(sh);

    const int arow = lane & 15;
    const int apar = lane >> 4;
    const int brow = (lane & 7) + ((lane >> 4) << 3);
    const int bpar = (lane >> 3) & 1;

#define V4LOAD(slot, k0)                                                          \
    do {                                                                          \
        uint32_t so = sA + (uint32_t)(slot)*V4_STGB;                              \
        _Pragma("unroll")                                                         \
        for (int i = 0; i < 16; i++) {                                            \
            int id = tid + i * 128;                                               \
            int row = id >> 3, ch = id & 7;                                       \
            const __half* gp = (row < 128)                                        \
                ? A + (size_t)(bm + row) * K + (k0) + ch * 8                      \
                : B + (size_t)(bn + row - 128) * K + (k0) + ch * 8;               \
            asm volatile("cp.async.cg.shared.global [%0], [%1], 16;"              \
                         ::"r"(so + (uint32_t)(row * 128 +                        \
                                               ((ch ^ (row & 7)) * 16))),         \
                           "l"(gp));                                              \
        }                                                                         \
    } while (0)

    const int nk = K >> 6;
    V4LOAD(0, 0);
    asm volatile("cp.async.commit_group;");
    V4LOAD(1, 64);
    asm volatile("cp.async.commit_group;");

    for (int t = 0; t < nk; t++) {
        asm volatile("cp.async.wait_group 1;");
        __syncthreads();
        if (t + 2 < nk) V4LOAD((t + 2) % 3, (t + 2) * 64);
        asm volatile("cp.async.commit_group;");

        uint32_t base = sA + (uint32_t)(t % 3) * V4_STGB;
#pragma unroll
        for (int ks = 0; ks < 4; ks++) {
            uint32_t af[4][4], bt[4][4];
#pragma unroll
            for (int mi = 0; mi < 4; mi++) {
                int row = wm + mi * 16 + arow;
                int ch = 2 * ks + apar;
                ldm_x4(af[mi], base + (uint32_t)(row * 128 + ((ch ^ (row & 7)) * 16)));
            }
#pragma unroll
            for (int nb = 0; nb < 4; nb++) {
                int row = 128 + wn + nb * 16 + brow;
                int ch = 2 * ks + bpar;
                ldm_x4(bt[nb], base + (uint32_t)(row * 128 + ((ch ^ (row & 7)) * 16)));
            }
#pragma unroll
            for (int mi = 0; mi < 4; mi++)
#pragma unroll
                for (int nb = 0; nb < 4; nb++) {
                    mma_fp16(acc[mi][2 * nb], af[mi][0], af[mi][1], af[mi][2],
                             af[mi][3], bt[nb][0], bt[nb][1]);
                    mma_fp16(acc[mi][2 * nb + 1], af[mi][0], af[mi][1], af[mi][2],
                             af[mi][3], bt[nb][2], bt[nb][3]);
                }
        }
    }

#pragma unroll
    for (int mi = 0; mi < 4; mi++)
#pragma unroll
        for (int ni = 0; ni < 8; ni++) {
            int row = bm + wm + mi * 16 + g;
            int col = bn + wn + ni * 8 + tg * 2;
            *(float2*)&C[(size_t)row * N + col] =
                make_float2(acc[mi][ni][0], acc[mi][ni][1]);
            *(float2*)&C[(size_t)(row + 8) * N + col] =
                make_float2(acc[mi][ni][2], acc[mi][ni][3]);
        }
#undef V4LOAD
}

// ---------------- RoPE: fp32 in -> rotated fp16 out ----------------
__global__ void rope_half(const float* __restrict__ X, __half* __restrict__ Y,
                          const float* __restrict__ cosT, const float* __restrict__ sinT,
                          int nheads) {
    int idx = blockIdx.x * blockDim.x + threadIdx.x;
    int total = SEQ * nheads * 64;
    if (idx >= total) return;
    int d = idx & 63;
    int h = (idx >> 6) % nheads;
    int s = idx / (64 * nheads);
    const float* p = X + (size_t)s * nheads * HD + h * HD + d;
    float x1 = p[0], x2 = p[64];
    float c1 = cosT[s * HD + d],      s1 = sinT[s * HD + d];
    float c2 = cosT[s * HD + 64 + d], s2 = sinT[s * HD + 64 + d];
    __half* o = Y + (size_t)s * nheads * HD + h * HD + d;
    o[0]  = __float2half_rn(fmaf(x1, c1, -x2 * s1));
    o[64] = __float2half_rn(fmaf(x2, c2,  x1 * s2));
}

// ---------------- fp16 flash attention v3: double-buffered K/V cp.async -------
#define QSTR 136
#define FL4_SMEM ((128 + 2 * 128) * QSTR * 2)

__global__ void __launch_bounds__(256) flash_fp16_v3(const __half* __restrict__ Qg,
                                                     const __half* __restrict__ Kg,
                                                     const __half* __restrict__ Vg,
                                                     __half* __restrict__ Og) {
    extern __shared__ __half sm[];
    __half* Qs = sm;
    const uint32_t sQ = smem_u32(Qs);
    const uint32_t sKV0 = sQ + 128 * (QSTR * 2);
    const uint32_t STG = 128 * (QSTR * 2);
    const uint32_t VOFF = 64 * (QSTR * 2);

    const int tid = threadIdx.x, wid = tid >> 5, lane = tid & 31;
    const int g = lane >> 2, tg = lane & 3;
    const int qb = gridDim.x - 1 - blockIdx.x;
    const int head = blockIdx.y, kvh = head >> 2;
    const __half* Qh = Qg + head * HD;
    const __half* Kh = Kg + kvh * HD;
    const __half* Vh = Vg + kvh * HD;

    const int nkb = 2 * qb + 2;

#define KVLOAD(slot, kb)                                                          \
    do {                                                                          \
        uint32_t so = sKV0 + (uint32_t)(slot)*STG;                                \
        _Pragma("unroll")                                                         \
        for (int i = 0; i < 4; i++) {                                             \
            int id = tid + i * 256;                                               \
            int r = id >> 4, ch = id & 15;                                        \
            uint32_t d = (uint32_t)(r * (QSTR * 2) + ch * 16);                    \
            const __half* srck = Kh + (size_t)((kb)*64 + r) * KVD + ch * 8;       \
            const __half* srcv = Vh + (size_t)((kb)*64 + r) * KVD + ch * 8;       \
            asm volatile("cp.async.cg.shared.global [%0], [%1], 16;"              \
                         ::"r"(so + d), "l"(srck));                               \
            asm volatile("cp.async.cg.shared.global [%0], [%1], 16;"              \
                         ::"r"(so + VOFF + d), "l"(srcv));                        \
        }                                                                         \
    } while (0)

#pragma unroll
    for (int i = 0; i < 8; i++) {
        int id = tid + i * 256;
        int r = id >> 4, ch = id & 15;
        const __half* src = Qh + (size_t)(qb * 128 + r) * HID + ch * 8;
        asm volatile("cp.async.cg.shared.global [%0], [%1], 16;"
                     ::"r"(sQ + (uint32_t)(r * (QSTR * 2) + ch * 16)), "l"(src));
    }
    KVLOAD(0, 0);
    asm volatile("cp.async.commit_group;");

    const int wm = wid * 16;
    const int row0 = qb * 128 + wm + g, row1 = row0 + 8;
    const int rowTop = qb * 128 + wm + 15;
    float m0 = -1e30f, m1 = -1e30f, l0 = 0.f, l1 = 0.f;
    float oacc[16][4];
#pragma unroll
    for (int i = 0; i < 16; i++)
#pragma unroll
        for (int j = 0; j < 4; j++) oacc[i][j] = 0.f;

    const float scale = 0.08838834764831845f;

    const int lrA = wm + (lane & 15), lcA = (lane >> 4) << 3;
    const int lrK = (lane & 7) + ((lane >> 4) << 3), lcK = ((lane >> 3) & 1) << 3;
    const int lrV = (lane & 7) + (((lane >> 3) & 1) << 3), lcV = (lane >> 4) << 3;

    for (int kb = 0; kb < nkb; kb++) {
        __syncthreads();
        if (kb + 1 < nkb) KVLOAD((kb + 1) & 1, kb + 1);
        asm volatile("cp.async.commit_group;");
        asm volatile("cp.async.wait_group 1;");
        __syncthreads();

        if (kb * 64 <= rowTop) {
            uint32_t sK = sKV0 + (uint32_t)(kb & 1) * STG;
            uint32_t sV = sK + VOFF;

            float sacc[8][4];
#pragma unroll
            for (int ni = 0; ni < 8; ni++)
#pragma unroll
                for (int j = 0; j < 4; j++) sacc[ni][j] = 0.f;
#pragma unroll
            for (int ks = 0; ks < 8; ks++) {
                int kk = ks * 16;
                uint32_t af[4];
                ldm_x4(af, sQ + (uint32_t)((lrA * QSTR + kk + lcA) * 2));
#pragma unroll
                for (int nb = 0; nb < 4; nb++) {
                    uint32_t bt[4];
                    ldm_x4(bt, sK + (uint32_t)(((nb * 16 + lrK) * QSTR + kk + lcK) * 2));
                    mma_fp16(sacc[2 * nb], af[0], af[1], af[2], af[3], bt[0], bt[1]);
                    mma_fp16(sacc[2 * nb + 1], af[0], af[1], af[2], af[3], bt[2], bt[3]);
                }
            }

#pragma unroll
            for (int ni = 0; ni < 8; ni++) {
                int c0 = kb * 64 + ni * 8 + 2 * tg, c1 = c0 + 1;
                sacc[ni][0] = (c0 <= row0) ? sacc[ni][0] * scale : -1e30f;
                sacc[ni][1] = (c1 <= row0) ? sacc[ni][1] * scale : -1e30f;
                sacc[ni][2] = (c0 <= row1) ? sacc[ni][2] * scale : -1e30f;
                sacc[ni][3] = (c1 <= row1) ? sacc[ni][3] * scale : -1e30f;
            }

            float mx0 = -1e30f, mx1 = -1e30f;
#pragma unroll
            for (int ni = 0; ni < 8; ni++) {
                mx0 = fmaxf(mx0, fmaxf(sacc[ni][0], sacc[ni][1]));
                mx1 = fmaxf(mx1, fmaxf(sacc[ni][2], sacc[ni][3]));
            }
            mx0 = fmaxf(mx0, __shfl_xor_sync(0xffffffffu, mx0, 1));
            mx0 = fmaxf(mx0, __shfl_xor_sync(0xffffffffu, mx0, 2));
            mx1 = fmaxf(mx1, __shfl_xor_sync(0xffffffffu, mx1, 1));
            mx1 = fmaxf(mx1, __shfl_xor_sync(0xffffffffu, mx1, 2));
            float mn0 = fmaxf(m0, mx0), mn1 = fmaxf(m1, mx1);
            float fs0 = __expf(m0 - mn0), fs1 = __expf(m1 - mn1);

            float ps0 = 0.f, ps1 = 0.f;
#pragma unroll
            for (int ni = 0; ni < 8; ni++) {
                float p0 = (sacc[ni][0] > -1e29f) ? __expf(sacc[ni][0] - mn0) : 0.f;
                float p1 = (sacc[ni][1] > -1e29f) ? __expf(sacc[ni][1] - mn0) : 0.f;
                float p2 = (sacc[ni][2] > -1e29f) ? __expf(sacc[ni][2] - mn1) : 0.f;
                float p3 = (sacc[ni][3] > -1e29f) ? __expf(sacc[ni][3] - mn1) : 0.f;
                sacc[ni][0] = p0; sacc[ni][1] = p1; sacc[ni][2] = p2; sacc[ni][3] = p3;
                ps0 += p0 + p1; ps1 += p2 + p3;
            }
            ps0 += __shfl_xor_sync(0xffffffffu, ps0, 1);
            ps0 += __shfl_xor_sync(0xffffffffu, ps0, 2);
            ps1 += __shfl_xor_sync(0xffffffffu, ps1, 1);
            ps1 += __shfl_xor_sync(0xffffffffu, ps1, 2);
            l0 = l0 * fs0 + ps0; l1 = l1 * fs1 + ps1;
            m0 = mn0; m1 = mn1;

#pragma unroll
            for (int nd = 0; nd < 16; nd++) {
                oacc[nd][0] *= fs0; oacc[nd][1] *= fs0;
                oacc[nd][2] *= fs1; oacc[nd][3] *= fs1;
            }

#pragma unroll
            for (int s = 0; s < 4; s++) {
                uint32_t a0 = packh2(sacc[2 * s][0], sacc[2 * s][1]);
                uint32_t a1 = packh2(sacc[2 * s][2], sacc[2 * s][3]);
                uint32_t a2 = packh2(sacc[2 * s + 1][0], sacc[2 * s + 1][1]);
                uint32_t a3 = packh2(sacc[2 * s + 1][2], sacc[2 * s + 1][3]);
                int kk = s * 16;
#pragma unroll
                for (int t8 = 0; t8 < 8; t8++) {
                    uint32_t vt[4];
                    ldm_x4_t(vt, sV + (uint32_t)(((kk + lrV) * QSTR + t8 * 16 + lcV) * 2));
                    mma_fp16(oacc[2 * t8], a0, a1, a2, a3, vt[0], vt[1]);
                    mma_fp16(oacc[2 * t8 + 1], a0, a1, a2, a3, vt[2], vt[3]);
                }
            }
        }
    }

    float li0 = 1.f / l0, li1 = 1.f / l1;
#pragma unroll
    for (int nd = 0; nd < 16; nd++) {
        int col = head * HD + nd * 8 + 2 * tg;
        *(uint32_t*)&Og[(size_t)row0 * HID + col] =
            packh2(oacc[nd][0] * li0, oacc[nd][1] * li0);
        *(uint32_t*)&Og[(size_t)row1 * HID + col] =
            packh2(oacc[nd][2] * li1, oacc[nd][3] * li1);
    }
#undef KVLOAD
}

// ---------------- launch: forked-stream graph ----------------
extern "C" void kernel_launch(void* const* d_in, const int* in_sizes, int n_in,
                              void* d_out, int out_size) {
    const float* hs   = (const float*)d_in[0];
    const float* wq   = (const float*)d_in[1];
    const float* wk   = (const float*)d_in[2];
    const float* wv   = (const float*)d_in[3];
    const float* wo   = (const float*)d_in[4];
    const float* scq  = (const float*)d_in[5];
    const float* sck  = (const float*)d_in[6];
    const float* scv  = (const float*)d_in[7];
    const float* sco  = (const float*)d_in[8];
    const float* pqkv = (const float*)d_in[9];
    const float* po   = (const float*)d_in[10];
    const float* cosT = (const float*)d_in[11];
    const float* sinT = (const float*)d_in[12];
    float* out = (float*)d_out;

    __half *wmq, *wmk, *wmv, *wmo, *hst, *qh, *kh, *vh, *ao;
    float *q, *k;
    int *ipq, *ipo;
    cudaGetSymbolAddress((void**)&wmq, g_wmq);
    cudaGetSymbolAddress((void**)&wmk, g_wmk);
    cudaGetSymbolAddress((void**)&wmv, g_wmv);
    cudaGetSymbolAddress((void**)&wmo, g_wmo);
    cudaGetSymbolAddress((void**)&hst, g_hst);
    cudaGetSymbolAddress((void**)&q,   g_q);
    cudaGetSymbolAddress((void**)&k,   g_k);
    cudaGetSymbolAddress((void**)&qh,  g_qh);
    cudaGetSymbolAddress((void**)&kh,  g_kh);
    cudaGetSymbolAddress((void**)&vh,  g_vh);
    cudaGetSymbolAddress((void**)&ao,  g_ao);
    cudaGetSymbolAddress((void**)&ipq, g_invp_qkv);
    cudaGetSymbolAddress((void**)&ipo, g_invp_o);

    const int smem64 = GEMM_SMEM_BM(64);
    cudaFuncSetAttribute(gemm_v4, cudaFuncAttributeMaxDynamicSharedMemorySize, V4_SMEM);
    cudaFuncSetAttribute(gemm_v3<64, 128, false>,
                         cudaFuncAttributeMaxDynamicSharedMemorySize, smem64);
    cudaFuncSetAttribute(gemm_v3<64, 128, true>,
                         cudaFuncAttributeMaxDynamicSharedMemorySize, smem64);
    cudaFuncSetAttribute(flash_fp16_v3, cudaFuncAttributeMaxDynamicSharedMemorySize,
                         FL4_SMEM);

    const int mw_smem = HID * 6;      // H floats + H halves

    cudaStream_t s2, s3, s4;
    cudaStreamCreateWithFlags(&s2, cudaStreamNonBlocking);
    cudaStreamCreateWithFlags(&s3, cudaStreamNonBlocking);
    cudaStreamCreateWithFlags(&s4, cudaStreamNonBlocking);
    cudaEvent_t ev0, ev_ipq, ev_k, ev_v, ev_wo;
    cudaEventCreateWithFlags(&ev0,    cudaEventDisableTiming);
    cudaEventCreateWithFlags(&ev_ipq, cudaEventDisableTiming);
    cudaEventCreateWithFlags(&ev_k,   cudaEventDisableTiming);
    cudaEventCreateWithFlags(&ev_v,   cudaEventDisableTiming);
    cudaEventCreateWithFlags(&ev_wo,  cudaEventDisableTiming);

    // ---- main chain: Q path (launches 1-4 so ncu profiles gemm_v4) ----
    round_half<<<(SEQ * HID / 8 + 255) / 256, 256>>>(hs, hst, SEQ * HID / 8);        // 1
    perm_extract<<<(HID * HID + 255) / 256, 256>>>(pqkv, ipq, HID);                  // 2
    cudaEventRecord(ev_ipq, 0);
    mask_weights_v2<<<HID, 256, mw_smem>>>(wq, scq, ipq, wmq, HID);                  // 3
    cudaEventRecord(ev0, 0);
    gemm_v4<<<dim3(HID / 128, SEQ / 128), 128, V4_SMEM>>>(hst, wmq, q,               // 4 (profiled)
                                                          SEQ, HID, HID);

    // ---- branch s2: K path (mask -> gemm -> rope), overlaps Q gemm ----
    cudaStreamWaitEvent(s2, ev_ipq, 0);
    mask_weights_v2<<<KVD, 256, mw_smem, s2>>>(wk, sck, ipq, wmk, HID);
    gemm_v3<64, 128, false><<<dim3(KVD / 128, SEQ / 64), 128, smem64, s2>>>(
        hst, wmk, k, SEQ, KVD, HID);
    rope_half<<<(SEQ * NKVH * 64 + 255) / 256, 256, 0, s2>>>(k, kh, cosT, sinT, NKVH);
    cudaEventRecord(ev_k, s2);

    // ---- branch s3: V path ----
    cudaStreamWaitEvent(s3, ev_ipq, 0);
    mask_weights_v2<<<KVD, 256, mw_smem, s3>>>(wv, scv, ipq, wmv, HID);
    gemm_v3<64, 128, true><<<dim3(KVD / 128, SEQ / 64), 128, smem64, s3>>>(
        hst, wmv, vh, SEQ, KVD, HID);
    cudaEventRecord(ev_v, s3);

    // ---- branch s4: O-weight path (fully hidden under Q gemm + flash) ----
    cudaStreamWaitEvent(s4, ev0, 0);
    perm_extract<<<(HID * HID + 255) / 256, 256, 0, s4>>>(po, ipo, HID);
    mask_weights_v2<<<HID, 256, mw_smem, s4>>>(wo, sco, ipo, wmo, HID);
    cudaEventRecord(ev_wo, s4);

    // ---- main: rope_q, join K/V, flash, join WO, O gemm ----
    rope_half<<<(SEQ * NHEADS * 64 + 255) / 256, 256>>>(q, qh, cosT, sinT, NHEADS);
    cudaStreamWaitEvent(0, ev_k, 0);
    cudaStreamWaitEvent(0, ev_v, 0);
    flash_fp16_v3<<<dim3(SEQ / 128, NHEADS), 256, FL4_SMEM>>>(qh, kh, vh, ao);
    cudaStreamWaitEvent(0, ev_wo, 0);
    gemm_v4<<<dim3(HID / 128, SEQ / 128), 128, V4_SMEM>>>(ao, wmo, out,
                                                          SEQ, HID, HID);

    cudaEventDestroy(ev0);
    cudaEventDestroy(ev_ipq);
    cudaEventDestroy(ev_k);
    cudaEventDestroy(ev_v);
    cudaEventDestroy(ev_wo);
    cudaStreamDestroy(s2);
    cudaStreamDestroy(s3);
    cudaStreamDestroy(s4);
}

// round 15
// speedup vs baseline: 9.1680x; 1.0026x over previous
#include <cuda_runtime.h>
#include <cuda_fp16.h>
#include <cstdint>

#define HID 4096
#define KVD 1024
#define SEQ 2048
#define NHEADS 32
#define NKVH 8
#define HD 128

// ---------------- scratch ----------------
__device__ __half g_wmq[HID * HID];
__device__ __half g_wmo[HID * HID];
__device__ __half g_wmk[KVD * HID];
__device__ __half g_wmv[KVD * HID];
__device__ __half g_hst[SEQ * HID];
__device__ float  g_q[SEQ * HID];
__device__ float  g_k[SEQ * KVD];
__device__ __half g_qh[SEQ * HID];
__device__ __half g_kh[SEQ * KVD];
__device__ __half g_vh[SEQ * KVD];
__device__ __half g_ao[SEQ * HID];
__device__ int    g_invp_qkv[HID];
__device__ int    g_invp_o[HID];

__device__ __forceinline__ uint32_t smem_u32(const void* p) {
    return (uint32_t)__cvta_generic_to_shared((void*)p);
}
__device__ __forceinline__ uint32_t packh2(float x, float y) {
    __half2 h = __floats2half2_rn(x, y);
    return *(uint32_t*)&h;
}
__device__ __forceinline__ void ldm_x4(uint32_t (&r)[4], uint32_t addr) {
    asm volatile("ldmatrix.sync.aligned.m8n8.x4.shared.b16 {%0,%1,%2,%3}, [%4];"
                 : "=r"(r[0]), "=r"(r[1]), "=r"(r[2]), "=r"(r[3]) : "r"(addr));
}
__device__ __forceinline__ void ldm_x4_t(uint32_t (&r)[4], uint32_t addr) {
    asm volatile("ldmatrix.sync.aligned.m8n8.x4.trans.shared.b16 {%0,%1,%2,%3}, [%4];"
                 : "=r"(r[0]), "=r"(r[1]), "=r"(r[2]), "=r"(r[3]) : "r"(addr));
}
__device__ __forceinline__ void mma_fp16(float c[4], uint32_t a0, uint32_t a1,
                                         uint32_t a2, uint32_t a3,
                                         uint32_t b0, uint32_t b1) {
    asm volatile(
        "mma.sync.aligned.m16n8k16.row.col.f32.f16.f16.f32 "
        "{%0,%1,%2,%3}, {%4,%5,%6,%7}, {%8,%9}, {%0,%1,%2,%3};"
        : "+f"(c[0]), "+f"(c[1]), "+f"(c[2]), "+f"(c[3])
        : "r"(a0), "r"(a1), "r"(a2), "r"(a3), "r"(b0), "r"(b1));
}

// ---------------- permutation extraction ----------------
__global__ void perm_extract(const float* __restrict__ P, int* __restrict__ invp, int n) {
    int idx = blockIdx.x * blockDim.x + threadIdx.x;
    if (idx >= n * n) return;
    if (P[idx] > 0.5f) invp[idx % n] = idx / n;
}

// ---------------- hidden states: fp32 -> fp16 ----------------
__global__ void round_half(const float* __restrict__ X, __half* __restrict__ Y, int n8) {
    int i = blockIdx.x * blockDim.x + threadIdx.x;
    if (i >= n8) return;
    const float4* p = (const float4*)(X + (size_t)i * 8);
    float4 a = p[0], b = p[1];
    uint4 o;
    o.x = packh2(a.x, a.y); o.y = packh2(a.z, a.w);
    o.z = packh2(b.x, b.y); o.w = packh2(b.z, b.w);
    *(uint4*)(Y + (size_t)i * 8) = o;
}

// ---------------- 2:4 hard mask v2: block-per-row, smem staged ----------------
__global__ void __launch_bounds__(256) mask_weights_v2(const float* __restrict__ W,
                                                       const float* __restrict__ scaler,
                                                       const int* __restrict__ invp,
                                                       __half* __restrict__ Wm, int H) {
    extern __shared__ float smr[];            // [H] floats, then [H] halves
    __half* smo = (__half*)(smr + H);
    const int r = blockIdx.x;
    const float* Wr = W + (size_t)r * H;
    for (int i = threadIdx.x; i < H / 4; i += 256)
        ((float4*)smr)[i] = ((const float4*)Wr)[i];
    __syncthreads();
    const int G = H >> 2;
    for (int g = threadIdx.x; g < G; g += 256) {
        int4 c = ((const int4*)invp)[g];
        float w0 = smr[c.x], w1 = smr[c.y], w2 = smr[c.z], w3 = smr[c.w];
        float m0 = fabsf(w0) * sqrtf(__ldg(scaler + c.x));
        float m1 = fabsf(w1) * sqrtf(__ldg(scaler + c.y));
        float m2 = fabsf(w2) * sqrtf(__ldg(scaler + c.z));
        float m3 = fabsf(w3) * sqrtf(__ldg(scaler + c.w));
        int r0 = (m1 > m0) + (m2 > m0) + (m3 > m0);
        int r1 = (m0 >= m1) + (m2 > m1) + (m3 > m1);
        int r2 = (m0 >= m2) + (m1 >= m2) + (m3 > m2);
        int r3 = (m0 >= m3) + (m1 >= m3) + (m2 >= m3);
        smo[c.x] = __float2half_rn(r0 < 2 ? w0 : 0.f);
        smo[c.y] = __float2half_rn(r1 < 2 ? w1 : 0.f);
        smo[c.z] = __float2half_rn(r2 < 2 ? w2 : 0.f);
        smo[c.w] = __float2half_rn(r3 < 2 ? w3 : 0.f);
    }
    __syncthreads();
    __half* Wo = Wm + (size_t)r * H;
    for (int i = threadIdx.x; i < H / 8; i += 256)
        ((uint4*)Wo)[i] = ((const uint4*)smo)[i];
}

// ---------------- fp16 NT GEMM v3: 3-slot/2-ahead, BK=64 (K/V projections) ----
#define GSH 72
#define GEMM_SMEM_BM(BM) (3 * ((BM) + 128) * GSH * 2)

template <int BM, int NTHR, bool HOUT>
__global__ void __launch_bounds__(NTHR, 2) gemm_v3(const __half* __restrict__ A,
                                                   const __half* __restrict__ B,
                                                   void* __restrict__ Cv,
                                                   int M, int N, int K) {
    extern __shared__ __half sh[];
    constexpr int STGH = (BM + 128) * GSH;
    constexpr uint32_t STGB = STGH * 2;
    constexpr uint32_t ABYTES = BM * GSH * 2;
    constexpr int AIT = BM * 8 / NTHR;
    constexpr int BIT = 128 * 8 / NTHR;

    const int tid = threadIdx.x, wid = tid >> 5, lane = tid & 31;
    const int g = lane >> 2, tg = lane & 3;
    const int wm = (wid >> 2) * 64, wn = (wid & 3) * 32;
    const int bm = blockIdx.y * BM, bn = blockIdx.x * 128;

    float acc[4][4][4] = {};
    uint32_t sA = smem_u32(sh);

    const uint32_t aoff = (uint32_t)((wm + (lane & 15)) * (GSH * 2) + (((lane >> 4) << 3) << 1));
    const uint32_t boff = ABYTES +
        (uint32_t)((wn + (lane & 7) + ((lane >> 4) << 3)) * (GSH * 2) +
                   ((((lane >> 3) & 1) << 3) << 1));

#define LOADSTAGE(slot, k0)                                                       \
    do {                                                                          \
        uint32_t so = sA + (uint32_t)(slot)*STGB;                                 \
        _Pragma("unroll")                                                         \
        for (int i = 0; i < AIT; i++) {                                           \
            int id = tid + i * NTHR;                                              \
            int row = id >> 3, ch = id & 7;                                       \
            const __half* pa = A + (size_t)(bm + row) * K + (k0) + ch * 8;        \
            asm volatile("cp.async.cg.shared.global [%0], [%1], 16;"              \
                         ::"r"(so + (uint32_t)((row * 9 + ch) * 16)), "l"(pa));   \
        }                                                                         \
        _Pragma("unroll")                                                         \
        for (int i = 0; i < BIT; i++) {                                           \
            int id = tid + i * NTHR;                                              \
            int row = id >> 3, ch = id & 7;                                       \
            const __half* pb = B + (size_t)(bn + row) * K + (k0) + ch * 8;        \
            asm volatile("cp.async.cg.shared.global [%0], [%1], 16;"              \
                         ::"r"(so + ABYTES + (uint32_t)((row * 9 + ch) * 16)),    \
                           "l"(pb));                                              \
        }                                                                         \
    } while (0)

    const int nk = K >> 6;
    LOADSTAGE(0, 0);
    asm volatile("cp.async.commit_group;");
    LOADSTAGE(1, 64);
    asm volatile("cp.async.commit_group;");

    for (int t = 0; t < nk; t++) {
        asm volatile("cp.async.wait_group 1;");
        __syncthreads();
        if (t + 2 < nk) LOADSTAGE((t + 2) % 3, (t + 2) * 64);
        asm volatile("cp.async.commit_group;");

        uint32_t base = sA + (uint32_t)(t % 3) * STGB;
#pragma unroll
        for (int ks = 0; ks < 4; ks++) {
            uint32_t kadd = (uint32_t)(ks * 32);
            uint32_t bt[2][4];
            ldm_x4(bt[0], base + boff + kadd);
            ldm_x4(bt[1], base + boff + kadd + 16 * (GSH * 2));
#pragma unroll
            for (int mi = 0; mi < 4; mi++) {
                uint32_t af[4];
                ldm_x4(af, base + aoff + kadd + (uint32_t)(mi * 16 * (GSH * 2)));
#pragma unroll
                for (int nb = 0; nb < 2; nb++) {
                    mma_fp16(acc[mi][2 * nb], af[0], af[1], af[2], af[3],
                             bt[nb][0], bt[nb][1]);
                    mma_fp16(acc[mi][2 * nb + 1], af[0], af[1], af[2], af[3],
                             bt[nb][2], bt[nb][3]);
                }
            }
        }
    }

#pragma unroll
    for (int mi = 0; mi < 4; mi++)
#pragma unroll
        for (int ni = 0; ni < 4; ni++) {
            int row = bm + wm + mi * 16 + g;
            int col = bn + wn + ni * 8 + tg * 2;
            if constexpr (HOUT) {
                __half* Ch = (__half*)Cv;
                *(uint32_t*)&Ch[(size_t)row * N + col] =
                    packh2(acc[mi][ni][0], acc[mi][ni][1]);
                *(uint32_t*)&Ch[(size_t)(row + 8) * N + col] =
                    packh2(acc[mi][ni][2], acc[mi][ni][3]);
            } else {
                float* Cf = (float*)Cv;
                *(float2*)&Cf[(size_t)row * N + col] =
                    make_float2(acc[mi][ni][0], acc[mi][ni][1]);
                *(float2*)&Cf[(size_t)(row + 8) * N + col] =
                    make_float2(acc[mi][ni][2], acc[mi][ni][3]);
            }
        }
#undef LOADSTAGE
}

// ---------------- fp16 NT GEMM v4: 128x128 CTA, 4 warps, 64x64 warptile -------
#define V4_STGB 32768u
#define V4_SMEM (3 * 32768)

__global__ void __launch_bounds__(128, 2) gemm_v4(const __half* __restrict__ A,
                                                  const __half* __restrict__ B,
                                                  float* __restrict__ C,
                                                  int M, int N, int K) {
    extern __shared__ __half sh[];
    const int tid = threadIdx.x, wid = tid >> 5, lane = tid & 31;
    const int g = lane >> 2, tg = lane & 3;
    const int wm = (wid >> 1) * 64, wn = (wid & 1) * 64;
    const int bm = blockIdx.y * 128, bn = blockIdx.x * 128;

    float acc[4][8][4] = {};
    uint32_t sA = smem_u32(sh);

    const int arow = lane & 15;
    const int apar = lane >> 4;
    const int brow = (lane & 7) + ((lane >> 4) << 3);
    const int bpar = (lane >> 3) & 1;

#define V4LOAD(slot, k0)                                                          \
    do {                                                                          \
        uint32_t so = sA + (uint32_t)(slot)*V4_STGB;                              \
        _Pragma("unroll")                                                         \
        for (int i = 0; i < 16; i++) {                                            \
            int id = tid + i * 128;                                               \
            int row = id >> 3, ch = id & 7;                                       \
            const __half* gp = (row < 128)                                        \
                ? A + (size_t)(bm + row) * K + (k0) + ch * 8                      \
                : B + (size_t)(bn + row - 128) * K + (k0) + ch * 8;               \
            asm volatile("cp.async.cg.shared.global [%0], [%1], 16;"              \
                         ::"r"(so + (uint32_t)(row * 128 +                        \
                                               ((ch ^ (row & 7)) * 16))),         \
                           "l"(gp));                                              \
        }                                                                         \
    } while (0)

    const int nk = K >> 6;
    V4LOAD(0, 0);
    asm volatile("cp.async.commit_group;");
    V4LOAD(1, 64);
    asm volatile("cp.async.commit_group;");

    for (int t = 0; t < nk; t++) {
        asm volatile("cp.async.wait_group 1;");
        __syncthreads();
        if (t + 2 < nk) V4LOAD((t + 2) % 3, (t + 2) * 64);
        asm volatile("cp.async.commit_group;");

        uint32_t base = sA + (uint32_t)(t % 3) * V4_STGB;
#pragma unroll
        for (int ks = 0; ks < 4; ks++) {
            uint32_t af[4][4], bt[4][4];
#pragma unroll
            for (int mi = 0; mi < 4; mi++) {
                int row = wm + mi * 16 + arow;
                int ch = 2 * ks + apar;
                ldm_x4(af[mi], base + (uint32_t)(row * 128 + ((ch ^ (row & 7)) * 16)));
            }
#pragma unroll
            for (int nb = 0; nb < 4; nb++) {
                int row = 128 + wn + nb * 16 + brow;
                int ch = 2 * ks + bpar;
                ldm_x4(bt[nb], base + (uint32_t)(row * 128 + ((ch ^ (row & 7)) * 16)));
            }
#pragma unroll
            for (int mi = 0; mi < 4; mi++)
#pragma unroll
                for (int nb = 0; nb < 4; nb++) {
                    mma_fp16(acc[mi][2 * nb], af[mi][0], af[mi][1], af[mi][2],
                             af[mi][3], bt[nb][0], bt[nb][1]);
                    mma_fp16(acc[mi][2 * nb + 1], af[mi][0], af[mi][1], af[mi][2],
                             af[mi][3], bt[nb][2], bt[nb][3]);
                }
        }
    }

#pragma unroll
    for (int mi = 0; mi < 4; mi++)
#pragma unroll
        for (int ni = 0; ni < 8; ni++) {
            int row = bm + wm + mi * 16 + g;
            int col = bn + wn + ni * 8 + tg * 2;
            *(float2*)&C[(size_t)row * N + col] =
                make_float2(acc[mi][ni][0], acc[mi][ni][1]);
            *(float2*)&C[(size_t)(row + 8) * N + col] =
                make_float2(acc[mi][ni][2], acc[mi][ni][3]);
        }
#undef V4LOAD
}

// ---------------- RoPE: fp32 in -> rotated fp16 out ----------------
__global__ void rope_half(const float* __restrict__ X, __half* __restrict__ Y,
                          const float* __restrict__ cosT, const float* __restrict__ sinT,
                          int nheads) {
    int idx = blockIdx.x * blockDim.x + threadIdx.x;
    int total = SEQ * nheads * 64;
    if (idx >= total) return;
    int d = idx & 63;
    int h = (idx >> 6) % nheads;
    int s = idx / (64 * nheads);
    const float* p = X + (size_t)s * nheads * HD + h * HD + d;
    float x1 = p[0], x2 = p[64];
    float c1 = cosT[s * HD + d],      s1 = sinT[s * HD + d];
    float c2 = cosT[s * HD + 64 + d], s2 = sinT[s * HD + 64 + d];
    __half* o = Y + (size_t)s * nheads * HD + h * HD + d;
    o[0]  = __float2half_rn(fmaf(x1, c1, -x2 * s1));
    o[64] = __float2half_rn(fmaf(x2, c2,  x1 * s2));
}

// ---------------- fp16 flash attention v3: double-buffered K/V cp.async -------
#define QSTR 136
#define FL4_SMEM ((128 + 2 * 128) * QSTR * 2)

__global__ void __launch_bounds__(256) flash_fp16_v3(const __half* __restrict__ Qg,
                                                     const __half* __restrict__ Kg,
                                                     const __half* __restrict__ Vg,
                                                     __half* __restrict__ Og,
                                                     int qb_base) {
    extern __shared__ __half sm[];
    __half* Qs = sm;
    const uint32_t sQ = smem_u32(Qs);
    const uint32_t sKV0 = sQ + 128 * (QSTR * 2);
    const uint32_t STG = 128 * (QSTR * 2);
    const uint32_t VOFF = 64 * (QSTR * 2);

    const int tid = threadIdx.x, wid = tid >> 5, lane = tid & 31;
    const int g = lane >> 2, tg = lane & 3;
    const int qb = qb_base + (int)gridDim.x - 1 - (int)blockIdx.x;   // heavy first
    const int head = blockIdx.y, kvh = head >> 2;
    const __half* Qh = Qg + head * HD;
    const __half* Kh = Kg + kvh * HD;
    const __half* Vh = Vg + kvh * HD;

    const int nkb = 2 * qb + 2;

#define KVLOAD(slot, kb)                                                          \
    do {                                                                          \
        uint32_t so = sKV0 + (uint32_t)(slot)*STG;                                \
        _Pragma("unroll")                                                         \
        for (int i = 0; i < 4; i++) {                                             \
            int id = tid + i * 256;                                               \
            int r = id >> 4, ch = id & 15;                                        \
            uint32_t d = (uint32_t)(r * (QSTR * 2) + ch * 16);                    \
            const __half* srck = Kh + (size_t)((kb)*64 + r) * KVD + ch * 8;       \
            const __half* srcv = Vh + (size_t)((kb)*64 + r) * KVD + ch * 8;       \
            asm volatile("cp.async.cg.shared.global [%0], [%1], 16;"              \
                         ::"r"(so + d), "l"(srck));                               \
            asm volatile("cp.async.cg.shared.global [%0], [%1], 16;"              \
                         ::"r"(so + VOFF + d), "l"(srcv));                        \
        }                                                                         \
    } while (0)

#pragma unroll
    for (int i = 0; i < 8; i++) {
        int id = tid + i * 256;
        int r = id >> 4, ch = id & 15;
        const __half* src = Qh + (size_t)(qb * 128 + r) * HID + ch * 8;
        asm volatile("cp.async.cg.shared.global [%0], [%1], 16;"
                     ::"r"(sQ + (uint32_t)(r * (QSTR * 2) + ch * 16)), "l"(src));
    }
    KVLOAD(0, 0);
    asm volatile("cp.async.commit_group;");

    const int wm = wid * 16;
    const int row0 = qb * 128 + wm + g, row1 = row0 + 8;
    const int rowTop = qb * 128 + wm + 15;
    float m0 = -1e30f, m1 = -1e30f, l0 = 0.f, l1 = 0.f;
    float oacc[16][4];
#pragma unroll
    for (int i = 0; i < 16; i++)
#pragma unroll
        for (int j = 0; j < 4; j++) oacc[i][j] = 0.f;

    const float scale = 0.08838834764831845f;

    const int lrA = wm + (lane & 15), lcA = (lane >> 4) << 3;
    const int lrK = (lane & 7) + ((lane >> 4) << 3), lcK = ((lane >> 3) & 1) << 3;
    const int lrV = (lane & 7) + (((lane >> 3) & 1) << 3), lcV = (lane >> 4) << 3;

    for (int kb = 0; kb < nkb; kb++) {
        __syncthreads();
        if (kb + 1 < nkb) KVLOAD((kb + 1) & 1, kb + 1);
        asm volatile("cp.async.commit_group;");
        asm volatile("cp.async.wait_group 1;");
        __syncthreads();

        if (kb * 64 <= rowTop) {
            uint32_t sK = sKV0 + (uint32_t)(kb & 1) * STG;
            uint32_t sV = sK + VOFF;

            float sacc[8][4];
#pragma unroll
            for (int ni = 0; ni < 8; ni++)
#pragma unroll
                for (int j = 0; j < 4; j++) sacc[ni][j] = 0.f;
#pragma unroll
            for (int ks = 0; ks < 8; ks++) {
                int kk = ks * 16;
                uint32_t af[4];
                ldm_x4(af, sQ + (uint32_t)((lrA * QSTR + kk + lcA) * 2));
#pragma unroll
                for (int nb = 0; nb < 4; nb++) {
                    uint32_t bt[4];
                    ldm_x4(bt, sK + (uint32_t)(((nb * 16 + lrK) * QSTR + kk + lcK) * 2));
                    mma_fp16(sacc[2 * nb], af[0], af[1], af[2], af[3], bt[0], bt[1]);
                    mma_fp16(sacc[2 * nb + 1], af[0], af[1], af[2], af[3], bt[2], bt[3]);
                }
            }

#pragma unroll
            for (int ni = 0; ni < 8; ni++) {
                int c0 = kb * 64 + ni * 8 + 2 * tg, c1 = c0 + 1;
                sacc[ni][0] = (c0 <= row0) ? sacc[ni][0] * scale : -1e30f;
                sacc[ni][1] = (c1 <= row0) ? sacc[ni][1] * scale : -1e30f;
                sacc[ni][2] = (c0 <= row1) ? sacc[ni][2] * scale : -1e30f;
                sacc[ni][3] = (c1 <= row1) ? sacc[ni][3] * scale : -1e30f;
            }

            float mx0 = -1e30f, mx1 = -1e30f;
#pragma unroll
            for (int ni = 0; ni < 8; ni++) {
                mx0 = fmaxf(mx0, fmaxf(sacc[ni][0], sacc[ni][1]));
                mx1 = fmaxf(mx1, fmaxf(sacc[ni][2], sacc[ni][3]));
            }
            mx0 = fmaxf(mx0, __shfl_xor_sync(0xffffffffu, mx0, 1));
            mx0 = fmaxf(mx0, __shfl_xor_sync(0xffffffffu, mx0, 2));
            mx1 = fmaxf(mx1, __shfl_xor_sync(0xffffffffu, mx1, 1));
            mx1 = fmaxf(mx1, __shfl_xor_sync(0xffffffffu, mx1, 2));
            float mn0 = fmaxf(m0, mx0), mn1 = fmaxf(m1, mx1);
            float fs0 = __expf(m0 - mn0), fs1 = __expf(m1 - mn1);

            float ps0 = 0.f, ps1 = 0.f;
#pragma unroll
            for (int ni = 0; ni < 8; ni++) {
                float p0 = (sacc[ni][0] > -1e29f) ? __expf(sacc[ni][0] - mn0) : 0.f;
                float p1 = (sacc[ni][1] > -1e29f) ? __expf(sacc[ni][1] - mn0) : 0.f;
                float p2 = (sacc[ni][2] > -1e29f) ? __expf(sacc[ni][2] - mn1) : 0.f;
                float p3 = (sacc[ni][3] > -1e29f) ? __expf(sacc[ni][3] - mn1) : 0.f;
                sacc[ni][0] = p0; sacc[ni][1] = p1; sacc[ni][2] = p2; sacc[ni][3] = p3;
                ps0 += p0 + p1; ps1 += p2 + p3;
            }
            ps0 += __shfl_xor_sync(0xffffffffu, ps0, 1);
            ps0 += __shfl_xor_sync(0xffffffffu, ps0, 2);
            ps1 += __shfl_xor_sync(0xffffffffu, ps1, 1);
            ps1 += __shfl_xor_sync(0xffffffffu, ps1, 2);
            l0 = l0 * fs0 + ps0; l1 = l1 * fs1 + ps1;
            m0 = mn0; m1 = mn1;

#pragma unroll
            for (int nd = 0; nd < 16; nd++) {
                oacc[nd][0] *= fs0; oacc[nd][1] *= fs0;
                oacc[nd][2] *= fs1; oacc[nd][3] *= fs1;
            }

#pragma unroll
            for (int s = 0; s < 4; s++) {
                uint32_t a0 = packh2(sacc[2 * s][0], sacc[2 * s][1]);
                uint32_t a1 = packh2(sacc[2 * s][2], sacc[2 * s][3]);
                uint32_t a2 = packh2(sacc[2 * s + 1][0], sacc[2 * s + 1][1]);
                uint32_t a3 = packh2(sacc[2 * s + 1][2], sacc[2 * s + 1][3]);
                int kk = s * 16;
#pragma unroll
                for (int t8 = 0; t8 < 8; t8++) {
                    uint32_t vt[4];
                    ldm_x4_t(vt, sV + (uint32_t)(((kk + lrV) * QSTR + t8 * 16 + lcV) * 2));
                    mma_fp16(oacc[2 * t8], a0, a1, a2, a3, vt[0], vt[1]);
                    mma_fp16(oacc[2 * t8 + 1], a0, a1, a2, a3, vt[2], vt[3]);
                }
            }
        }
    }

    float li0 = 1.f / l0, li1 = 1.f / l1;
#pragma unroll
    for (int nd = 0; nd < 16; nd++) {
        int col = head * HD + nd * 8 + 2 * tg;
        *(uint32_t*)&Og[(size_t)row0 * HID + col] =
            packh2(oacc[nd][0] * li0, oacc[nd][1] * li0);
        *(uint32_t*)&Og[(size_t)row1 * HID + col] =
            packh2(oacc[nd][2] * li1, oacc[nd][3] * li1);
    }
#undef KVLOAD
}

// ---------------- launch: 3-stream forked graph (proper capture fork) ---------
extern "C" void kernel_launch(void* const* d_in, const int* in_sizes, int n_in,
                              void* d_out, int out_size) {
    const float* hs   = (const float*)d_in[0];
    const float* wq   = (const float*)d_in[1];
    const float* wk   = (const float*)d_in[2];
    const float* wv   = (const float*)d_in[3];
    const float* wo   = (const float*)d_in[4];
    const float* scq  = (const float*)d_in[5];
    const float* sck  = (const float*)d_in[6];
    const float* scv  = (const float*)d_in[7];
    const float* sco  = (const float*)d_in[8];
    const float* pqkv = (const float*)d_in[9];
    const float* po   = (const float*)d_in[10];
    const float* cosT = (const float*)d_in[11];
    const float* sinT = (const float*)d_in[12];
    float* out = (float*)d_out;

    __half *wmq, *wmk, *wmv, *wmo, *hst, *qh, *kh, *vh, *ao;
    float *q, *k;
    int *ipq, *ipo;
    cudaGetSymbolAddress((void**)&wmq, g_wmq);
    cudaGetSymbolAddress((void**)&wmk, g_wmk);
    cudaGetSymbolAddress((void**)&wmv, g_wmv);
    cudaGetSymbolAddress((void**)&wmo, g_wmo);
    cudaGetSymbolAddress((void**)&hst, g_hst);
    cudaGetSymbolAddress((void**)&q,   g_q);
    cudaGetSymbolAddress((void**)&k,   g_k);
    cudaGetSymbolAddress((void**)&qh,  g_qh);
    cudaGetSymbolAddress((void**)&kh,  g_kh);
    cudaGetSymbolAddress((void**)&vh,  g_vh);
    cudaGetSymbolAddress((void**)&ao,  g_ao);
    cudaGetSymbolAddress((void**)&ipq, g_invp_qkv);
    cudaGetSymbolAddress((void**)&ipo, g_invp_o);

    const int smem64 = GEMM_SMEM_BM(64);
    cudaFuncSetAttribute(gemm_v4, cudaFuncAttributeMaxDynamicSharedMemorySize, V4_SMEM);
    cudaFuncSetAttribute(gemm_v3<64, 128, false>,
                         cudaFuncAttributeMaxDynamicSharedMemorySize, smem64);
    cudaFuncSetAttribute(gemm_v3<64, 128, true>,
                         cudaFuncAttributeMaxDynamicSharedMemorySize, smem64);
    cudaFuncSetAttribute(flash_fp16_v3, cudaFuncAttributeMaxDynamicSharedMemorySize,
                         FL4_SMEM);

    const int mw_smem = HID * 6;      // H floats + H halves

    // 3 extra streams (R12-proven footprint).  Every side stream is forked
    // from the capture stream via ev_root BEFORE any launch on it — required
    // for graph capture.
    cudaStream_t s2, s3, s4;
    cudaStreamCreateWithFlags(&s2, cudaStreamNonBlocking);
    cudaStreamCreateWithFlags(&s3, cudaStreamNonBlocking);
    cudaStreamCreateWithFlags(&s4, cudaStreamNonBlocking);
    cudaEvent_t ev_root, ev_ipq, ev_k, ev_v, ev_wo, ev_qh, ev_ob, ev_rh;
    cudaEventCreateWithFlags(&ev_root, cudaEventDisableTiming);
    cudaEventCreateWithFlags(&ev_ipq,  cudaEventDisableTiming);
    cudaEventCreateWithFlags(&ev_k,    cudaEventDisableTiming);
    cudaEventCreateWithFlags(&ev_v,    cudaEventDisableTiming);
    cudaEventCreateWithFlags(&ev_wo,   cudaEventDisableTiming);
    cudaEventCreateWithFlags(&ev_qh,   cudaEventDisableTiming);
    cudaEventCreateWithFlags(&ev_ob,   cudaEventDisableTiming);
    cudaEventCreateWithFlags(&ev_rh,   cudaEventDisableTiming);

    // ---- root fork point on the capture stream ----
    cudaEventRecord(ev_root, 0);

    // ---- s4: round_half (parallel with perm/mask), then O-weight path ----
    cudaStreamWaitEvent(s4, ev_root, 0);
    round_half<<<(SEQ * HID / 8 + 255) / 256, 256, 0, s4>>>(hs, hst, SEQ * HID / 8);
    cudaEventRecord(ev_rh, s4);
    perm_extract<<<(HID * HID + 255) / 256, 256, 0, s4>>>(po, ipo, HID);
    mask_weights_v2<<<HID, 256, mw_smem, s4>>>(wo, sco, ipo, wmo, HID);
    cudaEventRecord(ev_wo, s4);

    // ---- main: perm_qkv -> mask_wq -> (join round_half) -> Q GEMM ----
    perm_extract<<<(HID * HID + 255) / 256, 256>>>(pqkv, ipq, HID);
    cudaEventRecord(ev_ipq, 0);
    mask_weights_v2<<<HID, 256, mw_smem>>>(wq, scq, ipq, wmq, HID);
    cudaStreamWaitEvent(0, ev_rh, 0);
    gemm_v4<<<dim3(HID / 128, SEQ / 128), 128, V4_SMEM>>>(hst, wmq, q,
                                                          SEQ, HID, HID);

    // ---- s2: K path ----
    cudaStreamWaitEvent(s2, ev_ipq, 0);
    cudaStreamWaitEvent(s2, ev_rh, 0);
    mask_weights_v2<<<KVD, 256, mw_smem, s2>>>(wk, sck, ipq, wmk, HID);
    gemm_v3<64, 128, false><<<dim3(KVD / 128, SEQ / 64), 128, smem64, s2>>>(
        hst, wmk, k, SEQ, KVD, HID);
    rope_half<<<(SEQ * NKVH * 64 + 255) / 256, 256, 0, s2>>>(k, kh, cosT, sinT, NKVH);
    cudaEventRecord(ev_k, s2);

    // ---- s3: V path ----
    cudaStreamWaitEvent(s3, ev_ipq, 0);
    cudaStreamWaitEvent(s3, ev_rh, 0);
    mask_weights_v2<<<KVD, 256, mw_smem, s3>>>(wv, scv, ipq, wmv, HID);
    gemm_v3<64, 128, true><<<dim3(KVD / 128, SEQ / 64), 128, smem64, s3>>>(
        hst, wmv, vh, SEQ, KVD, HID);
    cudaEventRecord(ev_v, s3);

    // ---- main: rope_q ----
    rope_half<<<(SEQ * NHEADS * 64 + 255) / 256, 256>>>(q, qh, cosT, sinT, NHEADS);
    cudaEventRecord(ev_qh, 0);

    // ---- s2: flash LIGHT (qb 0..7) then O GEMM lower half (rows 0..1023) ----
    cudaStreamWaitEvent(s2, ev_qh, 0);
    cudaStreamWaitEvent(s2, ev_v, 0);
    flash_fp16_v3<<<dim3(8, NHEADS), 256, FL4_SMEM, s2>>>(qh, kh, vh, ao, 0);
    cudaStreamWaitEvent(s2, ev_wo, 0);
    gemm_v4<<<dim3(HID / 128, 8), 128, V4_SMEM, s2>>>(ao, wmo, out, 1024, HID, HID);
    cudaEventRecord(ev_ob, s2);

    // ---- main: flash HEAVY (qb 8..15), O GEMM upper half, join ----
    cudaStreamWaitEvent(0, ev_k, 0);
    cudaStreamWaitEvent(0, ev_v, 0);
    flash_fp16_v3<<<dim3(8, NHEADS), 256, FL4_SMEM>>>(qh, kh, vh, ao, 8);
    cudaStreamWaitEvent(0, ev_wo, 0);
    gemm_v4<<<dim3(HID / 128, 8), 128, V4_SMEM>>>(ao + (size_t)1024 * HID, wmo,
                                                  out + (size_t)1024 * HID,
                                                  1024, HID, HID);
    cudaStreamWaitEvent(0, ev_ob, 0);

    cudaEventDestroy(ev_root);
    cudaEventDestroy(ev_ipq);
    cudaEventDestroy(ev_k);
    cudaEventDestroy(ev_v);
    cudaEventDestroy(ev_wo);
    cudaEventDestroy(ev_qh);
    cudaEventDestroy(ev_ob);
    cudaEventDestroy(ev_rh);
    cudaStreamDestroy(s2);
    cudaStreamDestroy(s3);
    cudaStreamDestroy(s4);
}

// round 16
// speedup vs baseline: 9.4412x; 1.0298x over previous
#include <cuda_runtime.h>
#include <cuda_fp16.h>
#include <cstdint>

#define HID 4096
#define KVD 1024
#define SEQ 2048
#define NHEADS 32
#define NKVH 8
#define HD 128

// ---------------- scratch ----------------
__device__ __half g_wmq[HID * HID];
__device__ __half g_wmo[HID * HID];
__device__ __half g_wmk[KVD * HID];
__device__ __half g_wmv[KVD * HID];
__device__ __half g_hst[SEQ * HID];
__device__ float  g_q[SEQ * HID];
__device__ float  g_k[SEQ * KVD];
__device__ __half g_qh[SEQ * HID];
__device__ __half g_kh[SEQ * KVD];
__device__ __half g_vh[SEQ * KVD];
__device__ __half g_ao[SEQ * HID];
__device__ int    g_invp_qkv[HID];
__device__ int    g_invp_o[HID];

__device__ __forceinline__ uint32_t smem_u32(const void* p) {
    return (uint32_t)__cvta_generic_to_shared((void*)p);
}
__device__ __forceinline__ uint32_t packh2(float x, float y) {
    __half2 h = __floats2half2_rn(x, y);
    return *(uint32_t*)&h;
}
__device__ __forceinline__ void ldm_x4(uint32_t (&r)[4], uint32_t addr) {
    asm volatile("ldmatrix.sync.aligned.m8n8.x4.shared.b16 {%0,%1,%2,%3}, [%4];"
                 : "=r"(r[0]), "=r"(r[1]), "=r"(r[2]), "=r"(r[3]) : "r"(addr));
}
__device__ __forceinline__ void ldm_x4_t(uint32_t (&r)[4], uint32_t addr) {
    asm volatile("ldmatrix.sync.aligned.m8n8.x4.trans.shared.b16 {%0,%1,%2,%3}, [%4];"
                 : "=r"(r[0]), "=r"(r[1]), "=r"(r[2]), "=r"(r[3]) : "r"(addr));
}
__device__ __forceinline__ void mma_fp16(float c[4], uint32_t a0, uint32_t a1,
                                         uint32_t a2, uint32_t a3,
                                         uint32_t b0, uint32_t b1) {
    asm volatile(
        "mma.sync.aligned.m16n8k16.row.col.f32.f16.f16.f32 "
        "{%0,%1,%2,%3}, {%4,%5,%6,%7}, {%8,%9}, {%0,%1,%2,%3};"
        : "+f"(c[0]), "+f"(c[1]), "+f"(c[2]), "+f"(c[3])
        : "r"(a0), "r"(a1), "r"(a2), "r"(a3), "r"(b0), "r"(b1));
}

// ---------------- permutation extraction ----------------
__global__ void perm_extract(const float* __restrict__ P, int* __restrict__ invp, int n) {
    int idx = blockIdx.x * blockDim.x + threadIdx.x;
    if (idx >= n * n) return;
    if (P[idx] > 0.5f) invp[idx % n] = idx / n;
}

// ---------------- hidden states: fp32 -> fp16 ----------------
__global__ void round_half(const float* __restrict__ X, __half* __restrict__ Y, int n8) {
    int i = blockIdx.x * blockDim.x + threadIdx.x;
    if (i >= n8) return;
    const float4* p = (const float4*)(X + (size_t)i * 8);
    float4 a = p[0], b = p[1];
    uint4 o;
    o.x = packh2(a.x, a.y); o.y = packh2(a.z, a.w);
    o.z = packh2(b.x, b.y); o.w = packh2(b.z, b.w);
    *(uint4*)(Y + (size_t)i * 8) = o;
}

// ---------------- 2:4 hard mask v2: block-per-row, smem staged ----------------
__global__ void __launch_bounds__(256) mask_weights_v2(const float* __restrict__ W,
                                                       const float* __restrict__ scaler,
                                                       const int* __restrict__ invp,
                                                       __half* __restrict__ Wm, int H) {
    extern __shared__ float smr[];            // [H] floats, then [H] halves
    __half* smo = (__half*)(smr + H);
    const int r = blockIdx.x;
    const float* Wr = W + (size_t)r * H;
    for (int i = threadIdx.x; i < H / 4; i += 256)
        ((float4*)smr)[i] = ((const float4*)Wr)[i];
    __syncthreads();
    const int G = H >> 2;
    for (int g = threadIdx.x; g < G; g += 256) {
        int4 c = ((const int4*)invp)[g];
        float w0 = smr[c.x], w1 = smr[c.y], w2 = smr[c.z], w3 = smr[c.w];
        float m0 = fabsf(w0) * sqrtf(__ldg(scaler + c.x));
        float m1 = fabsf(w1) * sqrtf(__ldg(scaler + c.y));
        float m2 = fabsf(w2) * sqrtf(__ldg(scaler + c.z));
        float m3 = fabsf(w3) * sqrtf(__ldg(scaler + c.w));
        int r0 = (m1 > m0) + (m2 > m0) + (m3 > m0);
        int r1 = (m0 >= m1) + (m2 > m1) + (m3 > m1);
        int r2 = (m0 >= m2) + (m1 >= m2) + (m3 > m2);
        int r3 = (m0 >= m3) + (m1 >= m3) + (m2 >= m3);
        smo[c.x] = __float2half_rn(r0 < 2 ? w0 : 0.f);
        smo[c.y] = __float2half_rn(r1 < 2 ? w1 : 0.f);
        smo[c.z] = __float2half_rn(r2 < 2 ? w2 : 0.f);
        smo[c.w] = __float2half_rn(r3 < 2 ? w3 : 0.f);
    }
    __syncthreads();
    __half* Wo = Wm + (size_t)r * H;
    for (int i = threadIdx.x; i < H / 8; i += 256)
        ((uint4*)Wo)[i] = ((const uint4*)smo)[i];
}

// ---------------- fp16 NT GEMM v3: 3-slot/2-ahead, BK=64 (K/V projections) ----
#define GSH 72
#define GEMM_SMEM_BM(BM) (3 * ((BM) + 128) * GSH * 2)

template <int BM, int NTHR, bool HOUT>
__global__ void __launch_bounds__(NTHR, 2) gemm_v3(const __half* __restrict__ A,
                                                   const __half* __restrict__ B,
                                                   void* __restrict__ Cv,
                                                   int M, int N, int K) {
    extern __shared__ __half sh[];
    constexpr int STGH = (BM + 128) * GSH;
    constexpr uint32_t STGB = STGH * 2;
    constexpr uint32_t ABYTES = BM * GSH * 2;
    constexpr int AIT = BM * 8 / NTHR;
    constexpr int BIT = 128 * 8 / NTHR;

    const int tid = threadIdx.x, wid = tid >> 5, lane = tid & 31;
    const int g = lane >> 2, tg = lane & 3;
    const int wm = (wid >> 2) * 64, wn = (wid & 3) * 32;
    const int bm = blockIdx.y * BM, bn = blockIdx.x * 128;

    float acc[4][4][4] = {};
    uint32_t sA = smem_u32(sh);

    const uint32_t aoff = (uint32_t)((wm + (lane & 15)) * (GSH * 2) + (((lane >> 4) << 3) << 1));
    const uint32_t boff = ABYTES +
        (uint32_t)((wn + (lane & 7) + ((lane >> 4) << 3)) * (GSH * 2) +
                   ((((lane >> 3) & 1) << 3) << 1));

#define LOADSTAGE(slot, k0)                                                       \
    do {                                                                          \
        uint32_t so = sA + (uint32_t)(slot)*STGB;                                 \
        _Pragma("unroll")                                                         \
        for (int i = 0; i < AIT; i++) {                                           \
            int id = tid + i * NTHR;                                              \
            int row = id >> 3, ch = id & 7;                                       \
            const __half* pa = A + (size_t)(bm + row) * K + (k0) + ch * 8;        \
            asm volatile("cp.async.cg.shared.global [%0], [%1], 16;"              \
                         ::"r"(so + (uint32_t)((row * 9 + ch) * 16)), "l"(pa));   \
        }                                                                         \
        _Pragma("unroll")                                                         \
        for (int i = 0; i < BIT; i++) {                                           \
            int id = tid + i * NTHR;                                              \
            int row = id >> 3, ch = id & 7;                                       \
            const __half* pb = B + (size_t)(bn + row) * K + (k0) + ch * 8;        \
            asm volatile("cp.async.cg.shared.global [%0], [%1], 16;"              \
                         ::"r"(so + ABYTES + (uint32_t)((row * 9 + ch) * 16)),    \
                           "l"(pb));                                              \
        }                                                                         \
    } while (0)

    const int nk = K >> 6;
    LOADSTAGE(0, 0);
    asm volatile("cp.async.commit_group;");
    LOADSTAGE(1, 64);
    asm volatile("cp.async.commit_group;");

    for (int t = 0; t < nk; t++) {
        asm volatile("cp.async.wait_group 1;");
        __syncthreads();
        if (t + 2 < nk) LOADSTAGE((t + 2) % 3, (t + 2) * 64);
        asm volatile("cp.async.commit_group;");

        uint32_t base = sA + (uint32_t)(t % 3) * STGB;
#pragma unroll
        for (int ks = 0; ks < 4; ks++) {
            uint32_t kadd = (uint32_t)(ks * 32);
            uint32_t bt[2][4];
            ldm_x4(bt[0], base + boff + kadd);
            ldm_x4(bt[1], base + boff + kadd + 16 * (GSH * 2));
#pragma unroll
            for (int mi = 0; mi < 4; mi++) {
                uint32_t af[4];
                ldm_x4(af, base + aoff + kadd + (uint32_t)(mi * 16 * (GSH * 2)));
#pragma unroll
                for (int nb = 0; nb < 2; nb++) {
                    mma_fp16(acc[mi][2 * nb], af[0], af[1], af[2], af[3],
                             bt[nb][0], bt[nb][1]);
                    mma_fp16(acc[mi][2 * nb + 1], af[0], af[1], af[2], af[3],
                             bt[nb][2], bt[nb][3]);
                }
            }
        }
    }

#pragma unroll
    for (int mi = 0; mi < 4; mi++)
#pragma unroll
        for (int ni = 0; ni < 4; ni++) {
            int row = bm + wm + mi * 16 + g;
            int col = bn + wn + ni * 8 + tg * 2;
            if constexpr (HOUT) {
                __half* Ch = (__half*)Cv;
                *(uint32_t*)&Ch[(size_t)row * N + col] =
                    packh2(acc[mi][ni][0], acc[mi][ni][1]);
                *(uint32_t*)&Ch[(size_t)(row + 8) * N + col] =
                    packh2(acc[mi][ni][2], acc[mi][ni][3]);
            } else {
                float* Cf = (float*)Cv;
                *(float2*)&Cf[(size_t)row * N + col] =
                    make_float2(acc[mi][ni][0], acc[mi][ni][1]);
                *(float2*)&Cf[(size_t)(row + 8) * N + col] =
                    make_float2(acc[mi][ni][2], acc[mi][ni][3]);
            }
        }
#undef LOADSTAGE
}

// ---------------- fp16 NT GEMM v4: 128x128 CTA, 4 warps, 64x64 warptile -------
#define V4_STGB 32768u
#define V4_SMEM (3 * 32768)

__global__ void __launch_bounds__(128, 2) gemm_v4(const __half* __restrict__ A,
                                                  const __half* __restrict__ B,
                                                  float* __restrict__ C,
                                                  int M, int N, int K) {
    extern __shared__ __half sh[];
    const int tid = threadIdx.x, wid = tid >> 5, lane = tid & 31;
    const int g = lane >> 2, tg = lane & 3;
    const int wm = (wid >> 1) * 64, wn = (wid & 1) * 64;
    const int bm = blockIdx.y * 128, bn = blockIdx.x * 128;

    float acc[4][8][4] = {};
    uint32_t sA = smem_u32(sh);

    const int arow = lane & 15;
    const int apar = lane >> 4;
    const int brow = (lane & 7) + ((lane >> 4) << 3);
    const int bpar = (lane >> 3) & 1;

#define V4LOAD(slot, k0)                                                          \
    do {                                                                          \
        uint32_t so = sA + (uint32_t)(slot)*V4_STGB;                              \
        _Pragma("unroll")                                                         \
        for (int i = 0; i < 16; i++) {                                            \
            int id = tid + i * 128;                                               \
            int row = id >> 3, ch = id & 7;                                       \
            const __half* gp = (row < 128)                                        \
                ? A + (size_t)(bm + row) * K + (k0) + ch * 8                      \
                : B + (size_t)(bn + row - 128) * K + (k0) + ch * 8;               \
            asm volatile("cp.async.cg.shared.global [%0], [%1], 16;"              \
                         ::"r"(so + (uint32_t)(row * 128 +                        \
                                               ((ch ^ (row & 7)) * 16))),         \
                           "l"(gp));                                              \
        }                                                                         \
    } while (0)

    const int nk = K >> 6;
    V4LOAD(0, 0);
    asm volatile("cp.async.commit_group;");
    V4LOAD(1, 64);
    asm volatile("cp.async.commit_group;");

    for (int t = 0; t < nk; t++) {
        asm volatile("cp.async.wait_group 1;");
        __syncthreads();
        if (t + 2 < nk) V4LOAD((t + 2) % 3, (t + 2) * 64);
        asm volatile("cp.async.commit_group;");

        uint32_t base = sA + (uint32_t)(t % 3) * V4_STGB;
#pragma unroll
        for (int ks = 0; ks < 4; ks++) {
            uint32_t af[4][4], bt[4][4];
#pragma unroll
            for (int mi = 0; mi < 4; mi++) {
                int row = wm + mi * 16 + arow;
                int ch = 2 * ks + apar;
                ldm_x4(af[mi], base + (uint32_t)(row * 128 + ((ch ^ (row & 7)) * 16)));
            }
#pragma unroll
            for (int nb = 0; nb < 4; nb++) {
                int row = 128 + wn + nb * 16 + brow;
                int ch = 2 * ks + bpar;
                ldm_x4(bt[nb], base + (uint32_t)(row * 128 + ((ch ^ (row & 7)) * 16)));
            }
#pragma unroll
            for (int mi = 0; mi < 4; mi++)
#pragma unroll
                for (int nb = 0; nb < 4; nb++) {
                    mma_fp16(acc[mi][2 * nb], af[mi][0], af[mi][1], af[mi][2],
                             af[mi][3], bt[nb][0], bt[nb][1]);
                    mma_fp16(acc[mi][2 * nb + 1], af[mi][0], af[mi][1], af[mi][2],
                             af[mi][3], bt[nb][2], bt[nb][3]);
                }
        }
    }

#pragma unroll
    for (int mi = 0; mi < 4; mi++)
#pragma unroll
        for (int ni = 0; ni < 8; ni++) {
            int row = bm + wm + mi * 16 + g;
            int col = bn + wn + ni * 8 + tg * 2;
            *(float2*)&C[(size_t)row * N + col] =
                make_float2(acc[mi][ni][0], acc[mi][ni][1]);
            *(float2*)&C[(size_t)(row + 8) * N + col] =
                make_float2(acc[mi][ni][2], acc[mi][ni][3]);
        }
#undef V4LOAD
}

// ---------------- RoPE: fp32 in -> rotated fp16 out (row-range variant) -------
__global__ void rope_half(const float* __restrict__ X, __half* __restrict__ Y,
                          const float* __restrict__ cosT, const float* __restrict__ sinT,
                          int nheads, int s0, int nrows) {
    int idx = blockIdx.x * blockDim.x + threadIdx.x;
    int total = nrows * nheads * 64;
    if (idx >= total) return;
    int d = idx & 63;
    int h = (idx >> 6) % nheads;
    int s = s0 + idx / (64 * nheads);
    const float* p = X + (size_t)s * nheads * HD + h * HD + d;
    float x1 = p[0], x2 = p[64];
    float c1 = cosT[s * HD + d],      s1 = sinT[s * HD + d];
    float c2 = cosT[s * HD + 64 + d], s2 = sinT[s * HD + 64 + d];
    __half* o = Y + (size_t)s * nheads * HD + h * HD + d;
    o[0]  = __float2half_rn(fmaf(x1, c1, -x2 * s1));
    o[64] = __float2half_rn(fmaf(x2, c2,  x1 * s2));
}

// ---------------- fp16 flash attention v3: double-buffered K/V cp.async -------
#define QSTR 136
#define FL4_SMEM ((128 + 2 * 128) * QSTR * 2)

__global__ void __launch_bounds__(256) flash_fp16_v3(const __half* __restrict__ Qg,
                                                     const __half* __restrict__ Kg,
                                                     const __half* __restrict__ Vg,
                                                     __half* __restrict__ Og,
                                                     int qb_base) {
    extern __shared__ __half sm[];
    __half* Qs = sm;
    const uint32_t sQ = smem_u32(Qs);
    const uint32_t sKV0 = sQ + 128 * (QSTR * 2);
    const uint32_t STG = 128 * (QSTR * 2);
    const uint32_t VOFF = 64 * (QSTR * 2);

    const int tid = threadIdx.x, wid = tid >> 5, lane = tid & 31;
    const int g = lane >> 2, tg = lane & 3;
    const int qb = qb_base + (int)gridDim.x - 1 - (int)blockIdx.x;   // heavy first
    const int head = blockIdx.y, kvh = head >> 2;
    const __half* Qh = Qg + head * HD;
    const __half* Kh = Kg + kvh * HD;
    const __half* Vh = Vg + kvh * HD;

    const int nkb = 2 * qb + 2;

#define KVLOAD(slot, kb)                                                          \
    do {                                                                          \
        uint32_t so = sKV0 + (uint32_t)(slot)*STG;                                \
        _Pragma("unroll")                                                         \
        for (int i = 0; i < 4; i++) {                                             \
            int id = tid + i * 256;                                               \
            int r = id >> 4, ch = id & 15;                                        \
            uint32_t d = (uint32_t)(r * (QSTR * 2) + ch * 16);                    \
            const __half* srck = Kh + (size_t)((kb)*64 + r) * KVD + ch * 8;       \
            const __half* srcv = Vh + (size_t)((kb)*64 + r) * KVD + ch * 8;       \
            asm volatile("cp.async.cg.shared.global [%0], [%1], 16;"              \
                         ::"r"(so + d), "l"(srck));                               \
            asm volatile("cp.async.cg.shared.global [%0], [%1], 16;"              \
                         ::"r"(so + VOFF + d), "l"(srcv));                        \
        }                                                                         \
    } while (0)

#pragma unroll
    for (int i = 0; i < 8; i++) {
        int id = tid + i * 256;
        int r = id >> 4, ch = id & 15;
        const __half* src = Qh + (size_t)(qb * 128 + r) * HID + ch * 8;
        asm volatile("cp.async.cg.shared.global [%0], [%1], 16;"
                     ::"r"(sQ + (uint32_t)(r * (QSTR * 2) + ch * 16)), "l"(src));
    }
    KVLOAD(0, 0);
    asm volatile("cp.async.commit_group;");

    const int wm = wid * 16;
    const int row0 = qb * 128 + wm + g, row1 = row0 + 8;
    const int rowTop = qb * 128 + wm + 15;
    float m0 = -1e30f, m1 = -1e30f, l0 = 0.f, l1 = 0.f;
    float oacc[16][4];
#pragma unroll
    for (int i = 0; i < 16; i++)
#pragma unroll
        for (int j = 0; j < 4; j++) oacc[i][j] = 0.f;

    const float scale = 0.08838834764831845f;

    const int lrA = wm + (lane & 15), lcA = (lane >> 4) << 3;
    const int lrK = (lane & 7) + ((lane >> 4) << 3), lcK = ((lane >> 3) & 1) << 3;
    const int lrV = (lane & 7) + (((lane >> 3) & 1) << 3), lcV = (lane >> 4) << 3;

    for (int kb = 0; kb < nkb; kb++) {
        __syncthreads();
        if (kb + 1 < nkb) KVLOAD((kb + 1) & 1, kb + 1);
        asm volatile("cp.async.commit_group;");
        asm volatile("cp.async.wait_group 1;");
        __syncthreads();

        if (kb * 64 <= rowTop) {
            uint32_t sK = sKV0 + (uint32_t)(kb & 1) * STG;
            uint32_t sV = sK + VOFF;

            float sacc[8][4];
#pragma unroll
            for (int ni = 0; ni < 8; ni++)
#pragma unroll
                for (int j = 0; j < 4; j++) sacc[ni][j] = 0.f;
#pragma unroll
            for (int ks = 0; ks < 8; ks++) {
                int kk = ks * 16;
                uint32_t af[4];
                ldm_x4(af, sQ + (uint32_t)((lrA * QSTR + kk + lcA) * 2));
#pragma unroll
                for (int nb = 0; nb < 4; nb++) {
                    uint32_t bt[4];
                    ldm_x4(bt, sK + (uint32_t)(((nb * 16 + lrK) * QSTR + kk + lcK) * 2));
                    mma_fp16(sacc[2 * nb], af[0], af[1], af[2], af[3], bt[0], bt[1]);
                    mma_fp16(sacc[2 * nb + 1], af[0], af[1], af[2], af[3], bt[2], bt[3]);
                }
            }

#pragma unroll
            for (int ni = 0; ni < 8; ni++) {
                int c0 = kb * 64 + ni * 8 + 2 * tg, c1 = c0 + 1;
                sacc[ni][0] = (c0 <= row0) ? sacc[ni][0] * scale : -1e30f;
                sacc[ni][1] = (c1 <= row0) ? sacc[ni][1] * scale : -1e30f;
                sacc[ni][2] = (c0 <= row1) ? sacc[ni][2] * scale : -1e30f;
                sacc[ni][3] = (c1 <= row1) ? sacc[ni][3] * scale : -1e30f;
            }

            float mx0 = -1e30f, mx1 = -1e30f;
#pragma unroll
            for (int ni = 0; ni < 8; ni++) {
                mx0 = fmaxf(mx0, fmaxf(sacc[ni][0], sacc[ni][1]));
                mx1 = fmaxf(mx1, fmaxf(sacc[ni][2], sacc[ni][3]));
            }
            mx0 = fmaxf(mx0, __shfl_xor_sync(0xffffffffu, mx0, 1));
            mx0 = fmaxf(mx0, __shfl_xor_sync(0xffffffffu, mx0, 2));
            mx1 = fmaxf(mx1, __shfl_xor_sync(0xffffffffu, mx1, 1));
            mx1 = fmaxf(mx1, __shfl_xor_sync(0xffffffffu, mx1, 2));
            float mn0 = fmaxf(m0, mx0), mn1 = fmaxf(m1, mx1);
            float fs0 = __expf(m0 - mn0), fs1 = __expf(m1 - mn1);

            float ps0 = 0.f, ps1 = 0.f;
#pragma unroll
            for (int ni = 0; ni < 8; ni++) {
                float p0 = (sacc[ni][0] > -1e29f) ? __expf(sacc[ni][0] - mn0) : 0.f;
                float p1 = (sacc[ni][1] > -1e29f) ? __expf(sacc[ni][1] - mn0) : 0.f;
                float p2 = (sacc[ni][2] > -1e29f) ? __expf(sacc[ni][2] - mn1) : 0.f;
                float p3 = (sacc[ni][3] > -1e29f) ? __expf(sacc[ni][3] - mn1) : 0.f;
                sacc[ni][0] = p0; sacc[ni][1] = p1; sacc[ni][2] = p2; sacc[ni][3] = p3;
                ps0 += p0 + p1; ps1 += p2 + p3;
            }
            ps0 += __shfl_xor_sync(0xffffffffu, ps0, 1);
            ps0 += __shfl_xor_sync(0xffffffffu, ps0, 2);
            ps1 += __shfl_xor_sync(0xffffffffu, ps1, 1);
            ps1 += __shfl_xor_sync(0xffffffffu, ps1, 2);
            l0 = l0 * fs0 + ps0; l1 = l1 * fs1 + ps1;
            m0 = mn0; m1 = mn1;

#pragma unroll
            for (int nd = 0; nd < 16; nd++) {
                oacc[nd][0] *= fs0; oacc[nd][1] *= fs0;
                oacc[nd][2] *= fs1; oacc[nd][3] *= fs1;
            }

#pragma unroll
            for (int s = 0; s < 4; s++) {
                uint32_t a0 = packh2(sacc[2 * s][0], sacc[2 * s][1]);
                uint32_t a1 = packh2(sacc[2 * s][2], sacc[2 * s][3]);
                uint32_t a2 = packh2(sacc[2 * s + 1][0], sacc[2 * s + 1][1]);
                uint32_t a3 = packh2(sacc[2 * s + 1][2], sacc[2 * s + 1][3]);
                int kk = s * 16;
#pragma unroll
                for (int t8 = 0; t8 < 8; t8++) {
                    uint32_t vt[4];
                    ldm_x4_t(vt, sV + (uint32_t)(((kk + lrV) * QSTR + t8 * 16 + lcV) * 2));
                    mma_fp16(oacc[2 * t8], a0, a1, a2, a3, vt[0], vt[1]);
                    mma_fp16(oacc[2 * t8 + 1], a0, a1, a2, a3, vt[2], vt[3]);
                }
            }
        }
    }

    float li0 = 1.f / l0, li1 = 1.f / l1;
#pragma unroll
    for (int nd = 0; nd < 16; nd++) {
        int col = head * HD + nd * 8 + 2 * tg;
        *(uint32_t*)&Og[(size_t)row0 * HID + col] =
            packh2(oacc[nd][0] * li0, oacc[nd][1] * li0);
        *(uint32_t*)&Og[(size_t)row1 * HID + col] =
            packh2(oacc[nd][2] * li1, oacc[nd][3] * li1);
    }
#undef KVLOAD
}

// ---------------- launch: 3-stream graph, Q-axis-split pipeline ----------------
extern "C" void kernel_launch(void* const* d_in, const int* in_sizes, int n_in,
                              void* d_out, int out_size) {
    const float* hs   = (const float*)d_in[0];
    const float* wq   = (const float*)d_in[1];
    const float* wk   = (const float*)d_in[2];
    const float* wv   = (const float*)d_in[3];
    const float* wo   = (const float*)d_in[4];
    const float* scq  = (const float*)d_in[5];
    const float* sck  = (const float*)d_in[6];
    const float* scv  = (const float*)d_in[7];
    const float* sco  = (const float*)d_in[8];
    const float* pqkv = (const float*)d_in[9];
    const float* po   = (const float*)d_in[10];
    const float* cosT = (const float*)d_in[11];
    const float* sinT = (const float*)d_in[12];
    float* out = (float*)d_out;

    __half *wmq, *wmk, *wmv, *wmo, *hst, *qh, *kh, *vh, *ao;
    float *q, *k;
    int *ipq, *ipo;
    cudaGetSymbolAddress((void**)&wmq, g_wmq);
    cudaGetSymbolAddress((void**)&wmk, g_wmk);
    cudaGetSymbolAddress((void**)&wmv, g_wmv);
    cudaGetSymbolAddress((void**)&wmo, g_wmo);
    cudaGetSymbolAddress((void**)&hst, g_hst);
    cudaGetSymbolAddress((void**)&q,   g_q);
    cudaGetSymbolAddress((void**)&k,   g_k);
    cudaGetSymbolAddress((void**)&qh,  g_qh);
    cudaGetSymbolAddress((void**)&kh,  g_kh);
    cudaGetSymbolAddress((void**)&vh,  g_vh);
    cudaGetSymbolAddress((void**)&ao,  g_ao);
    cudaGetSymbolAddress((void**)&ipq, g_invp_qkv);
    cudaGetSymbolAddress((void**)&ipo, g_invp_o);

    const int smem64 = GEMM_SMEM_BM(64);
    cudaFuncSetAttribute(gemm_v4, cudaFuncAttributeMaxDynamicSharedMemorySize, V4_SMEM);
    cudaFuncSetAttribute(gemm_v3<64, 128, false>,
                         cudaFuncAttributeMaxDynamicSharedMemorySize, smem64);
    cudaFuncSetAttribute(gemm_v3<64, 128, true>,
                         cudaFuncAttributeMaxDynamicSharedMemorySize, smem64);
    cudaFuncSetAttribute(flash_fp16_v3, cudaFuncAttributeMaxDynamicSharedMemorySize,
                         FL4_SMEM);

    const int mw_smem = HID * 6;

    cudaStream_t s2, s3, s4;
    cudaStreamCreateWithFlags(&s2, cudaStreamNonBlocking);
    cudaStreamCreateWithFlags(&s3, cudaStreamNonBlocking);
    cudaStreamCreateWithFlags(&s4, cudaStreamNonBlocking);
    cudaEvent_t ev_root, ev_ipq, ev_wq, ev_rh, ev_k, ev_v, ev_wo, ev_qlo, ev_ob;
    cudaEventCreateWithFlags(&ev_root, cudaEventDisableTiming);
    cudaEventCreateWithFlags(&ev_ipq,  cudaEventDisableTiming);
    cudaEventCreateWithFlags(&ev_wq,   cudaEventDisableTiming);
    cudaEventCreateWithFlags(&ev_rh,   cudaEventDisableTiming);
    cudaEventCreateWithFlags(&ev_k,    cudaEventDisableTiming);
    cudaEventCreateWithFlags(&ev_v,    cudaEventDisableTiming);
    cudaEventCreateWithFlags(&ev_wo,   cudaEventDisableTiming);
    cudaEventCreateWithFlags(&ev_qlo,  cudaEventDisableTiming);
    cudaEventCreateWithFlags(&ev_ob,   cudaEventDisableTiming);

    cudaEventRecord(ev_root, 0);

    // ---- s4: round_half, then O-weight path (all hidden) ----
    cudaStreamWaitEvent(s4, ev_root, 0);
    round_half<<<(SEQ * HID / 8 + 255) / 256, 256, 0, s4>>>(hs, hst, SEQ * HID / 8);
    cudaEventRecord(ev_rh, s4);
    perm_extract<<<(HID * HID + 255) / 256, 256, 0, s4>>>(po, ipo, HID);
    mask_weights_v2<<<HID, 256, mw_smem, s4>>>(wo, sco, ipo, wmo, HID);
    cudaEventRecord(ev_wo, s4);

    // ---- main: perm_qkv -> mask_wq -> Q GEMM upper (rows 1024..2047) ----
    perm_extract<<<(HID * HID + 255) / 256, 256>>>(pqkv, ipq, HID);
    cudaEventRecord(ev_ipq, 0);
    mask_weights_v2<<<HID, 256, mw_smem>>>(wq, scq, ipq, wmq, HID);
    cudaEventRecord(ev_wq, 0);
    cudaStreamWaitEvent(0, ev_rh, 0);
    gemm_v4<<<dim3(HID / 128, 8), 128, V4_SMEM>>>(hst + (size_t)1024 * HID, wmq,
                                                  q + (size_t)1024 * HID,
                                                  1024, HID, HID);
    rope_half<<<(1024 * NHEADS * 64 + 255) / 256, 256>>>(q, qh, cosT, sinT,
                                                         NHEADS, 1024, 1024);

    // ---- s2: K path ----
    cudaStreamWaitEvent(s2, ev_ipq, 0);
    cudaStreamWaitEvent(s2, ev_rh, 0);
    mask_weights_v2<<<KVD, 256, mw_smem, s2>>>(wk, sck, ipq, wmk, HID);
    gemm_v3<64, 128, false><<<dim3(KVD / 128, SEQ / 64), 128, smem64, s2>>>(
        hst, wmk, k, SEQ, KVD, HID);
    rope_half<<<(SEQ * NKVH * 64 + 255) / 256, 256, 0, s2>>>(k, kh, cosT, sinT,
                                                             NKVH, 0, SEQ);
    cudaEventRecord(ev_k, s2);

    // ---- s3: V path, then Q GEMM lower (rows 0..1023) + rope lower ----
    cudaStreamWaitEvent(s3, ev_ipq, 0);
    cudaStreamWaitEvent(s3, ev_rh, 0);
    mask_weights_v2<<<KVD, 256, mw_smem, s3>>>(wv, scv, ipq, wmv, HID);
    gemm_v3<64, 128, true><<<dim3(KVD / 128, SEQ / 64), 128, smem64, s3>>>(
        hst, wmv, vh, SEQ, KVD, HID);
    cudaEventRecord(ev_v, s3);
    cudaStreamWaitEvent(s3, ev_wq, 0);
    gemm_v4<<<dim3(HID / 128, 8), 128, V4_SMEM, s3>>>(hst, wmq, q, 1024, HID, HID);
    rope_half<<<(1024 * NHEADS * 64 + 255) / 256, 256, 0, s3>>>(q, qh, cosT, sinT,
                                                                NHEADS, 0, 1024);
    cudaEventRecord(ev_qlo, s3);

    // ---- main: flash HEAVY (qb 8..15) as early as possible ----
    cudaStreamWaitEvent(0, ev_k, 0);
    cudaStreamWaitEvent(0, ev_v, 0);
    flash_fp16_v3<<<dim3(8, NHEADS), 256, FL4_SMEM>>>(qh, kh, vh, ao, 8);

    // ---- s2: flash LIGHT (qb 0..7) then O GEMM lower (out rows 0..1023) ----
    cudaStreamWaitEvent(s2, ev_qlo, 0);      // covers V via s3 chain
    flash_fp16_v3<<<dim3(8, NHEADS), 256, FL4_SMEM, s2>>>(qh, kh, vh, ao, 0);
    cudaStreamWaitEvent(s2, ev_wo, 0);
    gemm_v4<<<dim3(HID / 128, 8), 128, V4_SMEM, s2>>>(ao, wmo, out, 1024, HID, HID);
    cudaEventRecord(ev_ob, s2);

    // ---- main: O GEMM upper (out rows 1024..2047), then join ----
    cudaStreamWaitEvent(0, ev_wo, 0);
    gemm_v4<<<dim3(HID / 128, 8), 128, V4_SMEM>>>(ao + (size_t)1024 * HID, wmo,
                                                  out + (size_t)1024 * HID,
                                                  1024, HID, HID);
    cudaStreamWaitEvent(0, ev_ob, 0);

    cudaEventDestroy(ev_root);
    cudaEventDestroy(ev_ipq);
    cudaEventDestroy(ev_wq);
    cudaEventDestroy(ev_rh);
    cudaEventDestroy(ev_k);
    cudaEventDestroy(ev_v);
    cudaEventDestroy(ev_wo);
    cudaEventDestroy(ev_qlo);
    cudaEventDestroy(ev_ob);
    cudaStreamDestroy(s2);
    cudaStreamDestroy(s3);
    cudaStreamDestroy(s4);
}